// round 11
// baseline (speedup 1.0000x reference)
#include <cuda_runtime.h>
#include <math.h>
#include <stdint.h>

#define BB 2
#define CDIM 320
#define NTOK 16384
#define DIN 640
#define DSTATE 32
#define NH 8
#define PDIM 80
#define CONVD 704
#define DPROJ 1352
#define INNERC 160
#define NQ 6
#define QCH 128
#define NCH (NTOK/QCH)
#define MLPD 1024
#define LN_EPS 1e-5f
#define TWOPI 6.28318530717958647692f

__device__ float g_xn[BB*NTOK*CDIM];
__device__ float g_zx[BB*NTOK*DPROJ];
__device__ float g_xbc[BB*NTOK*CONVD];
__device__ float g_dt[BB*NTOK*NH];
__device__ float g_cumL[BB*NH*NTOK];
__device__ float g_Sc[BB*NH*NCH*DSTATE*PDIM];
__device__ float g_Sin[BB*NH*NCH*DSTATE*PDIM];
__device__ float g_y[BB*NTOK*DIN];
__device__ float g_keys[BB*NTOK*CDIM];
__device__ float g_kpe[NTOK*CDIM];
__device__ float g_pe[BB*NQ*CDIM];
__device__ float g_qr[BB*NQ*CDIM];
__device__ float g_q6[BB*NQ*CDIM];
__device__ float g_k6[BB*NQ*CDIM];
__device__ float g_v6[BB*NQ*CDIM];
__device__ float g_a6[BB*NQ*CDIM];
__device__ float g_mlpb[BB*NQ*MLPD];
__device__ float g_kb[BB*NTOK*INNERC];
__device__ float g_vb[BB*NTOK*INNERC];
__device__ float g_qb[BB*NTOK*INNERC];
__device__ float g_ab[BB*NTOK*INNERC];

__device__ __forceinline__ float siluf(float x){ return x/(1.f+expf(-x)); }

__device__ __forceinline__ void blockReduce2(float& a,float& b,float* sa,float* sb){
    const unsigned m=0xffffffffu;
    for(int o=16;o>0;o>>=1){a+=__shfl_down_sync(m,a,o);b+=__shfl_down_sync(m,b,o);}
    int lane=threadIdx.x&31,w=threadIdx.x>>5;
    if(lane==0){sa[w]=a;sb[w]=b;}
    __syncthreads();
    int nw=(blockDim.x+31)>>5;
    if(w==0){
        a=(lane<nw)?sa[lane]:0.f; b=(lane<nw)?sb[lane]:0.f;
        for(int o=16;o>0;o>>=1){a+=__shfl_down_sync(m,a,o);b+=__shfl_down_sync(m,b,o);}
        if(lane==0){sa[0]=a;sb[0]=b;}
    }
    __syncthreads();
    a=sa[0];b=sb[0];
}

// fused transpose (B,320,T)->(B,T,320) + LayerNorm. 32 tokens/block, 256 thr
#define TLP 329
__global__ void k_transln(const float* __restrict__ in,float* __restrict__ out,
                          const float* __restrict__ w,const float* __restrict__ b){
    __shared__ float sm[32*TLP];
    int blk=blockIdx.x;
    int bb=blk/(NTOK/32), t0=(blk%(NTOK/32))*32;
    int tid=threadIdx.x;
    for(int i=tid;i<32*CDIM;i+=256){
        int c=i>>5, tt=i&31;
        sm[tt*TLP+c]=in[((size_t)bb*CDIM+c)*NTOK+t0+tt];
    }
    __syncthreads();
    int lane=tid&31,warp=tid>>5;
    for(int tt=warp;tt<32;tt+=8){
        float s1=0.f,s2=0.f;
        for(int c=lane;c<CDIM;c+=32){float v=sm[tt*TLP+c];s1+=v;s2+=v*v;}
        for(int o=16;o>0;o>>=1){s1+=__shfl_down_sync(0xffffffffu,s1,o);s2+=__shfl_down_sync(0xffffffffu,s2,o);}
        s1=__shfl_sync(0xffffffffu,s1,0); s2=__shfl_sync(0xffffffffu,s2,0);
        float mean=s1*(1.f/CDIM),var=s2*(1.f/CDIM)-mean*mean;
        float r=rsqrtf(var+LN_EPS);
        for(int c=lane;c<CDIM;c+=32)
            sm[tt*TLP+c]=(sm[tt*TLP+c]-mean)*r*w[c]+b[c];
    }
    __syncthreads();
    for(int i=tid;i<32*CDIM;i+=256){
        int tt=i/CDIM,c=i-tt*CDIM;
        out[((size_t)bb*NTOK+t0+tt)*CDIM+c]=sm[tt*TLP+c];
    }
}

// fused LayerNorm + transpose (B,T,320)->(B,320,T)
__global__ void k_lntrans(const float* __restrict__ in,float* __restrict__ out,
                          const float* __restrict__ w,const float* __restrict__ b){
    __shared__ float sm[32*TLP];
    int blk=blockIdx.x;
    int bb=blk/(NTOK/32), t0=(blk%(NTOK/32))*32;
    int tid=threadIdx.x;
    for(int i=tid;i<32*CDIM;i+=256){
        int tt=i/CDIM,c=i-tt*CDIM;
        sm[tt*TLP+c]=in[((size_t)bb*NTOK+t0+tt)*CDIM+c];
    }
    __syncthreads();
    int lane=tid&31,warp=tid>>5;
    for(int tt=warp;tt<32;tt+=8){
        float s1=0.f,s2=0.f;
        for(int c=lane;c<CDIM;c+=32){float v=sm[tt*TLP+c];s1+=v;s2+=v*v;}
        for(int o=16;o>0;o>>=1){s1+=__shfl_down_sync(0xffffffffu,s1,o);s2+=__shfl_down_sync(0xffffffffu,s2,o);}
        s1=__shfl_sync(0xffffffffu,s1,0); s2=__shfl_sync(0xffffffffu,s2,0);
        float mean=s1*(1.f/CDIM),var=s2*(1.f/CDIM)-mean*mean;
        float r=rsqrtf(var+LN_EPS);
        for(int c=lane;c<CDIM;c+=32)
            sm[tt*TLP+c]=(sm[tt*TLP+c]-mean)*r*w[c]+b[c];
    }
    __syncthreads();
    for(int i=tid;i<32*CDIM;i+=256){
        int c=i>>5, tt=i&31;
        out[((size_t)bb*CDIM+c)*NTOK+t0+tt]=sm[tt*TLP+c];
    }
}

// plain LayerNorm over 320, blockDim=320
__global__ void k_ln(const float* __restrict__ in,float* __restrict__ out,
                     const float* __restrict__ w,const float* __restrict__ b){
    __shared__ float sa[32],sb[32];
    int row=blockIdx.x;
    float v=in[(size_t)row*CDIM+threadIdx.x];
    float s1=v,s2=v*v;
    blockReduce2(s1,s2,sa,sb);
    float mean=s1*(1.f/CDIM),var=s2*(1.f/CDIM)-mean*mean;
    float r=rsqrtf(var+LN_EPS);
    out[(size_t)row*CDIM+threadIdx.x]=(v-mean)*r*w[threadIdx.x]+b[threadIdx.x];
}

// ===== bf16 mma.sync GEMM with hi/lo split =====
#define UPAD 20
__device__ __forceinline__ uint32_t pk2(float a,float b){
    uint32_t r; asm("cvt.rn.bf16x2.f32 %0, %1, %2;":"=r"(r):"f"(b),"f"(a)); return r;
}
__device__ __forceinline__ void mma_bf(float* d,uint32_t a0,uint32_t a1,uint32_t a2,uint32_t a3,
                                       uint32_t b0,uint32_t b1){
    asm volatile("mma.sync.aligned.m16n8k16.row.col.f32.bf16.bf16.f32 "
        "{%0,%1,%2,%3}, {%4,%5,%6,%7}, {%8,%9}, {%0,%1,%2,%3};"
        : "+f"(d[0]),"+f"(d[1]),"+f"(d[2]),"+f"(d[3])
        : "r"(a0),"r"(a1),"r"(a2),"r"(a3),"r"(b0),"r"(b1));
}

__global__ __launch_bounds__(256) void k_gemm_tc(
        const float* __restrict__ A,const float* __restrict__ Aadd,int addMod,
        const float* __restrict__ W,const float* __restrict__ bias,
        const float* __restrict__ res,float* __restrict__ C,int M,int N,int K){
    __shared__ uint32_t Ah[128*UPAD],Al[128*UPAD],Wh[128*UPAD],Wl[128*UPAD];
    int m0=blockIdx.y*128,n0=blockIdx.x*128;
    int tid=threadIdx.x,lane=tid&31,warp=tid>>5;
    int wm=warp&3,wn=warp>>2,lg=lane>>2,lk=lane&3;
    int bnEnd=(N-n0-wn*64+7)>>3;
    if(bnEnd<0)bnEnd=0; if(bnEnd>8)bnEnd=8;
    float acc[2][8][4];
    #pragma unroll
    for(int am=0;am<2;am++)
        #pragma unroll
        for(int bn=0;bn<8;bn++)
            #pragma unroll
            for(int j=0;j<4;j++)acc[am][bn][j]=0.f;

    for(int kt=0;kt<K;kt+=32){
        #pragma unroll
        for(int i=0;i<4;i++){
            int f=tid+i*256,r=f>>3,kq=(f&7)<<2;
            int gm=m0+r;
            float4 v=*(const float4*)(A+(size_t)gm*K+kt+kq);
            if(Aadd){
                float4 u=*(const float4*)(Aadd+(size_t)(gm%addMod)*K+kt+kq);
                v.x+=u.x;v.y+=u.y;v.z+=u.z;v.w+=u.w;
            }
            uint32_t h0=pk2(v.x,v.y),h1=pk2(v.z,v.w);
            float l0=v.x-__uint_as_float(h0<<16),l1=v.y-__uint_as_float(h0&0xffff0000u);
            float l2=v.z-__uint_as_float(h1<<16),l3=v.w-__uint_as_float(h1&0xffff0000u);
            int si=r*UPAD+(kq>>1);
            *(uint2*)(Ah+si)=make_uint2(h0,h1);
            *(uint2*)(Al+si)=make_uint2(pk2(l0,l1),pk2(l2,l3));
            int gn=n0+r;
            float4 wv=make_float4(0.f,0.f,0.f,0.f);
            if(gn<N)wv=*(const float4*)(W+(size_t)gn*K+kt+kq);
            uint32_t g0=pk2(wv.x,wv.y),g1=pk2(wv.z,wv.w);
            float m0f=wv.x-__uint_as_float(g0<<16),m1f=wv.y-__uint_as_float(g0&0xffff0000u);
            float m2f=wv.z-__uint_as_float(g1<<16),m3f=wv.w-__uint_as_float(g1&0xffff0000u);
            *(uint2*)(Wh+si)=make_uint2(g0,g1);
            *(uint2*)(Wl+si)=make_uint2(pk2(m0f,m1f),pk2(m2f,m3f));
        }
        __syncthreads();
        if(bnEnd>0){
            #pragma unroll
            for(int ks=0;ks<2;ks++){
                uint32_t a0[2],a1[2],a2[2],a3[2],e0[2],e1[2],e2[2],e3[2];
                #pragma unroll
                for(int am=0;am<2;am++){
                    int r=wm*32+am*16+lg,c=ks*8+lk;
                    a0[am]=Ah[r*UPAD+c];     a1[am]=Ah[(r+8)*UPAD+c];
                    a2[am]=Ah[r*UPAD+c+4];   a3[am]=Ah[(r+8)*UPAD+c+4];
                    e0[am]=Al[r*UPAD+c];     e1[am]=Al[(r+8)*UPAD+c];
                    e2[am]=Al[r*UPAD+c+4];   e3[am]=Al[(r+8)*UPAD+c+4];
                }
                for(int bn=0;bn<bnEnd;bn++){
                    int col=wn*64+bn*8+lg,c=ks*8+lk;
                    uint32_t b0=Wh[col*UPAD+c],b1=Wh[col*UPAD+c+4];
                    uint32_t f0=Wl[col*UPAD+c],f1=Wl[col*UPAD+c+4];
                    #pragma unroll
                    for(int am=0;am<2;am++){
                        mma_bf(acc[am][bn],a0[am],a1[am],a2[am],a3[am],b0,b1);
                        mma_bf(acc[am][bn],a0[am],a1[am],a2[am],a3[am],f0,f1);
                        mma_bf(acc[am][bn],e0[am],e1[am],e2[am],e3[am],b0,b1);
                    }
                }
            }
        }
        __syncthreads();
    }
    #pragma unroll
    for(int am=0;am<2;am++){
        int r0=m0+wm*32+am*16+lg;
        for(int bn=0;bn<bnEnd;bn++){
            int c0=n0+wn*64+bn*8+2*lk;
            #pragma unroll
            for(int half=0;half<2;half++){
                int gm=r0+half*8;
                float d0=acc[am][bn][half*2+0],d1=acc[am][bn][half*2+1];
                if(c0<N){
                    float v=d0;
                    if(bias)v+=bias[c0];
                    if(res)v+=res[(size_t)gm*N+c0];
                    C[(size_t)gm*N+c0]=v;
                }
                if(c0+1<N){
                    float v=d1;
                    if(bias)v+=bias[c0+1];
                    if(res)v+=res[(size_t)gm*N+c0+1];
                    C[(size_t)gm*N+c0+1]=v;
                }
            }
        }
    }
}

// conv: 8 tokens per block staged in smem (input read once)
__global__ void k_conv2(const float* __restrict__ cw,const float* __restrict__ cb,
                        const float* __restrict__ dt_bias){
    __shared__ float sx[11*CONVD];
    int blk=blockIdx.x;
    int bb=blk/(NTOK/8), t0=(blk%(NTOK/8))*8;
    int tid=threadIdx.x;
    for(int i=tid;i<11*CONVD;i+=256){
        int r=i/CONVD,c=i-r*CONVD;
        int tt=t0-3+r;
        sx[i]=(tt>=0)?g_zx[((size_t)bb*NTOK+tt)*DPROJ+DIN+c]:0.f;
    }
    __syncthreads();
    for(int i=tid;i<8*CONVD;i+=256){
        int r=i/CONVD,c=i-r*CONVD;
        float acc=cb[c];
        #pragma unroll
        for(int k=0;k<4;k++)acc+=cw[c*4+k]*sx[(r+k)*CONVD+c];
        g_xbc[((size_t)bb*NTOK+t0+r)*CONVD+c]=siluf(acc);
    }
    if(tid<8*NH){
        int r=tid>>3,h=tid&7;
        float v=g_zx[((size_t)bb*NTOK+t0+r)*DPROJ+DIN+CONVD+h]+dt_bias[h];
        v=(v>20.f)?v:log1pf(expf(v));
        g_dt[((size_t)bb*NTOK+t0+r)*NH+h]=v;
    }
}

// chunk state with inline per-chunk cumsum
__global__ void k_chunkstate(const float* __restrict__ A_log){
    extern __shared__ float sm[];
    float* w=sm; float* Bv=sm+QCH; float* Xv=Bv+QCH*DSTATE;
    float* sc=Xv+QCH*PDIM; float* sdt=sc+QCH;
    int g=blockIdx.x,ch=g%NCH,h=(g/NCH)%NH,b=g/(NCH*NH);
    int tid=threadIdx.x;
    float A=-expf(A_log[h]);
    if(tid<QCH){
        sdt[tid]=g_dt[((size_t)b*NTOK+ch*QCH+tid)*NH+h];
        sc[tid]=sdt[tid]*A;
    }
    __syncthreads();
    for(int off=1;off<QCH;off<<=1){
        float add=(tid>=off&&tid<QCH)?sc[tid-off]:0.f;
        __syncthreads();
        if(tid<QCH)sc[tid]+=add;
        __syncthreads();
    }
    if(tid<QCH)g_cumL[((size_t)(b*NH+h))*NTOK+ch*QCH+tid]=sc[tid];
    float total=sc[QCH-1];
    for(int i=tid;i<QCH;i+=256)
        w[i]=expf(total-sc[i])*sdt[i];
    for(int i=tid;i<QCH*DSTATE;i+=256){
        int s=i>>5,nn=i&31;
        Bv[i]=g_xbc[((size_t)b*NTOK+ch*QCH+s)*CONVD+DIN+nn];
    }
    for(int i=tid;i<QCH*PDIM;i+=256){
        int s=i/PDIM,p=i-s*PDIM;
        Xv[i]=g_xbc[((size_t)b*NTOK+ch*QCH+s)*CONVD+h*PDIM+p];
    }
    __syncthreads();
    int n0=(tid>>4)*2,p0=(tid&15)*5;
    float acc[2][5];
    for(int a=0;a<2;a++)for(int q=0;q<5;q++)acc[a][q]=0.f;
    for(int s=0;s<QCH;s++){
        float ws=w[s],wb0=ws*Bv[s*DSTATE+n0],wb1=ws*Bv[s*DSTATE+n0+1];
        #pragma unroll
        for(int q=0;q<5;q++){
            float xv=Xv[s*PDIM+p0+q];
            acc[0][q]+=wb0*xv; acc[1][q]+=wb1*xv;
        }
    }
    size_t base=(size_t)g*(DSTATE*PDIM);
    for(int a=0;a<2;a++)for(int q=0;q<5;q++)
        g_Sc[base+(size_t)(n0+a)*PDIM+p0+q]=acc[a][q];
}
#define CS_SMEM ((QCH+QCH*DSTATE+QCH*PDIM+QCH+QCH)*4)

__global__ void k_staterec(){
    int bh=blockIdx.x;
    __shared__ float etot[NCH];
    for(int i=threadIdx.x;i<NCH;i+=256)
        etot[i]=expf(g_cumL[(size_t)bh*NTOK+i*QCH+QCH-1]);
    __syncthreads();
    float S[10];
    for(int j=0;j<10;j++)S[j]=0.f;
    for(int c=0;c<NCH;c++){
        size_t base=((size_t)bh*NCH+c)*(DSTATE*PDIM);
        float e=etot[c];
        #pragma unroll
        for(int j=0;j<10;j++){
            int idx=threadIdx.x+j*256;
            g_Sin[base+idx]=S[j];
            S[j]=S[j]*e+g_Sc[base+idx];
        }
    }
}

// SSD output: phase1 reg-tiled (Cv cached per t), phase2 float4 G
#define BVW 36
__global__ void k_ssd_out(const float* __restrict__ Dp){
    extern __shared__ float sm[];
    float* Lc=sm; float* dts=Lc+QCH; float* Cv=dts+QCH;
    float* Bv=Cv+QCH*DSTATE; float* Xv=Bv+QCH*BVW;
    float* Ss=Xv+QCH*PDIM; float* G=Ss+DSTATE*PDIM;
    int g=blockIdx.x,ch=g%NCH,h=(g/NCH)%NH,b=g/(NCH*NH);
    int tid=threadIdx.x;
    const float* cl=g_cumL+((size_t)(b*NH+h))*NTOK+ch*QCH;
    for(int i=tid;i<QCH;i+=256){
        Lc[i]=cl[i];
        dts[i]=g_dt[((size_t)b*NTOK+ch*QCH+i)*NH+h];
    }
    for(int i=tid;i<QCH*DSTATE;i+=256){
        int s=i>>5,nn=i&31;
        size_t rb=((size_t)b*NTOK+ch*QCH+s)*CONVD;
        Cv[i]=g_xbc[rb+DIN+DSTATE+nn];
        Bv[s*BVW+nn]=g_xbc[rb+DIN+nn];
    }
    for(int i=tid;i<QCH*PDIM;i+=256){
        int s=i/PDIM,p=i-s*PDIM;
        Xv[i]=g_xbc[((size_t)b*NTOK+ch*QCH+s)*CONVD+h*PDIM+p];
    }
    for(int i=tid;i<DSTATE*PDIM;i+=256)
        Ss[i]=g_Sin[(((size_t)(b*NH+h))*NCH+ch)*(DSTATE*PDIM)+i];
    __syncthreads();
    // phase1: thread owns (t, s-half); Cv[t] cached in regs
    {
        int t=tid>>1, sBase=(tid&1)*64;
        float4 cv[8];
        #pragma unroll
        for(int j=0;j<8;j++)cv[j]=*(float4*)(Cv+t*DSTATE+j*4);
        float Lt=Lc[t];
        for(int s=sBase;s<sBase+64;s++){
            float val=0.f;
            if(s<=t){
                float d=0.f;
                #pragma unroll
                for(int j=0;j<8;j++){
                    float4 bv=*(float4*)(Bv+s*BVW+j*4);
                    d+=cv[j].x*bv.x+cv[j].y*bv.y+cv[j].z*bv.z+cv[j].w*bv.w;
                }
                val=d*expf(Lt-Lc[s])*dts[s];
            }
            G[t*QCH+s]=val;
        }
    }
    __syncthreads();
    float Dh=Dp[h];
    for(int o4=tid;o4<QCH*PDIM/4;o4+=256){
        int t=o4/20,p=(o4-t*20)*4;
        float4 acc=make_float4(0.f,0.f,0.f,0.f);
        const float* Gt=G+t*QCH;
        for(int s4=0;s4<=t;s4+=4){
            float4 gq=*(const float4*)(Gt+s4);
            float4 x0=*(const float4*)(Xv+s4*PDIM+p);
            acc.x+=gq.x*x0.x;acc.y+=gq.x*x0.y;acc.z+=gq.x*x0.z;acc.w+=gq.x*x0.w;
            float4 x1=*(const float4*)(Xv+(s4+1)*PDIM+p);
            acc.x+=gq.y*x1.x;acc.y+=gq.y*x1.y;acc.z+=gq.y*x1.z;acc.w+=gq.y*x1.w;
            float4 x2=*(const float4*)(Xv+(s4+2)*PDIM+p);
            acc.x+=gq.z*x2.x;acc.y+=gq.z*x2.y;acc.z+=gq.z*x2.z;acc.w+=gq.z*x2.w;
            float4 x3=*(const float4*)(Xv+(s4+3)*PDIM+p);
            acc.x+=gq.w*x3.x;acc.y+=gq.w*x3.y;acc.z+=gq.w*x3.z;acc.w+=gq.w*x3.w;
        }
        float4 inter=make_float4(0.f,0.f,0.f,0.f);
        #pragma unroll
        for(int nn=0;nn<DSTATE;nn++){
            float cc=Cv[t*DSTATE+nn];
            float4 sv=*(const float4*)(Ss+nn*PDIM+p);
            inter.x+=cc*sv.x;inter.y+=cc*sv.y;inter.z+=cc*sv.z;inter.w+=cc*sv.w;
        }
        float elt=expf(Lc[t]);
        float4 xt=*(const float4*)(Xv+t*PDIM+p);
        acc.x+=elt*inter.x+Dh*xt.x; acc.y+=elt*inter.y+Dh*xt.y;
        acc.z+=elt*inter.z+Dh*xt.z; acc.w+=elt*inter.w+Dh*xt.w;
        *(float4*)(g_y+((size_t)b*NTOK+ch*QCH+t)*DIN+h*PDIM+p)=acc;
    }
}
#define SSD_SMEM ((QCH+QCH+QCH*DSTATE+QCH*BVW+QCH*PDIM+DSTATE*PDIM+QCH*QCH)*4)

__global__ void k_gate_rms(const float* __restrict__ rms_w){
    __shared__ float sa[32],sb[32];
    int row=blockIdx.x;
    float* yr=g_y+(size_t)row*DIN;
    const float* zr=g_zx+(size_t)row*DPROJ;
    float vals[3],ss=0.f;
    #pragma unroll
    for(int i=0;i<3;i++){
        int c=threadIdx.x+i*256;
        float v=0.f;
        if(c<DIN)v=yr[c]*siluf(zr[c]);
        vals[i]=v; ss+=v*v;
    }
    float dummy=0.f;
    blockReduce2(ss,dummy,sa,sb);
    float scale=rsqrtf(ss*(1.f/DIN)+LN_EPS);
    #pragma unroll
    for(int i=0;i<3;i++){
        int c=threadIdx.x+i*256;
        if(c<DIN)yr[c]=vals[i]*scale*rms_w[c];
    }
}

__global__ void k_kpe(const float* __restrict__ gauss){
    int t=blockIdx.x,j=threadIdx.x;
    int d=t>>10,r=t&1023,hh=r>>5,ww=r&31;
    float g0=2.f*((d+0.5f)/16.f)-1.f,g1=2.f*((hh+0.5f)/32.f)-1.f,g2=2.f*((ww+0.5f)/32.f)-1.f;
    float c=TWOPI*(g0*gauss[j]+g1*gauss[160+j]+g2*gauss[320+j]);
    g_kpe[(size_t)t*CDIM+j]=sinf(c);
    g_kpe[(size_t)t*CDIM+160+j]=cosf(c);
}

__global__ void k_pemb(const float* __restrict__ coords,const int* __restrict__ labels,
                       const float* __restrict__ gauss,const float* __restrict__ tab){
    int bp=blockIdx.x,j=threadIdx.x;
    float g0=2.f*(coords[bp*3+0]*(1.f/128.f))-1.f;
    float g1=2.f*(coords[bp*3+1]*(1.f/256.f))-1.f;
    float g2=2.f*(coords[bp*3+2]*(1.f/256.f))-1.f;
    float c=TWOPI*(g0*gauss[j]+g1*gauss[160+j]+g2*gauss[320+j]);
    int lb=labels[bp];
    float s=sinf(c)+tab[lb*CDIM+j],co=cosf(c)+tab[lb*CDIM+160+j];
    g_pe[bp*CDIM+j]=s; g_pe[bp*CDIM+160+j]=co;
    g_qr[bp*CDIM+j]=s; g_qr[bp*CDIM+160+j]=co;
}

// coalesced tiny GEMM: warp-per-output; grid (M, ySlices)
__global__ void k_tiny(const float* __restrict__ in,const float* __restrict__ pe,
                       const float* __restrict__ W,const float* __restrict__ bias,
                       const float* __restrict__ res,float* __restrict__ out,
                       int N,int K,int relu){
    extern __shared__ float srow[];
    int m=blockIdx.x;
    for(int i=threadIdx.x;i<K;i+=blockDim.x){
        float v=in[m*K+i];
        if(pe)v+=pe[m*K+i];
        srow[i]=v;
    }
    __syncthreads();
    int lane=threadIdx.x&31,warp=threadIdx.x>>5;
    int nq=N/gridDim.y;
    int nBeg=blockIdx.y*nq,nEnd=nBeg+nq;
    for(int n=nBeg+warp;n<nEnd;n+=8){
        const float* wr=W+(size_t)n*K;
        float acc=0.f;
        for(int kk=lane;kk<K;kk+=32)acc+=srow[kk]*wr[kk];
        #pragma unroll
        for(int o=16;o>0;o>>=1)acc+=__shfl_down_sync(0xffffffffu,acc,o);
        if(lane==0){
            if(bias)acc+=bias[n];
            if(relu)acc=fmaxf(acc,0.f);
            if(res)acc+=res[m*N+n];
            out[m*N+n]=acc;
        }
    }
}

// batched tiny (up to 3 ops via grid.z), shared input row
__global__ void k_tiny3(const float* __restrict__ in,const float* __restrict__ pe,
                        const float* __restrict__ W0,const float* __restrict__ W1,const float* __restrict__ W2,
                        const float* __restrict__ b0,const float* __restrict__ b1,const float* __restrict__ b2,
                        float* __restrict__ o0,float* __restrict__ o1,float* __restrict__ o2,
                        int peMask,int N,int K){
    extern __shared__ float srow[];
    int m=blockIdx.x,z=blockIdx.z;
    const float* W=(z==0)?W0:((z==1)?W1:W2);
    const float* bi=(z==0)?b0:((z==1)?b1:b2);
    float* out=(z==0)?o0:((z==1)?o1:o2);
    int usePe=(peMask>>z)&1;
    for(int i=threadIdx.x;i<K;i+=blockDim.x){
        float v=in[m*K+i];
        if(pe&&usePe)v+=pe[m*K+i];
        srow[i]=v;
    }
    __syncthreads();
    int lane=threadIdx.x&31,warp=threadIdx.x>>5;
    int nq=N/gridDim.y;
    int nBeg=blockIdx.y*nq,nEnd=nBeg+nq;
    for(int n=nBeg+warp;n<nEnd;n+=8){
        const float* wr=W+(size_t)n*K;
        float acc=0.f;
        for(int kk=lane;kk<K;kk+=32)acc+=srow[kk]*wr[kk];
        #pragma unroll
        for(int o=16;o>0;o>>=1)acc+=__shfl_down_sync(0xffffffffu,acc,o);
        if(lane==0)out[m*N+n]=acc+(bi?bi[n]:0.f);
    }
}

// tiny out-proj + bias + residual + LayerNorm fused (N==320), grid=M
__global__ void k_tiny_ln(const float* __restrict__ in,const float* __restrict__ W,
                          const float* __restrict__ bias,const float* __restrict__ res,
                          float* __restrict__ out,const float* __restrict__ lnw,
                          const float* __restrict__ lnb,int K){
    extern __shared__ float smem[];
    float* srow=smem;        // K
    float* sout=smem+K;      // 320
    __shared__ float sa[32],sb[32];
    int m=blockIdx.x;
    for(int i=threadIdx.x;i<K;i+=256)srow[i]=in[m*K+i];
    __syncthreads();
    int lane=threadIdx.x&31,warp=threadIdx.x>>5;
    for(int n=warp;n<CDIM;n+=8){
        const float* wr=W+(size_t)n*K;
        float acc=0.f;
        for(int kk=lane;kk<K;kk+=32)acc+=srow[kk]*wr[kk];
        #pragma unroll
        for(int o=16;o>0;o>>=1)acc+=__shfl_down_sync(0xffffffffu,acc,o);
        if(lane==0){
            acc+=bias[n];
            if(res)acc+=res[m*CDIM+n];
            sout[n]=acc;
        }
    }
    __syncthreads();
    float v0=(threadIdx.x<CDIM)?sout[threadIdx.x]:0.f;
    int e1=threadIdx.x+256;
    float v1=(e1<CDIM)?sout[e1]:0.f;
    float s1=v0+v1,s2=v0*v0+v1*v1;
    blockReduce2(s1,s2,sa,sb);
    float mean=s1*(1.f/CDIM),var=s2*(1.f/CDIM)-mean*mean;
    float r=rsqrtf(var+LN_EPS);
    if(threadIdx.x<CDIM)out[m*CDIM+threadIdx.x]=(v0-mean)*r*lnw[threadIdx.x]+lnb[threadIdx.x];
    if(e1<CDIM)out[m*CDIM+e1]=(v1-mean)*r*lnw[e1]+lnb[e1];
}

__global__ void k_selfattn(const float* __restrict__ q,const float* __restrict__ k,
                           const float* __restrict__ v,float* __restrict__ out){
    int bh=blockIdx.x,b=bh>>2,h=bh&3;
    __shared__ float qs[NQ][80],ks[NQ][80],vs[NQ][80],p[NQ][NQ];
    for(int i=threadIdx.x;i<NQ*80;i+=blockDim.x){
        int r=i/80,d=i-r*80;
        size_t off=(size_t)(b*NQ+r)*CDIM+h*80+d;
        qs[r][d]=q[off];ks[r][d]=k[off];vs[r][d]=v[off];
    }
    __syncthreads();
    if(threadIdx.x<36){
        int i=threadIdx.x/6,j=threadIdx.x%6;
        float s=0.f;
        #pragma unroll
        for(int d=0;d<80;d++)s+=qs[i][d]*ks[j][d];
        p[i][j]=s*0.11180339887498949f;
    }
    __syncthreads();
    if(threadIdx.x<NQ){
        int i=threadIdx.x;
        float m=-1e30f;
        for(int j=0;j<NQ;j++)m=fmaxf(m,p[i][j]);
        float ssum=0.f;
        for(int j=0;j<NQ;j++){float e=expf(p[i][j]-m);p[i][j]=e;ssum+=e;}
        float inv=1.f/ssum;
        for(int j=0;j<NQ;j++)p[i][j]*=inv;
    }
    __syncthreads();
    if(threadIdx.x<80){
        int d=threadIdx.x;
        for(int i=0;i<NQ;i++){
            float o=0.f;
            #pragma unroll
            for(int j=0;j<NQ;j++)o+=p[i][j]*vs[j][d];
            out[(size_t)(b*NQ+i)*CDIM+h*80+d]=o;
        }
    }
}

#define T2I_TP 41
#define T2I_SMEM ((NTOK + 256*T2I_TP + 256)*4)
__global__ void k_t2i_attn(const float* __restrict__ q6,const float* __restrict__ kbig,
                           const float* __restrict__ vbig,float* __restrict__ out){
    extern __shared__ float sm[];
    float* scr=sm;
    float* tile=sm+NTOK;
    float* red=tile+256*T2I_TP;
    __shared__ float wred[8][40];
    int g=blockIdx.x,qi=g%6,h=(g/6)%4,b=g/24;
    int tid=threadIdx.x;
    float qv[40];
    const float* qp=q6+(size_t)(b*NQ+qi)*INNERC+h*40;
    #pragma unroll
    for(int d=0;d<40;d++)qv[d]=qp[d]*0.15811388300841897f;
    const float* kb=kbig+(size_t)b*NTOK*INNERC+h*40;
    float lmax=-1e30f;
    for(int t0=0;t0<NTOK;t0+=256){
        for(int i=tid;i<256*40;i+=256){
            int r=i/40,c=i-r*40;
            tile[r*T2I_TP+c]=kb[(size_t)(t0+r)*INNERC+c];
        }
        __syncthreads();
        const float* tr=tile+tid*T2I_TP;
        float s=0.f;
        #pragma unroll
        for(int d=0;d<40;d++)s+=qv[d]*tr[d];
        scr[t0+tid]=s; lmax=fmaxf(lmax,s);
        __syncthreads();
    }
    red[tid]=lmax;__syncthreads();
    for(int o=128;o>0;o>>=1){if(tid<o)red[tid]=fmaxf(red[tid],red[tid+o]);__syncthreads();}
    float gmax=red[0];__syncthreads();
    float lsum=0.f;
    for(int kk=tid;kk<NTOK;kk+=256){float e=expf(scr[kk]-gmax);scr[kk]=e;lsum+=e;}
    red[tid]=lsum;__syncthreads();
    for(int o=128;o>0;o>>=1){if(tid<o)red[tid]+=red[tid+o];__syncthreads();}
    float gsum=red[0];__syncthreads();
    float acc[40];
    #pragma unroll
    for(int d=0;d<40;d++)acc[d]=0.f;
    const float* vb=vbig+(size_t)b*NTOK*INNERC+h*40;
    for(int t0=0;t0<NTOK;t0+=256){
        for(int i=tid;i<256*40;i+=256){
            int r=i/40,c=i-r*40;
            tile[r*T2I_TP+c]=vb[(size_t)(t0+r)*INNERC+c];
        }
        __syncthreads();
        float e=scr[t0+tid];
        const float* tr=tile+tid*T2I_TP;
        #pragma unroll
        for(int d=0;d<40;d++)acc[d]+=e*tr[d];
        __syncthreads();
    }
    int lane=tid&31,w=tid>>5;
    #pragma unroll
    for(int d=0;d<40;d++){
        float a=acc[d];
        for(int o=16;o>0;o>>=1)a+=__shfl_down_sync(0xffffffffu,a,o);
        if(lane==0)wred[w][d]=a;
    }
    __syncthreads();
    if(tid<40){
        float o=0.f;
        #pragma unroll
        for(int ww=0;ww<8;ww++)o+=wred[ww][tid];
        out[(size_t)(b*NQ+qi)*INNERC+h*40+tid]=o/gsum;
    }
}

__global__ void k_i2t_attn(const float* __restrict__ qbig,const float* __restrict__ k6,
                           const float* __restrict__ v6,float* __restrict__ out){
    __shared__ __align__(16) float ks[NQ*INNERC];
    __shared__ __align__(16) float vs[NQ*INNERC];
    int b=blockIdx.x>>8;
    for(int i=threadIdx.x;i<NQ*INNERC;i+=256){
        ks[i]=k6[b*NQ*INNERC+i]; vs[i]=v6[b*NQ*INNERC+i];
    }
    __syncthreads();
    int rem=(blockIdx.x&255)*256+threadIdx.x;
    int t=rem>>2,h=rem&3;
    const float* qp=qbig+((size_t)b*NTOK+t)*INNERC+h*40;
    float qv[40];
    #pragma unroll
    for(int d4=0;d4<10;d4++)((float4*)qv)[d4]=((const float4*)qp)[d4];
    float s[NQ];
    #pragma unroll
    for(int j=0;j<NQ;j++){
        float d=0.f;
        #pragma unroll
        for(int dd=0;dd<40;dd++)d+=qv[dd]*ks[j*INNERC+h*40+dd];
        s[j]=d*0.15811388300841897f;
    }
    float m=-1e30f;
    #pragma unroll
    for(int j=0;j<NQ;j++)m=fmaxf(m,s[j]);
    float ssum=0.f;
    #pragma unroll
    for(int j=0;j<NQ;j++){s[j]=expf(s[j]-m);ssum+=s[j];}
    float inv=1.f/ssum;
    float* op=out+((size_t)b*NTOK+t)*INNERC+h*40;
    #pragma unroll
    for(int d4=0;d4<10;d4++){
        float4 o=make_float4(0.f,0.f,0.f,0.f);
        #pragma unroll
        for(int j=0;j<NQ;j++){
            float e=s[j];
            float4 v=((const float4*)(vs+j*INNERC+h*40))[d4];
            o.x+=e*v.x;o.y+=e*v.y;o.z+=e*v.z;o.w+=e*v.w;
        }
        o.x*=inv;o.y*=inv;o.z*=inv;o.w*=inv;
        ((float4*)op)[d4]=o;
    }
}

extern "C" void kernel_launch(void* const* d_in,const int* in_sizes,int n_in,
                              void* d_out,int out_size){
    const float* x=(const float*)d_in[0];
    const float* coords=(const float*)d_in[1];
    const int* labels=(const int*)d_in[2];
    const float* ln_w=(const float*)d_in[3];
    const float* ln_b=(const float*)d_in[4];
    const float* in_w=(const float*)d_in[5];
    const float* conv_w=(const float*)d_in[6];
    const float* conv_b=(const float*)d_in[7];
    const float* dt_bias=(const float*)d_in[8];
    const float* A_log=(const float*)d_in[9];
    const float* Dp=(const float*)d_in[10];
    const float* rms_w=(const float*)d_in[11];
    const float* out_w=(const float*)d_in[12];
    const float* gauss=(const float*)d_in[13];
    const float* ptab=(const float*)d_in[14];
    const float* sa_w=(const float*)d_in[15];
    const float* sa_b=(const float*)d_in[16];
    const float* t2i_w=(const float*)d_in[17];
    const float* t2i_b=(const float*)d_in[18];
    const float* t2i_ow=(const float*)d_in[19];
    const float* t2i_ob=(const float*)d_in[20];
    const float* i2t_w=(const float*)d_in[21];
    const float* i2t_b=(const float*)d_in[22];
    const float* i2t_ow=(const float*)d_in[23];
    const float* i2t_ob=(const float*)d_in[24];
    const float* norms_w=(const float*)d_in[25];
    const float* norms_b=(const float*)d_in[26];
    const float* mlp_w1=(const float*)d_in[27];
    const float* mlp_b1=(const float*)d_in[28];
    const float* mlp_w2=(const float*)d_in[29];
    const float* mlp_b2=(const float*)d_in[30];
    float* outp=(float*)d_out;

    float *p_xn,*p_zx,*p_y,*p_keys,*p_kpe,*p_pe,*p_qr,*p_q6,*p_k6,*p_v6,*p_a6,*p_mlp,*p_kb,*p_vb,*p_qb,*p_ab;
    cudaGetSymbolAddress((void**)&p_xn,g_xn);
    cudaGetSymbolAddress((void**)&p_zx,g_zx);
    cudaGetSymbolAddress((void**)&p_y,g_y);
    cudaGetSymbolAddress((void**)&p_keys,g_keys);
    cudaGetSymbolAddress((void**)&p_kpe,g_kpe);
    cudaGetSymbolAddress((void**)&p_pe,g_pe);
    cudaGetSymbolAddress((void**)&p_qr,g_qr);
    cudaGetSymbolAddress((void**)&p_q6,g_q6);
    cudaGetSymbolAddress((void**)&p_k6,g_k6);
    cudaGetSymbolAddress((void**)&p_v6,g_v6);
    cudaGetSymbolAddress((void**)&p_a6,g_a6);
    cudaGetSymbolAddress((void**)&p_mlp,g_mlpb);
    cudaGetSymbolAddress((void**)&p_kb,g_kb);
    cudaGetSymbolAddress((void**)&p_vb,g_vb);
    cudaGetSymbolAddress((void**)&p_qb,g_qb);
    cudaGetSymbolAddress((void**)&p_ab,g_ab);

    cudaFuncSetAttribute(k_chunkstate,cudaFuncAttributeMaxDynamicSharedMemorySize,CS_SMEM);
    cudaFuncSetAttribute(k_ssd_out,cudaFuncAttributeMaxDynamicSharedMemorySize,SSD_SMEM);
    cudaFuncSetAttribute(k_t2i_attn,cudaFuncAttributeMaxDynamicSharedMemorySize,T2I_SMEM);

    dim3 tg(BB*NQ,4);
    dim3 tg3(BB*NQ,4,3);
    dim3 tg2(BB*NQ,4,2);
    k_kpe<<<NTOK,160>>>(gauss);
    k_transln<<<BB*(NTOK/32),256>>>(x,p_xn,ln_w,ln_b);
    k_pemb<<<BB*NQ,160>>>(coords,labels,gauss,ptab);
    k_gemm_tc<<<dim3(11,256),256>>>(p_xn,nullptr,1,in_w,nullptr,nullptr,p_zx,BB*NTOK,DPROJ,CDIM);
    k_conv2<<<BB*(NTOK/8),256>>>(conv_w,conv_b,dt_bias);
    k_chunkstate<<<BB*NH*NCH,256,CS_SMEM>>>(A_log);
    k_staterec<<<BB*NH,256>>>();
    k_ssd_out<<<BB*NH*NCH,256,SSD_SMEM>>>(Dp);
    k_gate_rms<<<BB*NTOK,256>>>(rms_w);
    k_gemm_tc<<<dim3(3,256),256>>>(p_y,nullptr,1,out_w,nullptr,nullptr,p_keys,BB*NTOK,CDIM,DIN);

    for(int i=0;i<2;i++){
        const float* saw=sa_w+(size_t)i*4*CDIM*CDIM;
        const float* sab=sa_b+(size_t)i*4*CDIM;
        const float* pe0=i?p_pe:nullptr;
        k_tiny3<<<tg3,256,CDIM*4>>>(p_qr,pe0,saw,saw+CDIM*CDIM,saw+2*CDIM*CDIM,
                                    sab,sab+CDIM,sab+2*CDIM,p_q6,p_k6,p_v6,3,CDIM,CDIM);
        k_selfattn<<<BB*4,128>>>(p_q6,p_k6,p_v6,p_a6);
        k_tiny_ln<<<BB*NQ,256,(CDIM+CDIM)*4>>>(p_a6,saw+3*CDIM*CDIM,sab+3*CDIM,
                                               i?p_qr:nullptr,p_qr,
                                               norms_w+(i*4+0)*CDIM,norms_b+(i*4+0)*CDIM,CDIM);
        const float* tw=t2i_w+(size_t)i*3*INNERC*CDIM;
        const float* tb2=t2i_b+(size_t)i*3*INNERC;
        k_tiny<<<tg,256,CDIM*4>>>(p_qr,p_pe,tw,tb2,nullptr,p_q6,INNERC,CDIM,0);
        k_gemm_tc<<<dim3(2,256),256>>>(p_keys,p_kpe,NTOK,tw+1*INNERC*CDIM,tb2+INNERC,nullptr,p_kb,BB*NTOK,INNERC,CDIM);
        k_gemm_tc<<<dim3(2,256),256>>>(p_keys,nullptr,1,tw+2*INNERC*CDIM,tb2+2*INNERC,nullptr,p_vb,BB*NTOK,INNERC,CDIM);
        k_t2i_attn<<<BB*4*NQ,256,T2I_SMEM>>>(p_q6,p_kb,p_vb,p_a6);
        k_tiny_ln<<<BB*NQ,256,(INNERC+CDIM)*4>>>(p_a6,t2i_ow+(size_t)i*CDIM*INNERC,t2i_ob+i*CDIM,
                                                 p_qr,p_qr,
                                                 norms_w+(i*4+1)*CDIM,norms_b+(i*4+1)*CDIM,INNERC);
        k_tiny<<<tg,256,CDIM*4>>>(p_qr,nullptr,mlp_w1+(size_t)i*MLPD*CDIM,mlp_b1+i*MLPD,nullptr,p_mlp,MLPD,CDIM,1);
        k_tiny_ln<<<BB*NQ,256,(MLPD+CDIM)*4>>>(p_mlp,mlp_w2+(size_t)i*CDIM*MLPD,mlp_b2+i*CDIM,
                                               p_qr,p_qr,
                                               norms_w+(i*4+2)*CDIM,norms_b+(i*4+2)*CDIM,MLPD);
        const float* iw=i2t_w+(size_t)i*3*INNERC*CDIM;
        const float* ib=i2t_b+(size_t)i*3*INNERC;
        k_gemm_tc<<<dim3(2,256),256>>>(p_keys,p_kpe,NTOK,iw,ib,nullptr,p_qb,BB*NTOK,INNERC,CDIM);
        k_tiny3<<<tg2,256,CDIM*4>>>(p_qr,p_pe,iw+1*INNERC*CDIM,iw+2*INNERC*CDIM,nullptr,
                                    ib+INNERC,ib+2*INNERC,nullptr,p_k6,p_v6,nullptr,1,INNERC,CDIM);
        k_i2t_attn<<<BB*256,256>>>(p_qb,p_k6,p_v6,p_ab);
        k_gemm_tc<<<dim3(3,256),256>>>(p_ab,nullptr,1,i2t_ow+(size_t)i*CDIM*INNERC,i2t_ob+i*CDIM,p_keys,p_keys,BB*NTOK,CDIM,INNERC);
        if(i==0)
            k_ln<<<BB*NTOK,CDIM>>>(p_keys,p_keys,norms_w+3*CDIM,norms_b+3*CDIM);
    }
    k_lntrans<<<BB*(NTOK/32),256>>>(p_keys,outp,norms_w+7*CDIM,norms_b+7*CDIM);
}

// round 12
// speedup vs baseline: 1.0257x; 1.0257x over previous
#include <cuda_runtime.h>
#include <math.h>
#include <stdint.h>

#define BB 2
#define CDIM 320
#define NTOK 16384
#define DIN 640
#define DSTATE 32
#define NH 8
#define PDIM 80
#define CONVD 704
#define DPROJ 1352
#define INNERC 160
#define NQ 6
#define QCH 128
#define NCH (NTOK/QCH)
#define MLPD 1024
#define LN_EPS 1e-5f
#define TWOPI 6.28318530717958647692f

__device__ float g_xn[BB*NTOK*CDIM];
__device__ float g_zx[BB*NTOK*DPROJ];
__device__ float g_xbc[BB*NTOK*CONVD];
__device__ float g_dt[BB*NTOK*NH];
__device__ float g_cumL[BB*NH*NTOK];
__device__ float g_Sc[BB*NH*NCH*DSTATE*PDIM];
__device__ float g_Sin[BB*NH*NCH*DSTATE*PDIM];
__device__ float g_y[BB*NTOK*DIN];
__device__ float g_keys[BB*NTOK*CDIM];
__device__ float g_kpe[NTOK*CDIM];
__device__ float g_pe[BB*NQ*CDIM];
__device__ float g_qr[BB*NQ*CDIM];
__device__ float g_q6[BB*NQ*CDIM];
__device__ float g_k6[BB*NQ*CDIM];
__device__ float g_v6[BB*NQ*CDIM];
__device__ float g_a6[BB*NQ*CDIM];
__device__ float g_mlpb[BB*NQ*MLPD];
__device__ float g_kb[BB*NTOK*INNERC];
__device__ float g_vb[BB*NTOK*INNERC];
__device__ float g_qb[BB*NTOK*INNERC];
__device__ float g_ab[BB*NTOK*INNERC];

__device__ __forceinline__ float siluf(float x){ return x/(1.f+expf(-x)); }

__device__ __forceinline__ void blockReduce2(float& a,float& b,float* sa,float* sb){
    const unsigned m=0xffffffffu;
    for(int o=16;o>0;o>>=1){a+=__shfl_down_sync(m,a,o);b+=__shfl_down_sync(m,b,o);}
    int lane=threadIdx.x&31,w=threadIdx.x>>5;
    if(lane==0){sa[w]=a;sb[w]=b;}
    __syncthreads();
    int nw=(blockDim.x+31)>>5;
    if(w==0){
        a=(lane<nw)?sa[lane]:0.f; b=(lane<nw)?sb[lane]:0.f;
        for(int o=16;o>0;o>>=1){a+=__shfl_down_sync(m,a,o);b+=__shfl_down_sync(m,b,o);}
        if(lane==0){sa[0]=a;sb[0]=b;}
    }
    __syncthreads();
    a=sa[0];b=sb[0];
}

#define TLP 329
__global__ void k_transln(const float* __restrict__ in,float* __restrict__ out,
                          const float* __restrict__ w,const float* __restrict__ b){
    __shared__ float sm[32*TLP];
    int blk=blockIdx.x;
    int bb=blk/(NTOK/32), t0=(blk%(NTOK/32))*32;
    int tid=threadIdx.x;
    for(int i=tid;i<32*CDIM;i+=256){
        int c=i>>5, tt=i&31;
        sm[tt*TLP+c]=in[((size_t)bb*CDIM+c)*NTOK+t0+tt];
    }
    __syncthreads();
    int lane=tid&31,warp=tid>>5;
    for(int tt=warp;tt<32;tt+=8){
        float s1=0.f,s2=0.f;
        for(int c=lane;c<CDIM;c+=32){float v=sm[tt*TLP+c];s1+=v;s2+=v*v;}
        for(int o=16;o>0;o>>=1){s1+=__shfl_down_sync(0xffffffffu,s1,o);s2+=__shfl_down_sync(0xffffffffu,s2,o);}
        s1=__shfl_sync(0xffffffffu,s1,0); s2=__shfl_sync(0xffffffffu,s2,0);
        float mean=s1*(1.f/CDIM),var=s2*(1.f/CDIM)-mean*mean;
        float r=rsqrtf(var+LN_EPS);
        for(int c=lane;c<CDIM;c+=32)
            sm[tt*TLP+c]=(sm[tt*TLP+c]-mean)*r*w[c]+b[c];
    }
    __syncthreads();
    for(int i=tid;i<32*CDIM;i+=256){
        int tt=i/CDIM,c=i-tt*CDIM;
        out[((size_t)bb*NTOK+t0+tt)*CDIM+c]=sm[tt*TLP+c];
    }
}

__global__ void k_lntrans(const float* __restrict__ in,float* __restrict__ out,
                          const float* __restrict__ w,const float* __restrict__ b){
    __shared__ float sm[32*TLP];
    int blk=blockIdx.x;
    int bb=blk/(NTOK/32), t0=(blk%(NTOK/32))*32;
    int tid=threadIdx.x;
    for(int i=tid;i<32*CDIM;i+=256){
        int tt=i/CDIM,c=i-tt*CDIM;
        sm[tt*TLP+c]=in[((size_t)bb*NTOK+t0+tt)*CDIM+c];
    }
    __syncthreads();
    int lane=tid&31,warp=tid>>5;
    for(int tt=warp;tt<32;tt+=8){
        float s1=0.f,s2=0.f;
        for(int c=lane;c<CDIM;c+=32){float v=sm[tt*TLP+c];s1+=v;s2+=v*v;}
        for(int o=16;o>0;o>>=1){s1+=__shfl_down_sync(0xffffffffu,s1,o);s2+=__shfl_down_sync(0xffffffffu,s2,o);}
        s1=__shfl_sync(0xffffffffu,s1,0); s2=__shfl_sync(0xffffffffu,s2,0);
        float mean=s1*(1.f/CDIM),var=s2*(1.f/CDIM)-mean*mean;
        float r=rsqrtf(var+LN_EPS);
        for(int c=lane;c<CDIM;c+=32)
            sm[tt*TLP+c]=(sm[tt*TLP+c]-mean)*r*w[c]+b[c];
    }
    __syncthreads();
    for(int i=tid;i<32*CDIM;i+=256){
        int c=i>>5, tt=i&31;
        out[((size_t)bb*CDIM+c)*NTOK+t0+tt]=sm[tt*TLP+c];
    }
}

__global__ void k_ln(const float* __restrict__ in,float* __restrict__ out,
                     const float* __restrict__ w,const float* __restrict__ b){
    __shared__ float sa[32],sb[32];
    int row=blockIdx.x;
    float v=in[(size_t)row*CDIM+threadIdx.x];
    float s1=v,s2=v*v;
    blockReduce2(s1,s2,sa,sb);
    float mean=s1*(1.f/CDIM),var=s2*(1.f/CDIM)-mean*mean;
    float r=rsqrtf(var+LN_EPS);
    out[(size_t)row*CDIM+threadIdx.x]=(v-mean)*r*w[threadIdx.x]+b[threadIdx.x];
}

#define UPAD 20
__device__ __forceinline__ uint32_t pk2(float a,float b){
    uint32_t r; asm("cvt.rn.bf16x2.f32 %0, %1, %2;":"=r"(r):"f"(b),"f"(a)); return r;
}
__device__ __forceinline__ void mma_bf(float* d,uint32_t a0,uint32_t a1,uint32_t a2,uint32_t a3,
                                       uint32_t b0,uint32_t b1){
    asm volatile("mma.sync.aligned.m16n8k16.row.col.f32.bf16.bf16.f32 "
        "{%0,%1,%2,%3}, {%4,%5,%6,%7}, {%8,%9}, {%0,%1,%2,%3};"
        : "+f"(d[0]),"+f"(d[1]),"+f"(d[2]),"+f"(d[3])
        : "r"(a0),"r"(a1),"r"(a2),"r"(a3),"r"(b0),"r"(b1));
}

__global__ __launch_bounds__(256) void k_gemm_tc(
        const float* __restrict__ A,const float* __restrict__ Aadd,int addMod,
        const float* __restrict__ W,const float* __restrict__ bias,
        const float* __restrict__ res,float* __restrict__ C,int M,int N,int K){
    __shared__ uint32_t Ah[128*UPAD],Al[128*UPAD],Wh[128*UPAD],Wl[128*UPAD];
    int m0=blockIdx.y*128,n0=blockIdx.x*128;
    int tid=threadIdx.x,lane=tid&31,warp=tid>>5;
    int wm=warp&3,wn=warp>>2,lg=lane>>2,lk=lane&3;
    int bnEnd=(N-n0-wn*64+7)>>3;
    if(bnEnd<0)bnEnd=0; if(bnEnd>8)bnEnd=8;
    float acc[2][8][4];
    #pragma unroll
    for(int am=0;am<2;am++)
        #pragma unroll
        for(int bn=0;bn<8;bn++)
            #pragma unroll
            for(int j=0;j<4;j++)acc[am][bn][j]=0.f;

    for(int kt=0;kt<K;kt+=32){
        #pragma unroll
        for(int i=0;i<4;i++){
            int f=tid+i*256,r=f>>3,kq=(f&7)<<2;
            int gm=m0+r;
            float4 v=*(const float4*)(A+(size_t)gm*K+kt+kq);
            if(Aadd){
                float4 u=*(const float4*)(Aadd+(size_t)(gm%addMod)*K+kt+kq);
                v.x+=u.x;v.y+=u.y;v.z+=u.z;v.w+=u.w;
            }
            uint32_t h0=pk2(v.x,v.y),h1=pk2(v.z,v.w);
            float l0=v.x-__uint_as_float(h0<<16),l1=v.y-__uint_as_float(h0&0xffff0000u);
            float l2=v.z-__uint_as_float(h1<<16),l3=v.w-__uint_as_float(h1&0xffff0000u);
            int si=r*UPAD+(kq>>1);
            *(uint2*)(Ah+si)=make_uint2(h0,h1);
            *(uint2*)(Al+si)=make_uint2(pk2(l0,l1),pk2(l2,l3));
            int gn=n0+r;
            float4 wv=make_float4(0.f,0.f,0.f,0.f);
            if(gn<N)wv=*(const float4*)(W+(size_t)gn*K+kt+kq);
            uint32_t g0=pk2(wv.x,wv.y),g1=pk2(wv.z,wv.w);
            float m0f=wv.x-__uint_as_float(g0<<16),m1f=wv.y-__uint_as_float(g0&0xffff0000u);
            float m2f=wv.z-__uint_as_float(g1<<16),m3f=wv.w-__uint_as_float(g1&0xffff0000u);
            *(uint2*)(Wh+si)=make_uint2(g0,g1);
            *(uint2*)(Wl+si)=make_uint2(pk2(m0f,m1f),pk2(m2f,m3f));
        }
        __syncthreads();
        if(bnEnd>0){
            #pragma unroll
            for(int ks=0;ks<2;ks++){
                uint32_t a0[2],a1[2],a2[2],a3[2],e0[2],e1[2],e2[2],e3[2];
                #pragma unroll
                for(int am=0;am<2;am++){
                    int r=wm*32+am*16+lg,c=ks*8+lk;
                    a0[am]=Ah[r*UPAD+c];     a1[am]=Ah[(r+8)*UPAD+c];
                    a2[am]=Ah[r*UPAD+c+4];   a3[am]=Ah[(r+8)*UPAD+c+4];
                    e0[am]=Al[r*UPAD+c];     e1[am]=Al[(r+8)*UPAD+c];
                    e2[am]=Al[r*UPAD+c+4];   e3[am]=Al[(r+8)*UPAD+c+4];
                }
                for(int bn=0;bn<bnEnd;bn++){
                    int col=wn*64+bn*8+lg,c=ks*8+lk;
                    uint32_t b0=Wh[col*UPAD+c],b1=Wh[col*UPAD+c+4];
                    uint32_t f0=Wl[col*UPAD+c],f1=Wl[col*UPAD+c+4];
                    #pragma unroll
                    for(int am=0;am<2;am++){
                        mma_bf(acc[am][bn],a0[am],a1[am],a2[am],a3[am],b0,b1);
                        mma_bf(acc[am][bn],a0[am],a1[am],a2[am],a3[am],f0,f1);
                        mma_bf(acc[am][bn],e0[am],e1[am],e2[am],e3[am],b0,b1);
                    }
                }
            }
        }
        __syncthreads();
    }
    #pragma unroll
    for(int am=0;am<2;am++){
        int r0=m0+wm*32+am*16+lg;
        for(int bn=0;bn<bnEnd;bn++){
            int c0=n0+wn*64+bn*8+2*lk;
            #pragma unroll
            for(int half=0;half<2;half++){
                int gm=r0+half*8;
                float d0=acc[am][bn][half*2+0],d1=acc[am][bn][half*2+1];
                if(c0<N){
                    float v=d0;
                    if(bias)v+=bias[c0];
                    if(res)v+=res[(size_t)gm*N+c0];
                    C[(size_t)gm*N+c0]=v;
                }
                if(c0+1<N){
                    float v=d1;
                    if(bias)v+=bias[c0+1];
                    if(res)v+=res[(size_t)gm*N+c0+1];
                    C[(size_t)gm*N+c0+1]=v;
                }
            }
        }
    }
}

__global__ void k_conv2(const float* __restrict__ cw,const float* __restrict__ cb,
                        const float* __restrict__ dt_bias){
    __shared__ float sx[11*CONVD];
    int blk=blockIdx.x;
    int bb=blk/(NTOK/8), t0=(blk%(NTOK/8))*8;
    int tid=threadIdx.x;
    for(int i=tid;i<11*CONVD;i+=256){
        int r=i/CONVD,c=i-r*CONVD;
        int tt=t0-3+r;
        sx[i]=(tt>=0)?g_zx[((size_t)bb*NTOK+tt)*DPROJ+DIN+c]:0.f;
    }
    __syncthreads();
    for(int i=tid;i<8*CONVD;i+=256){
        int r=i/CONVD,c=i-r*CONVD;
        float acc=cb[c];
        #pragma unroll
        for(int k=0;k<4;k++)acc+=cw[c*4+k]*sx[(r+k)*CONVD+c];
        g_xbc[((size_t)bb*NTOK+t0+r)*CONVD+c]=siluf(acc);
    }
    if(tid<8*NH){
        int r=tid>>3,h=tid&7;
        float v=g_zx[((size_t)bb*NTOK+t0+r)*DPROJ+DIN+CONVD+h]+dt_bias[h];
        v=(v>20.f)?v:log1pf(expf(v));
        g_dt[((size_t)bb*NTOK+t0+r)*NH+h]=v;
    }
}

__global__ void k_chunkstate(const float* __restrict__ A_log){
    extern __shared__ float sm[];
    float* w=sm; float* Bv=sm+QCH; float* Xv=Bv+QCH*DSTATE;
    float* sc=Xv+QCH*PDIM; float* sdt=sc+QCH;
    int g=blockIdx.x,ch=g%NCH,h=(g/NCH)%NH,b=g/(NCH*NH);
    int tid=threadIdx.x;
    float A=-expf(A_log[h]);
    if(tid<QCH){
        sdt[tid]=g_dt[((size_t)b*NTOK+ch*QCH+tid)*NH+h];
        sc[tid]=sdt[tid]*A;
    }
    __syncthreads();
    for(int off=1;off<QCH;off<<=1){
        float add=(tid>=off&&tid<QCH)?sc[tid-off]:0.f;
        __syncthreads();
        if(tid<QCH)sc[tid]+=add;
        __syncthreads();
    }
    if(tid<QCH)g_cumL[((size_t)(b*NH+h))*NTOK+ch*QCH+tid]=sc[tid];
    float total=sc[QCH-1];
    for(int i=tid;i<QCH;i+=256)
        w[i]=expf(total-sc[i])*sdt[i];
    for(int i=tid;i<QCH*DSTATE;i+=256){
        int s=i>>5,nn=i&31;
        Bv[i]=g_xbc[((size_t)b*NTOK+ch*QCH+s)*CONVD+DIN+nn];
    }
    for(int i=tid;i<QCH*PDIM;i+=256){
        int s=i/PDIM,p=i-s*PDIM;
        Xv[i]=g_xbc[((size_t)b*NTOK+ch*QCH+s)*CONVD+h*PDIM+p];
    }
    __syncthreads();
    int n0=(tid>>4)*2,p0=(tid&15)*5;
    float acc[2][5];
    for(int a=0;a<2;a++)for(int q=0;q<5;q++)acc[a][q]=0.f;
    for(int s=0;s<QCH;s++){
        float ws=w[s],wb0=ws*Bv[s*DSTATE+n0],wb1=ws*Bv[s*DSTATE+n0+1];
        #pragma unroll
        for(int q=0;q<5;q++){
            float xv=Xv[s*PDIM+p0+q];
            acc[0][q]+=wb0*xv; acc[1][q]+=wb1*xv;
        }
    }
    size_t base=(size_t)g*(DSTATE*PDIM);
    for(int a=0;a<2;a++)for(int q=0;q<5;q++)
        g_Sc[base+(size_t)(n0+a)*PDIM+p0+q]=acc[a][q];
}
#define CS_SMEM ((QCH+QCH*DSTATE+QCH*PDIM+QCH+QCH)*4)

__global__ void k_staterec(){
    int bh=blockIdx.x;
    __shared__ float etot[NCH];
    for(int i=threadIdx.x;i<NCH;i+=256)
        etot[i]=expf(g_cumL[(size_t)bh*NTOK+i*QCH+QCH-1]);
    __syncthreads();
    float S[10];
    for(int j=0;j<10;j++)S[j]=0.f;
    for(int c=0;c<NCH;c++){
        size_t base=((size_t)bh*NCH+c)*(DSTATE*PDIM);
        float e=etot[c];
        #pragma unroll
        for(int j=0;j<10;j++){
            int idx=threadIdx.x+j*256;
            g_Sin[base+idx]=S[j];
            S[j]=S[j]*e+g_Sc[base+idx];
        }
    }
}

// SSD output — round-9 proven version (BvT transposed+padded, linear e-indexing)
#define BVP 133
__global__ void k_ssd_out(const float* __restrict__ Dp){
    extern __shared__ float sm[];
    float* Lc=sm; float* dts=Lc+QCH; float* Cv=dts+QCH;
    float* BvT=Cv+QCH*DSTATE; float* Xv=BvT+DSTATE*BVP;
    float* Ss=Xv+QCH*PDIM; float* G=Ss+DSTATE*PDIM;
    int g=blockIdx.x,ch=g%NCH,h=(g/NCH)%NH,b=g/(NCH*NH);
    const float* cl=g_cumL+((size_t)(b*NH+h))*NTOK+ch*QCH;
    for(int i=threadIdx.x;i<QCH;i+=256){
        Lc[i]=cl[i];
        dts[i]=g_dt[((size_t)b*NTOK+ch*QCH+i)*NH+h];
    }
    for(int i=threadIdx.x;i<QCH*DSTATE;i+=256){
        int s=i>>5,nn=i&31;
        size_t rb=((size_t)b*NTOK+ch*QCH+s)*CONVD;
        Cv[i]=g_xbc[rb+DIN+DSTATE+nn];
        BvT[nn*BVP+s]=g_xbc[rb+DIN+nn];
    }
    for(int i=threadIdx.x;i<QCH*PDIM;i+=256){
        int s=i/PDIM,p=i-s*PDIM;
        Xv[i]=g_xbc[((size_t)b*NTOK+ch*QCH+s)*CONVD+h*PDIM+p];
    }
    for(int i=threadIdx.x;i<DSTATE*PDIM;i+=256)
        Ss[i]=g_Sin[(((size_t)(b*NH+h))*NCH+ch)*(DSTATE*PDIM)+i];
    __syncthreads();
    for(int e=threadIdx.x;e<QCH*QCH;e+=256){
        int t=e>>7,s=e&127;
        float val=0.f;
        if(s<=t){
            float d=0.f;
            #pragma unroll
            for(int nn=0;nn<DSTATE;nn++)d+=Cv[t*DSTATE+nn]*BvT[nn*BVP+s];
            val=d*expf(Lc[t]-Lc[s])*dts[s];
        }
        G[e]=val;
    }
    __syncthreads();
    float Dh=Dp[h];
    for(int o4=threadIdx.x;o4<QCH*PDIM/4;o4+=256){
        int idx=o4*4,t=idx/PDIM,p=idx-t*PDIM;
        float4 acc=make_float4(0.f,0.f,0.f,0.f);
        const float* Gt=G+t*QCH;
        for(int s=0;s<=t;s++){
            float gg=Gt[s];
            float4 xv=*(const float4*)(Xv+s*PDIM+p);
            acc.x+=gg*xv.x;acc.y+=gg*xv.y;acc.z+=gg*xv.z;acc.w+=gg*xv.w;
        }
        float4 inter=make_float4(0.f,0.f,0.f,0.f);
        #pragma unroll
        for(int nn=0;nn<DSTATE;nn++){
            float cc=Cv[t*DSTATE+nn];
            float4 sv=*(const float4*)(Ss+nn*PDIM+p);
            inter.x+=cc*sv.x;inter.y+=cc*sv.y;inter.z+=cc*sv.z;inter.w+=cc*sv.w;
        }
        float elt=expf(Lc[t]);
        float4 xt=*(const float4*)(Xv+t*PDIM+p);
        acc.x+=elt*inter.x+Dh*xt.x; acc.y+=elt*inter.y+Dh*xt.y;
        acc.z+=elt*inter.z+Dh*xt.z; acc.w+=elt*inter.w+Dh*xt.w;
        *(float4*)(g_y+((size_t)b*NTOK+ch*QCH+t)*DIN+h*PDIM+p)=acc;
    }
}
#define SSD_SMEM ((QCH+QCH+QCH*DSTATE+DSTATE*BVP+QCH*PDIM+DSTATE*PDIM+QCH*QCH)*4)

__global__ void k_gate_rms(const float* __restrict__ rms_w){
    __shared__ float sa[32],sb[32];
    int row=blockIdx.x;
    float* yr=g_y+(size_t)row*DIN;
    const float* zr=g_zx+(size_t)row*DPROJ;
    float vals[3],ss=0.f;
    #pragma unroll
    for(int i=0;i<3;i++){
        int c=threadIdx.x+i*256;
        float v=0.f;
        if(c<DIN)v=yr[c]*siluf(zr[c]);
        vals[i]=v; ss+=v*v;
    }
    float dummy=0.f;
    blockReduce2(ss,dummy,sa,sb);
    float scale=rsqrtf(ss*(1.f/DIN)+LN_EPS);
    #pragma unroll
    for(int i=0;i<3;i++){
        int c=threadIdx.x+i*256;
        if(c<DIN)yr[c]=vals[i]*scale*rms_w[c];
    }
}

__global__ void k_kpe(const float* __restrict__ gauss){
    int t=blockIdx.x,j=threadIdx.x;
    int d=t>>10,r=t&1023,hh=r>>5,ww=r&31;
    float g0=2.f*((d+0.5f)/16.f)-1.f,g1=2.f*((hh+0.5f)/32.f)-1.f,g2=2.f*((ww+0.5f)/32.f)-1.f;
    float c=TWOPI*(g0*gauss[j]+g1*gauss[160+j]+g2*gauss[320+j]);
    g_kpe[(size_t)t*CDIM+j]=sinf(c);
    g_kpe[(size_t)t*CDIM+160+j]=cosf(c);
}

__global__ void k_pemb(const float* __restrict__ coords,const int* __restrict__ labels,
                       const float* __restrict__ gauss,const float* __restrict__ tab){
    int bp=blockIdx.x,j=threadIdx.x;
    float g0=2.f*(coords[bp*3+0]*(1.f/128.f))-1.f;
    float g1=2.f*(coords[bp*3+1]*(1.f/256.f))-1.f;
    float g2=2.f*(coords[bp*3+2]*(1.f/256.f))-1.f;
    float c=TWOPI*(g0*gauss[j]+g1*gauss[160+j]+g2*gauss[320+j]);
    int lb=labels[bp];
    float s=sinf(c)+tab[lb*CDIM+j],co=cosf(c)+tab[lb*CDIM+160+j];
    g_pe[bp*CDIM+j]=s; g_pe[bp*CDIM+160+j]=co;
    g_qr[bp*CDIM+j]=s; g_qr[bp*CDIM+160+j]=co;
}

__global__ void k_tiny(const float* __restrict__ in,const float* __restrict__ pe,
                       const float* __restrict__ W,const float* __restrict__ bias,
                       const float* __restrict__ res,float* __restrict__ out,
                       int N,int K,int relu){
    extern __shared__ float srow[];
    int m=blockIdx.x;
    for(int i=threadIdx.x;i<K;i+=blockDim.x){
        float v=in[m*K+i];
        if(pe)v+=pe[m*K+i];
        srow[i]=v;
    }
    __syncthreads();
    int lane=threadIdx.x&31,warp=threadIdx.x>>5;
    int nq=N/gridDim.y;
    int nBeg=blockIdx.y*nq,nEnd=nBeg+nq;
    for(int n=nBeg+warp;n<nEnd;n+=8){
        const float* wr=W+(size_t)n*K;
        float acc=0.f;
        for(int kk=lane;kk<K;kk+=32)acc+=srow[kk]*wr[kk];
        #pragma unroll
        for(int o=16;o>0;o>>=1)acc+=__shfl_down_sync(0xffffffffu,acc,o);
        if(lane==0){
            if(bias)acc+=bias[n];
            if(relu)acc=fmaxf(acc,0.f);
            if(res)acc+=res[m*N+n];
            out[m*N+n]=acc;
        }
    }
}

__global__ void k_tiny3(const float* __restrict__ in,const float* __restrict__ pe,
                        const float* __restrict__ W0,const float* __restrict__ W1,const float* __restrict__ W2,
                        const float* __restrict__ b0,const float* __restrict__ b1,const float* __restrict__ b2,
                        float* __restrict__ o0,float* __restrict__ o1,float* __restrict__ o2,
                        int peMask,int N,int K){
    extern __shared__ float srow[];
    int m=blockIdx.x,z=blockIdx.z;
    const float* W=(z==0)?W0:((z==1)?W1:W2);
    const float* bi=(z==0)?b0:((z==1)?b1:b2);
    float* out=(z==0)?o0:((z==1)?o1:o2);
    int usePe=(peMask>>z)&1;
    for(int i=threadIdx.x;i<K;i+=blockDim.x){
        float v=in[m*K+i];
        if(pe&&usePe)v+=pe[m*K+i];
        srow[i]=v;
    }
    __syncthreads();
    int lane=threadIdx.x&31,warp=threadIdx.x>>5;
    int nq=N/gridDim.y;
    int nBeg=blockIdx.y*nq,nEnd=nBeg+nq;
    for(int n=nBeg+warp;n<nEnd;n+=8){
        const float* wr=W+(size_t)n*K;
        float acc=0.f;
        for(int kk=lane;kk<K;kk+=32)acc+=srow[kk]*wr[kk];
        #pragma unroll
        for(int o=16;o>0;o>>=1)acc+=__shfl_down_sync(0xffffffffu,acc,o);
        if(lane==0)out[m*N+n]=acc+(bi?bi[n]:0.f);
    }
}

__global__ void k_tiny_ln(const float* __restrict__ in,const float* __restrict__ W,
                          const float* __restrict__ bias,const float* __restrict__ res,
                          float* __restrict__ out,const float* __restrict__ lnw,
                          const float* __restrict__ lnb,int K){
    extern __shared__ float smem[];
    float* srow=smem;
    float* sout=smem+K;
    __shared__ float sa[32],sb[32];
    int m=blockIdx.x;
    for(int i=threadIdx.x;i<K;i+=256)srow[i]=in[m*K+i];
    __syncthreads();
    int lane=threadIdx.x&31,warp=threadIdx.x>>5;
    for(int n=warp;n<CDIM;n+=8){
        const float* wr=W+(size_t)n*K;
        float acc=0.f;
        for(int kk=lane;kk<K;kk+=32)acc+=srow[kk]*wr[kk];
        #pragma unroll
        for(int o=16;o>0;o>>=1)acc+=__shfl_down_sync(0xffffffffu,acc,o);
        if(lane==0){
            acc+=bias[n];
            if(res)acc+=res[m*CDIM+n];
            sout[n]=acc;
        }
    }
    __syncthreads();
    float v0=(threadIdx.x<CDIM)?sout[threadIdx.x]:0.f;
    int e1=threadIdx.x+256;
    float v1=(e1<CDIM)?sout[e1]:0.f;
    float s1=v0+v1,s2=v0*v0+v1*v1;
    blockReduce2(s1,s2,sa,sb);
    float mean=s1*(1.f/CDIM),var=s2*(1.f/CDIM)-mean*mean;
    float r=rsqrtf(var+LN_EPS);
    if(threadIdx.x<CDIM)out[m*CDIM+threadIdx.x]=(v0-mean)*r*lnw[threadIdx.x]+lnb[threadIdx.x];
    if(e1<CDIM)out[m*CDIM+e1]=(v1-mean)*r*lnw[e1]+lnb[e1];
}

__global__ void k_selfattn(const float* __restrict__ q,const float* __restrict__ k,
                           const float* __restrict__ v,float* __restrict__ out){
    int bh=blockIdx.x,b=bh>>2,h=bh&3;
    __shared__ float qs[NQ][80],ks[NQ][80],vs[NQ][80],p[NQ][NQ];
    for(int i=threadIdx.x;i<NQ*80;i+=blockDim.x){
        int r=i/80,d=i-r*80;
        size_t off=(size_t)(b*NQ+r)*CDIM+h*80+d;
        qs[r][d]=q[off];ks[r][d]=k[off];vs[r][d]=v[off];
    }
    __syncthreads();
    if(threadIdx.x<36){
        int i=threadIdx.x/6,j=threadIdx.x%6;
        float s=0.f;
        #pragma unroll
        for(int d=0;d<80;d++)s+=qs[i][d]*ks[j][d];
        p[i][j]=s*0.11180339887498949f;
    }
    __syncthreads();
    if(threadIdx.x<NQ){
        int i=threadIdx.x;
        float m=-1e30f;
        for(int j=0;j<NQ;j++)m=fmaxf(m,p[i][j]);
        float ssum=0.f;
        for(int j=0;j<NQ;j++){float e=expf(p[i][j]-m);p[i][j]=e;ssum+=e;}
        float inv=1.f/ssum;
        for(int j=0;j<NQ;j++)p[i][j]*=inv;
    }
    __syncthreads();
    if(threadIdx.x<80){
        int d=threadIdx.x;
        for(int i=0;i<NQ;i++){
            float o=0.f;
            #pragma unroll
            for(int j=0;j<NQ;j++)o+=p[i][j]*vs[j][d];
            out[(size_t)(b*NQ+i)*CDIM+h*80+d]=o;
        }
    }
}

#define T2I_TP 41
#define T2I_SMEM ((NTOK + 256*T2I_TP + 256)*4)
__global__ void k_t2i_attn(const float* __restrict__ q6,const float* __restrict__ kbig,
                           const float* __restrict__ vbig,float* __restrict__ out){
    extern __shared__ float sm[];
    float* scr=sm;
    float* tile=sm+NTOK;
    float* red=tile+256*T2I_TP;
    __shared__ float wred[8][40];
    int g=blockIdx.x,qi=g%6,h=(g/6)%4,b=g/24;
    int tid=threadIdx.x;
    float qv[40];
    const float* qp=q6+(size_t)(b*NQ+qi)*INNERC+h*40;
    #pragma unroll
    for(int d=0;d<40;d++)qv[d]=qp[d]*0.15811388300841897f;
    const float* kb=kbig+(size_t)b*NTOK*INNERC+h*40;
    float lmax=-1e30f;
    for(int t0=0;t0<NTOK;t0+=256){
        for(int i=tid;i<256*40;i+=256){
            int r=i/40,c=i-r*40;
            tile[r*T2I_TP+c]=kb[(size_t)(t0+r)*INNERC+c];
        }
        __syncthreads();
        const float* tr=tile+tid*T2I_TP;
        float s=0.f;
        #pragma unroll
        for(int d=0;d<40;d++)s+=qv[d]*tr[d];
        scr[t0+tid]=s; lmax=fmaxf(lmax,s);
        __syncthreads();
    }
    red[tid]=lmax;__syncthreads();
    for(int o=128;o>0;o>>=1){if(tid<o)red[tid]=fmaxf(red[tid],red[tid+o]);__syncthreads();}
    float gmax=red[0];__syncthreads();
    float lsum=0.f;
    for(int kk=tid;kk<NTOK;kk+=256){float e=expf(scr[kk]-gmax);scr[kk]=e;lsum+=e;}
    red[tid]=lsum;__syncthreads();
    for(int o=128;o>0;o>>=1){if(tid<o)red[tid]+=red[tid+o];__syncthreads();}
    float gsum=red[0];__syncthreads();
    float acc[40];
    #pragma unroll
    for(int d=0;d<40;d++)acc[d]=0.f;
    const float* vb=vbig+(size_t)b*NTOK*INNERC+h*40;
    for(int t0=0;t0<NTOK;t0+=256){
        for(int i=tid;i<256*40;i+=256){
            int r=i/40,c=i-r*40;
            tile[r*T2I_TP+c]=vb[(size_t)(t0+r)*INNERC+c];
        }
        __syncthreads();
        float e=scr[t0+tid];
        const float* tr=tile+tid*T2I_TP;
        #pragma unroll
        for(int d=0;d<40;d++)acc[d]+=e*tr[d];
        __syncthreads();
    }
    int lane=tid&31,w=tid>>5;
    #pragma unroll
    for(int d=0;d<40;d++){
        float a=acc[d];
        for(int o=16;o>0;o>>=1)a+=__shfl_down_sync(0xffffffffu,a,o);
        if(lane==0)wred[w][d]=a;
    }
    __syncthreads();
    if(tid<40){
        float o=0.f;
        #pragma unroll
        for(int ww=0;ww<8;ww++)o+=wred[ww][tid];
        out[(size_t)(b*NQ+qi)*INNERC+h*40+tid]=o/gsum;
    }
}

__global__ void k_i2t_attn(const float* __restrict__ qbig,const float* __restrict__ k6,
                           const float* __restrict__ v6,float* __restrict__ out){
    __shared__ __align__(16) float ks[NQ*INNERC];
    __shared__ __align__(16) float vs[NQ*INNERC];
    int b=blockIdx.x>>8;
    for(int i=threadIdx.x;i<NQ*INNERC;i+=256){
        ks[i]=k6[b*NQ*INNERC+i]; vs[i]=v6[b*NQ*INNERC+i];
    }
    __syncthreads();
    int rem=(blockIdx.x&255)*256+threadIdx.x;
    int t=rem>>2,h=rem&3;
    const float* qp=qbig+((size_t)b*NTOK+t)*INNERC+h*40;
    float qv[40];
    #pragma unroll
    for(int d4=0;d4<10;d4++)((float4*)qv)[d4]=((const float4*)qp)[d4];
    float s[NQ];
    #pragma unroll
    for(int j=0;j<NQ;j++){
        float d=0.f;
        #pragma unroll
        for(int dd=0;dd<40;dd++)d+=qv[dd]*ks[j*INNERC+h*40+dd];
        s[j]=d*0.15811388300841897f;
    }
    float m=-1e30f;
    #pragma unroll
    for(int j=0;j<NQ;j++)m=fmaxf(m,s[j]);
    float ssum=0.f;
    #pragma unroll
    for(int j=0;j<NQ;j++){s[j]=expf(s[j]-m);ssum+=s[j];}
    float inv=1.f/ssum;
    float* op=out+((size_t)b*NTOK+t)*INNERC+h*40;
    #pragma unroll
    for(int d4=0;d4<10;d4++){
        float4 o=make_float4(0.f,0.f,0.f,0.f);
        #pragma unroll
        for(int j=0;j<NQ;j++){
            float e=s[j];
            float4 v=((const float4*)(vs+j*INNERC+h*40))[d4];
            o.x+=e*v.x;o.y+=e*v.y;o.z+=e*v.z;o.w+=e*v.w;
        }
        o.x*=inv;o.y*=inv;o.z*=inv;o.w*=inv;
        ((float4*)op)[d4]=o;
    }
}

extern "C" void kernel_launch(void* const* d_in,const int* in_sizes,int n_in,
                              void* d_out,int out_size){
    const float* x=(const float*)d_in[0];
    const float* coords=(const float*)d_in[1];
    const int* labels=(const int*)d_in[2];
    const float* ln_w=(const float*)d_in[3];
    const float* ln_b=(const float*)d_in[4];
    const float* in_w=(const float*)d_in[5];
    const float* conv_w=(const float*)d_in[6];
    const float* conv_b=(const float*)d_in[7];
    const float* dt_bias=(const float*)d_in[8];
    const float* A_log=(const float*)d_in[9];
    const float* Dp=(const float*)d_in[10];
    const float* rms_w=(const float*)d_in[11];
    const float* out_w=(const float*)d_in[12];
    const float* gauss=(const float*)d_in[13];
    const float* ptab=(const float*)d_in[14];
    const float* sa_w=(const float*)d_in[15];
    const float* sa_b=(const float*)d_in[16];
    const float* t2i_w=(const float*)d_in[17];
    const float* t2i_b=(const float*)d_in[18];
    const float* t2i_ow=(const float*)d_in[19];
    const float* t2i_ob=(const float*)d_in[20];
    const float* i2t_w=(const float*)d_in[21];
    const float* i2t_b=(const float*)d_in[22];
    const float* i2t_ow=(const float*)d_in[23];
    const float* i2t_ob=(const float*)d_in[24];
    const float* norms_w=(const float*)d_in[25];
    const float* norms_b=(const float*)d_in[26];
    const float* mlp_w1=(const float*)d_in[27];
    const float* mlp_b1=(const float*)d_in[28];
    const float* mlp_w2=(const float*)d_in[29];
    const float* mlp_b2=(const float*)d_in[30];
    float* outp=(float*)d_out;

    float *p_xn,*p_zx,*p_y,*p_keys,*p_kpe,*p_pe,*p_qr,*p_q6,*p_k6,*p_v6,*p_a6,*p_mlp,*p_kb,*p_vb,*p_qb,*p_ab;
    cudaGetSymbolAddress((void**)&p_xn,g_xn);
    cudaGetSymbolAddress((void**)&p_zx,g_zx);
    cudaGetSymbolAddress((void**)&p_y,g_y);
    cudaGetSymbolAddress((void**)&p_keys,g_keys);
    cudaGetSymbolAddress((void**)&p_kpe,g_kpe);
    cudaGetSymbolAddress((void**)&p_pe,g_pe);
    cudaGetSymbolAddress((void**)&p_qr,g_qr);
    cudaGetSymbolAddress((void**)&p_q6,g_q6);
    cudaGetSymbolAddress((void**)&p_k6,g_k6);
    cudaGetSymbolAddress((void**)&p_v6,g_v6);
    cudaGetSymbolAddress((void**)&p_a6,g_a6);
    cudaGetSymbolAddress((void**)&p_mlp,g_mlpb);
    cudaGetSymbolAddress((void**)&p_kb,g_kb);
    cudaGetSymbolAddress((void**)&p_vb,g_vb);
    cudaGetSymbolAddress((void**)&p_qb,g_qb);
    cudaGetSymbolAddress((void**)&p_ab,g_ab);

    cudaFuncSetAttribute(k_chunkstate,cudaFuncAttributeMaxDynamicSharedMemorySize,CS_SMEM);
    cudaFuncSetAttribute(k_ssd_out,cudaFuncAttributeMaxDynamicSharedMemorySize,SSD_SMEM);
    cudaFuncSetAttribute(k_t2i_attn,cudaFuncAttributeMaxDynamicSharedMemorySize,T2I_SMEM);

    dim3 tg(BB*NQ,4);
    dim3 tg3(BB*NQ,4,3);
    dim3 tg2(BB*NQ,4,2);
    k_kpe<<<NTOK,160>>>(gauss);
    k_transln<<<BB*(NTOK/32),256>>>(x,p_xn,ln_w,ln_b);
    k_pemb<<<BB*NQ,160>>>(coords,labels,gauss,ptab);
    k_gemm_tc<<<dim3(11,256),256>>>(p_xn,nullptr,1,in_w,nullptr,nullptr,p_zx,BB*NTOK,DPROJ,CDIM);
    k_conv2<<<BB*(NTOK/8),256>>>(conv_w,conv_b,dt_bias);
    k_chunkstate<<<BB*NH*NCH,256,CS_SMEM>>>(A_log);
    k_staterec<<<BB*NH,256>>>();
    k_ssd_out<<<BB*NH*NCH,256,SSD_SMEM>>>(Dp);
    k_gate_rms<<<BB*NTOK,256>>>(rms_w);
    k_gemm_tc<<<dim3(3,256),256>>>(p_y,nullptr,1,out_w,nullptr,nullptr,p_keys,BB*NTOK,CDIM,DIN);

    for(int i=0;i<2;i++){
        const float* saw=sa_w+(size_t)i*4*CDIM*CDIM;
        const float* sab=sa_b+(size_t)i*4*CDIM;
        const float* pe0=i?p_pe:nullptr;
        k_tiny3<<<tg3,256,CDIM*4>>>(p_qr,pe0,saw,saw+CDIM*CDIM,saw+2*CDIM*CDIM,
                                    sab,sab+CDIM,sab+2*CDIM,p_q6,p_k6,p_v6,3,CDIM,CDIM);
        k_selfattn<<<BB*4,128>>>(p_q6,p_k6,p_v6,p_a6);
        k_tiny_ln<<<BB*NQ,256,(CDIM+CDIM)*4>>>(p_a6,saw+3*CDIM*CDIM,sab+3*CDIM,
                                               i?p_qr:nullptr,p_qr,
                                               norms_w+(i*4+0)*CDIM,norms_b+(i*4+0)*CDIM,CDIM);
        const float* tw=t2i_w+(size_t)i*3*INNERC*CDIM;
        const float* tb2=t2i_b+(size_t)i*3*INNERC;
        k_tiny<<<tg,256,CDIM*4>>>(p_qr,p_pe,tw,tb2,nullptr,p_q6,INNERC,CDIM,0);
        k_gemm_tc<<<dim3(2,256),256>>>(p_keys,p_kpe,NTOK,tw+1*INNERC*CDIM,tb2+INNERC,nullptr,p_kb,BB*NTOK,INNERC,CDIM);
        k_gemm_tc<<<dim3(2,256),256>>>(p_keys,nullptr,1,tw+2*INNERC*CDIM,tb2+2*INNERC,nullptr,p_vb,BB*NTOK,INNERC,CDIM);
        k_t2i_attn<<<BB*4*NQ,256,T2I_SMEM>>>(p_q6,p_kb,p_vb,p_a6);
        k_tiny_ln<<<BB*NQ,256,(INNERC+CDIM)*4>>>(p_a6,t2i_ow+(size_t)i*CDIM*INNERC,t2i_ob+i*CDIM,
                                                 p_qr,p_qr,
                                                 norms_w+(i*4+1)*CDIM,norms_b+(i*4+1)*CDIM,INNERC);
        k_tiny<<<tg,256,CDIM*4>>>(p_qr,nullptr,mlp_w1+(size_t)i*MLPD*CDIM,mlp_b1+i*MLPD,nullptr,p_mlp,MLPD,CDIM,1);
        k_tiny_ln<<<BB*NQ,256,(MLPD+CDIM)*4>>>(p_mlp,mlp_w2+(size_t)i*CDIM*MLPD,mlp_b2+i*CDIM,
                                               p_qr,p_qr,
                                               norms_w+(i*4+2)*CDIM,norms_b+(i*4+2)*CDIM,MLPD);
        const float* iw=i2t_w+(size_t)i*3*INNERC*CDIM;
        const float* ib=i2t_b+(size_t)i*3*INNERC;
        k_gemm_tc<<<dim3(2,256),256>>>(p_keys,p_kpe,NTOK,iw,ib,nullptr,p_qb,BB*NTOK,INNERC,CDIM);
        k_tiny3<<<tg2,256,CDIM*4>>>(p_qr,p_pe,iw+1*INNERC*CDIM,iw+2*INNERC*CDIM,nullptr,
                                    ib+INNERC,ib+2*INNERC,nullptr,p_k6,p_v6,nullptr,1,INNERC,CDIM);
        k_i2t_attn<<<BB*256,256>>>(p_qb,p_k6,p_v6,p_ab);
        k_gemm_tc<<<dim3(3,256),256>>>(p_ab,nullptr,1,i2t_ow+(size_t)i*CDIM*INNERC,i2t_ob+i*CDIM,p_keys,p_keys,BB*NTOK,CDIM,INNERC);
        if(i==0)
            k_ln<<<BB*NTOK,CDIM>>>(p_keys,p_keys,norms_w+3*CDIM,norms_b+3*CDIM);
    }
    k_lntrans<<<BB*(NTOK/32),256>>>(p_keys,outp,norms_w+7*CDIM,norms_b+7*CDIM);
}

// round 13
// speedup vs baseline: 1.0330x; 1.0071x over previous
#include <cuda_runtime.h>
#include <math.h>
#include <stdint.h>

#define BB 2
#define CDIM 320
#define NTOK 16384
#define DIN 640
#define DSTATE 32
#define NH 8
#define PDIM 80
#define CONVD 704
#define DPROJ 1352
#define INNERC 160
#define NQ 6
#define QCH 128
#define NCH (NTOK/QCH)
#define MLPD 1024
#define LN_EPS 1e-5f
#define TWOPI 6.28318530717958647692f

__device__ float g_xn[BB*NTOK*CDIM];
__device__ float g_zx[BB*NTOK*DPROJ];
__device__ float g_xbc[BB*NTOK*CONVD];
__device__ float g_dt[BB*NTOK*NH];
__device__ float g_cumL[BB*NH*NTOK];
__device__ float g_Sc[BB*NH*NCH*DSTATE*PDIM];
__device__ float g_Sin[BB*NH*NCH*DSTATE*PDIM];
__device__ float g_y[BB*NTOK*DIN];
__device__ float g_keys[BB*NTOK*CDIM];
__device__ float g_kpe[NTOK*CDIM];
__device__ float g_pe[BB*NQ*CDIM];
__device__ float g_qr[BB*NQ*CDIM];
__device__ float g_q6[BB*NQ*CDIM];
__device__ float g_k6[BB*NQ*CDIM];
__device__ float g_v6[BB*NQ*CDIM];
__device__ float g_a6[BB*NQ*CDIM];
__device__ float g_mlpb[BB*NQ*MLPD];
__device__ float g_kb[BB*NTOK*INNERC];
__device__ float g_vb[BB*NTOK*INNERC];
__device__ float g_qb[BB*NTOK*INNERC];
__device__ float g_ab[BB*NTOK*INNERC];

__device__ __forceinline__ float siluf(float x){ return x/(1.f+expf(-x)); }

__device__ __forceinline__ void blockReduce2(float& a,float& b,float* sa,float* sb){
    const unsigned m=0xffffffffu;
    for(int o=16;o>0;o>>=1){a+=__shfl_down_sync(m,a,o);b+=__shfl_down_sync(m,b,o);}
    int lane=threadIdx.x&31,w=threadIdx.x>>5;
    if(lane==0){sa[w]=a;sb[w]=b;}
    __syncthreads();
    int nw=(blockDim.x+31)>>5;
    if(w==0){
        a=(lane<nw)?sa[lane]:0.f; b=(lane<nw)?sb[lane]:0.f;
        for(int o=16;o>0;o>>=1){a+=__shfl_down_sync(m,a,o);b+=__shfl_down_sync(m,b,o);}
        if(lane==0){sa[0]=a;sb[0]=b;}
    }
    __syncthreads();
    a=sa[0];b=sb[0];
}

#define TLP 329
__global__ void k_transln(const float* __restrict__ in,float* __restrict__ out,
                          const float* __restrict__ w,const float* __restrict__ b){
    __shared__ float sm[32*TLP];
    int blk=blockIdx.x;
    int bb=blk/(NTOK/32), t0=(blk%(NTOK/32))*32;
    int tid=threadIdx.x;
    for(int i=tid;i<32*CDIM;i+=256){
        int c=i>>5, tt=i&31;
        sm[tt*TLP+c]=in[((size_t)bb*CDIM+c)*NTOK+t0+tt];
    }
    __syncthreads();
    int lane=tid&31,warp=tid>>5;
    for(int tt=warp;tt<32;tt+=8){
        float s1=0.f,s2=0.f;
        for(int c=lane;c<CDIM;c+=32){float v=sm[tt*TLP+c];s1+=v;s2+=v*v;}
        for(int o=16;o>0;o>>=1){s1+=__shfl_down_sync(0xffffffffu,s1,o);s2+=__shfl_down_sync(0xffffffffu,s2,o);}
        s1=__shfl_sync(0xffffffffu,s1,0); s2=__shfl_sync(0xffffffffu,s2,0);
        float mean=s1*(1.f/CDIM),var=s2*(1.f/CDIM)-mean*mean;
        float r=rsqrtf(var+LN_EPS);
        for(int c=lane;c<CDIM;c+=32)
            sm[tt*TLP+c]=(sm[tt*TLP+c]-mean)*r*w[c]+b[c];
    }
    __syncthreads();
    for(int i=tid;i<32*CDIM;i+=256){
        int tt=i/CDIM,c=i-tt*CDIM;
        out[((size_t)bb*NTOK+t0+tt)*CDIM+c]=sm[tt*TLP+c];
    }
}

__global__ void k_lntrans(const float* __restrict__ in,float* __restrict__ out,
                          const float* __restrict__ w,const float* __restrict__ b){
    __shared__ float sm[32*TLP];
    int blk=blockIdx.x;
    int bb=blk/(NTOK/32), t0=(blk%(NTOK/32))*32;
    int tid=threadIdx.x;
    for(int i=tid;i<32*CDIM;i+=256){
        int tt=i/CDIM,c=i-tt*CDIM;
        sm[tt*TLP+c]=in[((size_t)bb*NTOK+t0+tt)*CDIM+c];
    }
    __syncthreads();
    int lane=tid&31,warp=tid>>5;
    for(int tt=warp;tt<32;tt+=8){
        float s1=0.f,s2=0.f;
        for(int c=lane;c<CDIM;c+=32){float v=sm[tt*TLP+c];s1+=v;s2+=v*v;}
        for(int o=16;o>0;o>>=1){s1+=__shfl_down_sync(0xffffffffu,s1,o);s2+=__shfl_down_sync(0xffffffffu,s2,o);}
        s1=__shfl_sync(0xffffffffu,s1,0); s2=__shfl_sync(0xffffffffu,s2,0);
        float mean=s1*(1.f/CDIM),var=s2*(1.f/CDIM)-mean*mean;
        float r=rsqrtf(var+LN_EPS);
        for(int c=lane;c<CDIM;c+=32)
            sm[tt*TLP+c]=(sm[tt*TLP+c]-mean)*r*w[c]+b[c];
    }
    __syncthreads();
    for(int i=tid;i<32*CDIM;i+=256){
        int c=i>>5, tt=i&31;
        out[((size_t)bb*CDIM+c)*NTOK+t0+tt]=sm[tt*TLP+c];
    }
}

__global__ void k_ln(const float* __restrict__ in,float* __restrict__ out,
                     const float* __restrict__ w,const float* __restrict__ b){
    __shared__ float sa[32],sb[32];
    int row=blockIdx.x;
    float v=in[(size_t)row*CDIM+threadIdx.x];
    float s1=v,s2=v*v;
    blockReduce2(s1,s2,sa,sb);
    float mean=s1*(1.f/CDIM),var=s2*(1.f/CDIM)-mean*mean;
    float r=rsqrtf(var+LN_EPS);
    out[(size_t)row*CDIM+threadIdx.x]=(v-mean)*r*w[threadIdx.x]+b[threadIdx.x];
}

#define UPAD 20
__device__ __forceinline__ uint32_t pk2(float a,float b){
    uint32_t r; asm("cvt.rn.bf16x2.f32 %0, %1, %2;":"=r"(r):"f"(b),"f"(a)); return r;
}
__device__ __forceinline__ void mma_bf(float* d,uint32_t a0,uint32_t a1,uint32_t a2,uint32_t a3,
                                       uint32_t b0,uint32_t b1){
    asm volatile("mma.sync.aligned.m16n8k16.row.col.f32.bf16.bf16.f32 "
        "{%0,%1,%2,%3}, {%4,%5,%6,%7}, {%8,%9}, {%0,%1,%2,%3};"
        : "+f"(d[0]),"+f"(d[1]),"+f"(d[2]),"+f"(d[3])
        : "r"(a0),"r"(a1),"r"(a2),"r"(a3),"r"(b0),"r"(b1));
}

__global__ __launch_bounds__(256) void k_gemm_tc(
        const float* __restrict__ A,const float* __restrict__ Aadd,int addMod,
        const float* __restrict__ W,const float* __restrict__ bias,
        const float* __restrict__ res,float* __restrict__ C,int M,int N,int K){
    __shared__ uint32_t Ah[128*UPAD],Al[128*UPAD],Wh[128*UPAD],Wl[128*UPAD];
    int m0=blockIdx.y*128,n0=blockIdx.x*128;
    int tid=threadIdx.x,lane=tid&31,warp=tid>>5;
    int wm=warp&3,wn=warp>>2,lg=lane>>2,lk=lane&3;
    int bnEnd=(N-n0-wn*64+7)>>3;
    if(bnEnd<0)bnEnd=0; if(bnEnd>8)bnEnd=8;
    float acc[2][8][4];
    #pragma unroll
    for(int am=0;am<2;am++)
        #pragma unroll
        for(int bn=0;bn<8;bn++)
            #pragma unroll
            for(int j=0;j<4;j++)acc[am][bn][j]=0.f;

    for(int kt=0;kt<K;kt+=32){
        #pragma unroll
        for(int i=0;i<4;i++){
            int f=tid+i*256,r=f>>3,kq=(f&7)<<2;
            int gm=m0+r;
            float4 v=*(const float4*)(A+(size_t)gm*K+kt+kq);
            if(Aadd){
                float4 u=*(const float4*)(Aadd+(size_t)(gm%addMod)*K+kt+kq);
                v.x+=u.x;v.y+=u.y;v.z+=u.z;v.w+=u.w;
            }
            uint32_t h0=pk2(v.x,v.y),h1=pk2(v.z,v.w);
            float l0=v.x-__uint_as_float(h0<<16),l1=v.y-__uint_as_float(h0&0xffff0000u);
            float l2=v.z-__uint_as_float(h1<<16),l3=v.w-__uint_as_float(h1&0xffff0000u);
            int si=r*UPAD+(kq>>1);
            *(uint2*)(Ah+si)=make_uint2(h0,h1);
            *(uint2*)(Al+si)=make_uint2(pk2(l0,l1),pk2(l2,l3));
            int gn=n0+r;
            float4 wv=make_float4(0.f,0.f,0.f,0.f);
            if(gn<N)wv=*(const float4*)(W+(size_t)gn*K+kt+kq);
            uint32_t g0=pk2(wv.x,wv.y),g1=pk2(wv.z,wv.w);
            float m0f=wv.x-__uint_as_float(g0<<16),m1f=wv.y-__uint_as_float(g0&0xffff0000u);
            float m2f=wv.z-__uint_as_float(g1<<16),m3f=wv.w-__uint_as_float(g1&0xffff0000u);
            *(uint2*)(Wh+si)=make_uint2(g0,g1);
            *(uint2*)(Wl+si)=make_uint2(pk2(m0f,m1f),pk2(m2f,m3f));
        }
        __syncthreads();
        if(bnEnd>0){
            #pragma unroll
            for(int ks=0;ks<2;ks++){
                uint32_t a0[2],a1[2],a2[2],a3[2],e0[2],e1[2],e2[2],e3[2];
                #pragma unroll
                for(int am=0;am<2;am++){
                    int r=wm*32+am*16+lg,c=ks*8+lk;
                    a0[am]=Ah[r*UPAD+c];     a1[am]=Ah[(r+8)*UPAD+c];
                    a2[am]=Ah[r*UPAD+c+4];   a3[am]=Ah[(r+8)*UPAD+c+4];
                    e0[am]=Al[r*UPAD+c];     e1[am]=Al[(r+8)*UPAD+c];
                    e2[am]=Al[r*UPAD+c+4];   e3[am]=Al[(r+8)*UPAD+c+4];
                }
                for(int bn=0;bn<bnEnd;bn++){
                    int col=wn*64+bn*8+lg,c=ks*8+lk;
                    uint32_t b0=Wh[col*UPAD+c],b1=Wh[col*UPAD+c+4];
                    uint32_t f0=Wl[col*UPAD+c],f1=Wl[col*UPAD+c+4];
                    #pragma unroll
                    for(int am=0;am<2;am++){
                        mma_bf(acc[am][bn],a0[am],a1[am],a2[am],a3[am],b0,b1);
                        mma_bf(acc[am][bn],a0[am],a1[am],a2[am],a3[am],f0,f1);
                        mma_bf(acc[am][bn],e0[am],e1[am],e2[am],e3[am],b0,b1);
                    }
                }
            }
        }
        __syncthreads();
    }
    #pragma unroll
    for(int am=0;am<2;am++){
        int r0=m0+wm*32+am*16+lg;
        for(int bn=0;bn<bnEnd;bn++){
            int c0=n0+wn*64+bn*8+2*lk;
            #pragma unroll
            for(int half=0;half<2;half++){
                int gm=r0+half*8;
                float d0=acc[am][bn][half*2+0],d1=acc[am][bn][half*2+1];
                if(c0<N){
                    float v=d0;
                    if(bias)v+=bias[c0];
                    if(res)v+=res[(size_t)gm*N+c0];
                    C[(size_t)gm*N+c0]=v;
                }
                if(c0+1<N){
                    float v=d1;
                    if(bias)v+=bias[c0+1];
                    if(res)v+=res[(size_t)gm*N+c0+1];
                    C[(size_t)gm*N+c0+1]=v;
                }
            }
        }
    }
}

__global__ void k_conv2(const float* __restrict__ cw,const float* __restrict__ cb,
                        const float* __restrict__ dt_bias){
    __shared__ float sx[11*CONVD];
    int blk=blockIdx.x;
    int bb=blk/(NTOK/8), t0=(blk%(NTOK/8))*8;
    int tid=threadIdx.x;
    for(int i=tid;i<11*CONVD;i+=256){
        int r=i/CONVD,c=i-r*CONVD;
        int tt=t0-3+r;
        sx[i]=(tt>=0)?g_zx[((size_t)bb*NTOK+tt)*DPROJ+DIN+c]:0.f;
    }
    __syncthreads();
    for(int i=tid;i<8*CONVD;i+=256){
        int r=i/CONVD,c=i-r*CONVD;
        float acc=cb[c];
        #pragma unroll
        for(int k=0;k<4;k++)acc+=cw[c*4+k]*sx[(r+k)*CONVD+c];
        g_xbc[((size_t)bb*NTOK+t0+r)*CONVD+c]=siluf(acc);
    }
    if(tid<8*NH){
        int r=tid>>3,h=tid&7;
        float v=g_zx[((size_t)bb*NTOK+t0+r)*DPROJ+DIN+CONVD+h]+dt_bias[h];
        v=(v>20.f)?v:log1pf(expf(v));
        g_dt[((size_t)bb*NTOK+t0+r)*NH+h]=v;
    }
}

__global__ void k_chunkstate(const float* __restrict__ A_log){
    extern __shared__ float sm[];
    float* w=sm; float* Bv=sm+QCH; float* Xv=Bv+QCH*DSTATE;
    float* sc=Xv+QCH*PDIM; float* sdt=sc+QCH;
    int g=blockIdx.x,ch=g%NCH,h=(g/NCH)%NH,b=g/(NCH*NH);
    int tid=threadIdx.x;
    float A=-expf(A_log[h]);
    if(tid<QCH){
        sdt[tid]=g_dt[((size_t)b*NTOK+ch*QCH+tid)*NH+h];
        sc[tid]=sdt[tid]*A;
    }
    __syncthreads();
    for(int off=1;off<QCH;off<<=1){
        float add=(tid>=off&&tid<QCH)?sc[tid-off]:0.f;
        __syncthreads();
        if(tid<QCH)sc[tid]+=add;
        __syncthreads();
    }
    if(tid<QCH)g_cumL[((size_t)(b*NH+h))*NTOK+ch*QCH+tid]=sc[tid];
    float total=sc[QCH-1];
    for(int i=tid;i<QCH;i+=256)
        w[i]=expf(total-sc[i])*sdt[i];
    for(int i=tid;i<QCH*DSTATE;i+=256){
        int s=i>>5,nn=i&31;
        Bv[i]=g_xbc[((size_t)b*NTOK+ch*QCH+s)*CONVD+DIN+nn];
    }
    for(int i=tid;i<QCH*PDIM;i+=256){
        int s=i/PDIM,p=i-s*PDIM;
        Xv[i]=g_xbc[((size_t)b*NTOK+ch*QCH+s)*CONVD+h*PDIM+p];
    }
    __syncthreads();
    int n0=(tid>>4)*2,p0=(tid&15)*5;
    float acc[2][5];
    for(int a=0;a<2;a++)for(int q=0;q<5;q++)acc[a][q]=0.f;
    for(int s=0;s<QCH;s++){
        float ws=w[s],wb0=ws*Bv[s*DSTATE+n0],wb1=ws*Bv[s*DSTATE+n0+1];
        #pragma unroll
        for(int q=0;q<5;q++){
            float xv=Xv[s*PDIM+p0+q];
            acc[0][q]+=wb0*xv; acc[1][q]+=wb1*xv;
        }
    }
    size_t base=(size_t)g*(DSTATE*PDIM);
    for(int a=0;a<2;a++)for(int q=0;q<5;q++)
        g_Sc[base+(size_t)(n0+a)*PDIM+p0+q]=acc[a][q];
}
#define CS_SMEM ((QCH+QCH*DSTATE+QCH*PDIM+QCH+QCH)*4)

__global__ void k_staterec(){
    int bh=blockIdx.x;
    __shared__ float etot[NCH];
    for(int i=threadIdx.x;i<NCH;i+=256)
        etot[i]=expf(g_cumL[(size_t)bh*NTOK+i*QCH+QCH-1]);
    __syncthreads();
    float S[10];
    for(int j=0;j<10;j++)S[j]=0.f;
    for(int c=0;c<NCH;c++){
        size_t base=((size_t)bh*NCH+c)*(DSTATE*PDIM);
        float e=etot[c];
        #pragma unroll
        for(int j=0;j<10;j++){
            int idx=threadIdx.x+j*256;
            g_Sin[base+idx]=S[j];
            S[j]=S[j]*e+g_Sc[base+idx];
        }
    }
}

// SSD output — round-9 proven version (BvT transposed+padded, linear e-indexing)
#define BVP 133
__global__ void k_ssd_out(const float* __restrict__ Dp){
    extern __shared__ float sm[];
    float* Lc=sm; float* dts=Lc+QCH; float* Cv=dts+QCH;
    float* BvT=Cv+QCH*DSTATE; float* Xv=BvT+DSTATE*BVP;
    float* Ss=Xv+QCH*PDIM; float* G=Ss+DSTATE*PDIM;
    int g=blockIdx.x,ch=g%NCH,h=(g/NCH)%NH,b=g/(NCH*NH);
    const float* cl=g_cumL+((size_t)(b*NH+h))*NTOK+ch*QCH;
    for(int i=threadIdx.x;i<QCH;i+=256){
        Lc[i]=cl[i];
        dts[i]=g_dt[((size_t)b*NTOK+ch*QCH+i)*NH+h];
    }
    for(int i=threadIdx.x;i<QCH*DSTATE;i+=256){
        int s=i>>5,nn=i&31;
        size_t rb=((size_t)b*NTOK+ch*QCH+s)*CONVD;
        Cv[i]=g_xbc[rb+DIN+DSTATE+nn];
        BvT[nn*BVP+s]=g_xbc[rb+DIN+nn];
    }
    for(int i=threadIdx.x;i<QCH*PDIM;i+=256){
        int s=i/PDIM,p=i-s*PDIM;
        Xv[i]=g_xbc[((size_t)b*NTOK+ch*QCH+s)*CONVD+h*PDIM+p];
    }
    for(int i=threadIdx.x;i<DSTATE*PDIM;i+=256)
        Ss[i]=g_Sin[(((size_t)(b*NH+h))*NCH+ch)*(DSTATE*PDIM)+i];
    __syncthreads();
    for(int e=threadIdx.x;e<QCH*QCH;e+=256){
        int t=e>>7,s=e&127;
        float val=0.f;
        if(s<=t){
            float d=0.f;
            #pragma unroll
            for(int nn=0;nn<DSTATE;nn++)d+=Cv[t*DSTATE+nn]*BvT[nn*BVP+s];
            val=d*expf(Lc[t]-Lc[s])*dts[s];
        }
        G[e]=val;
    }
    __syncthreads();
    float Dh=Dp[h];
    for(int o4=threadIdx.x;o4<QCH*PDIM/4;o4+=256){
        int idx=o4*4,t=idx/PDIM,p=idx-t*PDIM;
        float4 acc=make_float4(0.f,0.f,0.f,0.f);
        const float* Gt=G+t*QCH;
        for(int s=0;s<=t;s++){
            float gg=Gt[s];
            float4 xv=*(const float4*)(Xv+s*PDIM+p);
            acc.x+=gg*xv.x;acc.y+=gg*xv.y;acc.z+=gg*xv.z;acc.w+=gg*xv.w;
        }
        float4 inter=make_float4(0.f,0.f,0.f,0.f);
        #pragma unroll
        for(int nn=0;nn<DSTATE;nn++){
            float cc=Cv[t*DSTATE+nn];
            float4 sv=*(const float4*)(Ss+nn*PDIM+p);
            inter.x+=cc*sv.x;inter.y+=cc*sv.y;inter.z+=cc*sv.z;inter.w+=cc*sv.w;
        }
        float elt=expf(Lc[t]);
        float4 xt=*(const float4*)(Xv+t*PDIM+p);
        acc.x+=elt*inter.x+Dh*xt.x; acc.y+=elt*inter.y+Dh*xt.y;
        acc.z+=elt*inter.z+Dh*xt.z; acc.w+=elt*inter.w+Dh*xt.w;
        *(float4*)(g_y+((size_t)b*NTOK+ch*QCH+t)*DIN+h*PDIM+p)=acc;
    }
}
#define SSD_SMEM ((QCH+QCH+QCH*DSTATE+DSTATE*BVP+QCH*PDIM+DSTATE*PDIM+QCH*QCH)*4)

__global__ void k_gate_rms(const float* __restrict__ rms_w){
    __shared__ float sa[32],sb[32];
    int row=blockIdx.x;
    float* yr=g_y+(size_t)row*DIN;
    const float* zr=g_zx+(size_t)row*DPROJ;
    float vals[3],ss=0.f;
    #pragma unroll
    for(int i=0;i<3;i++){
        int c=threadIdx.x+i*256;
        float v=0.f;
        if(c<DIN)v=yr[c]*siluf(zr[c]);
        vals[i]=v; ss+=v*v;
    }
    float dummy=0.f;
    blockReduce2(ss,dummy,sa,sb);
    float scale=rsqrtf(ss*(1.f/DIN)+LN_EPS);
    #pragma unroll
    for(int i=0;i<3;i++){
        int c=threadIdx.x+i*256;
        if(c<DIN)yr[c]=vals[i]*scale*rms_w[c];
    }
}

__global__ void k_kpe(const float* __restrict__ gauss){
    int t=blockIdx.x,j=threadIdx.x;
    int d=t>>10,r=t&1023,hh=r>>5,ww=r&31;
    float g0=2.f*((d+0.5f)/16.f)-1.f,g1=2.f*((hh+0.5f)/32.f)-1.f,g2=2.f*((ww+0.5f)/32.f)-1.f;
    float c=TWOPI*(g0*gauss[j]+g1*gauss[160+j]+g2*gauss[320+j]);
    g_kpe[(size_t)t*CDIM+j]=sinf(c);
    g_kpe[(size_t)t*CDIM+160+j]=cosf(c);
}

__global__ void k_pemb(const float* __restrict__ coords,const int* __restrict__ labels,
                       const float* __restrict__ gauss,const float* __restrict__ tab){
    int bp=blockIdx.x,j=threadIdx.x;
    float g0=2.f*(coords[bp*3+0]*(1.f/128.f))-1.f;
    float g1=2.f*(coords[bp*3+1]*(1.f/256.f))-1.f;
    float g2=2.f*(coords[bp*3+2]*(1.f/256.f))-1.f;
    float c=TWOPI*(g0*gauss[j]+g1*gauss[160+j]+g2*gauss[320+j]);
    int lb=labels[bp];
    float s=sinf(c)+tab[lb*CDIM+j],co=cosf(c)+tab[lb*CDIM+160+j];
    g_pe[bp*CDIM+j]=s; g_pe[bp*CDIM+160+j]=co;
    g_qr[bp*CDIM+j]=s; g_qr[bp*CDIM+160+j]=co;
}

__global__ void k_tiny(const float* __restrict__ in,const float* __restrict__ pe,
                       const float* __restrict__ W,const float* __restrict__ bias,
                       const float* __restrict__ res,float* __restrict__ out,
                       int N,int K,int relu){
    extern __shared__ float srow[];
    int m=blockIdx.x;
    for(int i=threadIdx.x;i<K;i+=blockDim.x){
        float v=in[m*K+i];
        if(pe)v+=pe[m*K+i];
        srow[i]=v;
    }
    __syncthreads();
    int lane=threadIdx.x&31,warp=threadIdx.x>>5;
    int nq=N/gridDim.y;
    int nBeg=blockIdx.y*nq,nEnd=nBeg+nq;
    for(int n=nBeg+warp;n<nEnd;n+=8){
        const float* wr=W+(size_t)n*K;
        float acc=0.f;
        for(int kk=lane;kk<K;kk+=32)acc+=srow[kk]*wr[kk];
        #pragma unroll
        for(int o=16;o>0;o>>=1)acc+=__shfl_down_sync(0xffffffffu,acc,o);
        if(lane==0){
            if(bias)acc+=bias[n];
            if(relu)acc=fmaxf(acc,0.f);
            if(res)acc+=res[m*N+n];
            out[m*N+n]=acc;
        }
    }
}

__global__ void k_tiny3(const float* __restrict__ in,const float* __restrict__ pe,
                        const float* __restrict__ W0,const float* __restrict__ W1,const float* __restrict__ W2,
                        const float* __restrict__ b0,const float* __restrict__ b1,const float* __restrict__ b2,
                        float* __restrict__ o0,float* __restrict__ o1,float* __restrict__ o2,
                        int peMask,int N,int K){
    extern __shared__ float srow[];
    int m=blockIdx.x,z=blockIdx.z;
    const float* W=(z==0)?W0:((z==1)?W1:W2);
    const float* bi=(z==0)?b0:((z==1)?b1:b2);
    float* out=(z==0)?o0:((z==1)?o1:o2);
    int usePe=(peMask>>z)&1;
    for(int i=threadIdx.x;i<K;i+=blockDim.x){
        float v=in[m*K+i];
        if(pe&&usePe)v+=pe[m*K+i];
        srow[i]=v;
    }
    __syncthreads();
    int lane=threadIdx.x&31,warp=threadIdx.x>>5;
    int nq=N/gridDim.y;
    int nBeg=blockIdx.y*nq,nEnd=nBeg+nq;
    for(int n=nBeg+warp;n<nEnd;n+=8){
        const float* wr=W+(size_t)n*K;
        float acc=0.f;
        for(int kk=lane;kk<K;kk+=32)acc+=srow[kk]*wr[kk];
        #pragma unroll
        for(int o=16;o>0;o>>=1)acc+=__shfl_down_sync(0xffffffffu,acc,o);
        if(lane==0)out[m*N+n]=acc+(bi?bi[n]:0.f);
    }
}

__global__ void k_tiny_ln(const float* __restrict__ in,const float* __restrict__ W,
                          const float* __restrict__ bias,const float* __restrict__ res,
                          float* __restrict__ out,const float* __restrict__ lnw,
                          const float* __restrict__ lnb,int K){
    extern __shared__ float smem[];
    float* srow=smem;
    float* sout=smem+K;
    __shared__ float sa[32],sb[32];
    int m=blockIdx.x;
    for(int i=threadIdx.x;i<K;i+=256)srow[i]=in[m*K+i];
    __syncthreads();
    int lane=threadIdx.x&31,warp=threadIdx.x>>5;
    for(int n=warp;n<CDIM;n+=8){
        const float* wr=W+(size_t)n*K;
        float acc=0.f;
        for(int kk=lane;kk<K;kk+=32)acc+=srow[kk]*wr[kk];
        #pragma unroll
        for(int o=16;o>0;o>>=1)acc+=__shfl_down_sync(0xffffffffu,acc,o);
        if(lane==0){
            acc+=bias[n];
            if(res)acc+=res[m*CDIM+n];
            sout[n]=acc;
        }
    }
    __syncthreads();
    float v0=(threadIdx.x<CDIM)?sout[threadIdx.x]:0.f;
    int e1=threadIdx.x+256;
    float v1=(e1<CDIM)?sout[e1]:0.f;
    float s1=v0+v1,s2=v0*v0+v1*v1;
    blockReduce2(s1,s2,sa,sb);
    float mean=s1*(1.f/CDIM),var=s2*(1.f/CDIM)-mean*mean;
    float r=rsqrtf(var+LN_EPS);
    if(threadIdx.x<CDIM)out[m*CDIM+threadIdx.x]=(v0-mean)*r*lnw[threadIdx.x]+lnb[threadIdx.x];
    if(e1<CDIM)out[m*CDIM+e1]=(v1-mean)*r*lnw[e1]+lnb[e1];
}

__global__ void k_selfattn(const float* __restrict__ q,const float* __restrict__ k,
                           const float* __restrict__ v,float* __restrict__ out){
    int bh=blockIdx.x,b=bh>>2,h=bh&3;
    __shared__ float qs[NQ][80],ks[NQ][80],vs[NQ][80],p[NQ][NQ];
    for(int i=threadIdx.x;i<NQ*80;i+=blockDim.x){
        int r=i/80,d=i-r*80;
        size_t off=(size_t)(b*NQ+r)*CDIM+h*80+d;
        qs[r][d]=q[off];ks[r][d]=k[off];vs[r][d]=v[off];
    }
    __syncthreads();
    if(threadIdx.x<36){
        int i=threadIdx.x/6,j=threadIdx.x%6;
        float s=0.f;
        #pragma unroll
        for(int d=0;d<80;d++)s+=qs[i][d]*ks[j][d];
        p[i][j]=s*0.11180339887498949f;
    }
    __syncthreads();
    if(threadIdx.x<NQ){
        int i=threadIdx.x;
        float m=-1e30f;
        for(int j=0;j<NQ;j++)m=fmaxf(m,p[i][j]);
        float ssum=0.f;
        for(int j=0;j<NQ;j++){float e=expf(p[i][j]-m);p[i][j]=e;ssum+=e;}
        float inv=1.f/ssum;
        for(int j=0;j<NQ;j++)p[i][j]*=inv;
    }
    __syncthreads();
    if(threadIdx.x<80){
        int d=threadIdx.x;
        for(int i=0;i<NQ;i++){
            float o=0.f;
            #pragma unroll
            for(int j=0;j<NQ;j++)o+=p[i][j]*vs[j][d];
            out[(size_t)(b*NQ+i)*CDIM+h*80+d]=o;
        }
    }
}

#define T2I_TP 41
#define T2I_SMEM ((NTOK + 256*T2I_TP + 256)*4)
__global__ void k_t2i_attn(const float* __restrict__ q6,const float* __restrict__ kbig,
                           const float* __restrict__ vbig,float* __restrict__ out){
    extern __shared__ float sm[];
    float* scr=sm;
    float* tile=sm+NTOK;
    float* red=tile+256*T2I_TP;
    __shared__ float wred[8][40];
    int g=blockIdx.x,qi=g%6,h=(g/6)%4,b=g/24;
    int tid=threadIdx.x;
    float qv[40];
    const float* qp=q6+(size_t)(b*NQ+qi)*INNERC+h*40;
    #pragma unroll
    for(int d=0;d<40;d++)qv[d]=qp[d]*0.15811388300841897f;
    const float* kb=kbig+(size_t)b*NTOK*INNERC+h*40;
    float lmax=-1e30f;
    for(int t0=0;t0<NTOK;t0+=256){
        for(int i=tid;i<256*40;i+=256){
            int r=i/40,c=i-r*40;
            tile[r*T2I_TP+c]=kb[(size_t)(t0+r)*INNERC+c];
        }
        __syncthreads();
        const float* tr=tile+tid*T2I_TP;
        float s=0.f;
        #pragma unroll
        for(int d=0;d<40;d++)s+=qv[d]*tr[d];
        scr[t0+tid]=s; lmax=fmaxf(lmax,s);
        __syncthreads();
    }
    red[tid]=lmax;__syncthreads();
    for(int o=128;o>0;o>>=1){if(tid<o)red[tid]=fmaxf(red[tid],red[tid+o]);__syncthreads();}
    float gmax=red[0];__syncthreads();
    float lsum=0.f;
    for(int kk=tid;kk<NTOK;kk+=256){float e=expf(scr[kk]-gmax);scr[kk]=e;lsum+=e;}
    red[tid]=lsum;__syncthreads();
    for(int o=128;o>0;o>>=1){if(tid<o)red[tid]+=red[tid+o];__syncthreads();}
    float gsum=red[0];__syncthreads();
    float acc[40];
    #pragma unroll
    for(int d=0;d<40;d++)acc[d]=0.f;
    const float* vb=vbig+(size_t)b*NTOK*INNERC+h*40;
    for(int t0=0;t0<NTOK;t0+=256){
        for(int i=tid;i<256*40;i+=256){
            int r=i/40,c=i-r*40;
            tile[r*T2I_TP+c]=vb[(size_t)(t0+r)*INNERC+c];
        }
        __syncthreads();
        float e=scr[t0+tid];
        const float* tr=tile+tid*T2I_TP;
        #pragma unroll
        for(int d=0;d<40;d++)acc[d]+=e*tr[d];
        __syncthreads();
    }
    int lane=tid&31,w=tid>>5;
    #pragma unroll
    for(int d=0;d<40;d++){
        float a=acc[d];
        for(int o=16;o>0;o>>=1)a+=__shfl_down_sync(0xffffffffu,a,o);
        if(lane==0)wred[w][d]=a;
    }
    __syncthreads();
    if(tid<40){
        float o=0.f;
        #pragma unroll
        for(int ww=0;ww<8;ww++)o+=wred[ww][tid];
        out[(size_t)(b*NQ+qi)*INNERC+h*40+tid]=o/gsum;
    }
}

__global__ void k_i2t_attn(const float* __restrict__ qbig,const float* __restrict__ k6,
                           const float* __restrict__ v6,float* __restrict__ out){
    __shared__ __align__(16) float ks[NQ*INNERC];
    __shared__ __align__(16) float vs[NQ*INNERC];
    int b=blockIdx.x>>8;
    for(int i=threadIdx.x;i<NQ*INNERC;i+=256){
        ks[i]=k6[b*NQ*INNERC+i]; vs[i]=v6[b*NQ*INNERC+i];
    }
    __syncthreads();
    int rem=(blockIdx.x&255)*256+threadIdx.x;
    int t=rem>>2,h=rem&3;
    const float* qp=qbig+((size_t)b*NTOK+t)*INNERC+h*40;
    float qv[40];
    #pragma unroll
    for(int d4=0;d4<10;d4++)((float4*)qv)[d4]=((const float4*)qp)[d4];
    float s[NQ];
    #pragma unroll
    for(int j=0;j<NQ;j++){
        float d=0.f;
        #pragma unroll
        for(int dd=0;dd<40;dd++)d+=qv[dd]*ks[j*INNERC+h*40+dd];
        s[j]=d*0.15811388300841897f;
    }
    float m=-1e30f;
    #pragma unroll
    for(int j=0;j<NQ;j++)m=fmaxf(m,s[j]);
    float ssum=0.f;
    #pragma unroll
    for(int j=0;j<NQ;j++){s[j]=expf(s[j]-m);ssum+=s[j];}
    float inv=1.f/ssum;
    float* op=out+((size_t)b*NTOK+t)*INNERC+h*40;
    #pragma unroll
    for(int d4=0;d4<10;d4++){
        float4 o=make_float4(0.f,0.f,0.f,0.f);
        #pragma unroll
        for(int j=0;j<NQ;j++){
            float e=s[j];
            float4 v=((const float4*)(vs+j*INNERC+h*40))[d4];
            o.x+=e*v.x;o.y+=e*v.y;o.z+=e*v.z;o.w+=e*v.w;
        }
        o.x*=inv;o.y*=inv;o.z*=inv;o.w*=inv;
        ((float4*)op)[d4]=o;
    }
}

extern "C" void kernel_launch(void* const* d_in,const int* in_sizes,int n_in,
                              void* d_out,int out_size){
    const float* x=(const float*)d_in[0];
    const float* coords=(const float*)d_in[1];
    const int* labels=(const int*)d_in[2];
    const float* ln_w=(const float*)d_in[3];
    const float* ln_b=(const float*)d_in[4];
    const float* in_w=(const float*)d_in[5];
    const float* conv_w=(const float*)d_in[6];
    const float* conv_b=(const float*)d_in[7];
    const float* dt_bias=(const float*)d_in[8];
    const float* A_log=(const float*)d_in[9];
    const float* Dp=(const float*)d_in[10];
    const float* rms_w=(const float*)d_in[11];
    const float* out_w=(const float*)d_in[12];
    const float* gauss=(const float*)d_in[13];
    const float* ptab=(const float*)d_in[14];
    const float* sa_w=(const float*)d_in[15];
    const float* sa_b=(const float*)d_in[16];
    const float* t2i_w=(const float*)d_in[17];
    const float* t2i_b=(const float*)d_in[18];
    const float* t2i_ow=(const float*)d_in[19];
    const float* t2i_ob=(const float*)d_in[20];
    const float* i2t_w=(const float*)d_in[21];
    const float* i2t_b=(const float*)d_in[22];
    const float* i2t_ow=(const float*)d_in[23];
    const float* i2t_ob=(const float*)d_in[24];
    const float* norms_w=(const float*)d_in[25];
    const float* norms_b=(const float*)d_in[26];
    const float* mlp_w1=(const float*)d_in[27];
    const float* mlp_b1=(const float*)d_in[28];
    const float* mlp_w2=(const float*)d_in[29];
    const float* mlp_b2=(const float*)d_in[30];
    float* outp=(float*)d_out;

    float *p_xn,*p_zx,*p_y,*p_keys,*p_kpe,*p_pe,*p_qr,*p_q6,*p_k6,*p_v6,*p_a6,*p_mlp,*p_kb,*p_vb,*p_qb,*p_ab;
    cudaGetSymbolAddress((void**)&p_xn,g_xn);
    cudaGetSymbolAddress((void**)&p_zx,g_zx);
    cudaGetSymbolAddress((void**)&p_y,g_y);
    cudaGetSymbolAddress((void**)&p_keys,g_keys);
    cudaGetSymbolAddress((void**)&p_kpe,g_kpe);
    cudaGetSymbolAddress((void**)&p_pe,g_pe);
    cudaGetSymbolAddress((void**)&p_qr,g_qr);
    cudaGetSymbolAddress((void**)&p_q6,g_q6);
    cudaGetSymbolAddress((void**)&p_k6,g_k6);
    cudaGetSymbolAddress((void**)&p_v6,g_v6);
    cudaGetSymbolAddress((void**)&p_a6,g_a6);
    cudaGetSymbolAddress((void**)&p_mlp,g_mlpb);
    cudaGetSymbolAddress((void**)&p_kb,g_kb);
    cudaGetSymbolAddress((void**)&p_vb,g_vb);
    cudaGetSymbolAddress((void**)&p_qb,g_qb);
    cudaGetSymbolAddress((void**)&p_ab,g_ab);

    cudaFuncSetAttribute(k_chunkstate,cudaFuncAttributeMaxDynamicSharedMemorySize,CS_SMEM);
    cudaFuncSetAttribute(k_ssd_out,cudaFuncAttributeMaxDynamicSharedMemorySize,SSD_SMEM);
    cudaFuncSetAttribute(k_t2i_attn,cudaFuncAttributeMaxDynamicSharedMemorySize,T2I_SMEM);

    dim3 tg(BB*NQ,4);
    dim3 tg3(BB*NQ,4,3);
    dim3 tg2(BB*NQ,4,2);
    k_kpe<<<NTOK,160>>>(gauss);
    k_transln<<<BB*(NTOK/32),256>>>(x,p_xn,ln_w,ln_b);
    k_pemb<<<BB*NQ,160>>>(coords,labels,gauss,ptab);
    k_gemm_tc<<<dim3(11,256),256>>>(p_xn,nullptr,1,in_w,nullptr,nullptr,p_zx,BB*NTOK,DPROJ,CDIM);
    k_conv2<<<BB*(NTOK/8),256>>>(conv_w,conv_b,dt_bias);
    k_chunkstate<<<BB*NH*NCH,256,CS_SMEM>>>(A_log);
    k_staterec<<<BB*NH,256>>>();
    k_ssd_out<<<BB*NH*NCH,256,SSD_SMEM>>>(Dp);
    k_gate_rms<<<BB*NTOK,256>>>(rms_w);
    k_gemm_tc<<<dim3(3,256),256>>>(p_y,nullptr,1,out_w,nullptr,nullptr,p_keys,BB*NTOK,CDIM,DIN);

    for(int i=0;i<2;i++){
        const float* saw=sa_w+(size_t)i*4*CDIM*CDIM;
        const float* sab=sa_b+(size_t)i*4*CDIM;
        const float* pe0=i?p_pe:nullptr;
        k_tiny3<<<tg3,256,CDIM*4>>>(p_qr,pe0,saw,saw+CDIM*CDIM,saw+2*CDIM*CDIM,
                                    sab,sab+CDIM,sab+2*CDIM,p_q6,p_k6,p_v6,3,CDIM,CDIM);
        k_selfattn<<<BB*4,128>>>(p_q6,p_k6,p_v6,p_a6);
        k_tiny_ln<<<BB*NQ,256,(CDIM+CDIM)*4>>>(p_a6,saw+3*CDIM*CDIM,sab+3*CDIM,
                                               i?p_qr:nullptr,p_qr,
                                               norms_w+(i*4+0)*CDIM,norms_b+(i*4+0)*CDIM,CDIM);
        const float* tw=t2i_w+(size_t)i*3*INNERC*CDIM;
        const float* tb2=t2i_b+(size_t)i*3*INNERC;
        k_tiny<<<tg,256,CDIM*4>>>(p_qr,p_pe,tw,tb2,nullptr,p_q6,INNERC,CDIM,0);
        k_gemm_tc<<<dim3(2,256),256>>>(p_keys,p_kpe,NTOK,tw+1*INNERC*CDIM,tb2+INNERC,nullptr,p_kb,BB*NTOK,INNERC,CDIM);
        k_gemm_tc<<<dim3(2,256),256>>>(p_keys,nullptr,1,tw+2*INNERC*CDIM,tb2+2*INNERC,nullptr,p_vb,BB*NTOK,INNERC,CDIM);
        k_t2i_attn<<<BB*4*NQ,256,T2I_SMEM>>>(p_q6,p_kb,p_vb,p_a6);
        k_tiny_ln<<<BB*NQ,256,(INNERC+CDIM)*4>>>(p_a6,t2i_ow+(size_t)i*CDIM*INNERC,t2i_ob+i*CDIM,
                                                 p_qr,p_qr,
                                                 norms_w+(i*4+1)*CDIM,norms_b+(i*4+1)*CDIM,INNERC);
        k_tiny<<<tg,256,CDIM*4>>>(p_qr,nullptr,mlp_w1+(size_t)i*MLPD*CDIM,mlp_b1+i*MLPD,nullptr,p_mlp,MLPD,CDIM,1);
        k_tiny_ln<<<BB*NQ,256,(MLPD+CDIM)*4>>>(p_mlp,mlp_w2+(size_t)i*CDIM*MLPD,mlp_b2+i*CDIM,
                                               p_qr,p_qr,
                                               norms_w+(i*4+2)*CDIM,norms_b+(i*4+2)*CDIM,MLPD);
        const float* iw=i2t_w+(size_t)i*3*INNERC*CDIM;
        const float* ib=i2t_b+(size_t)i*3*INNERC;
        k_gemm_tc<<<dim3(2,256),256>>>(p_keys,p_kpe,NTOK,iw,ib,nullptr,p_qb,BB*NTOK,INNERC,CDIM);
        k_tiny3<<<tg2,256,CDIM*4>>>(p_qr,p_pe,iw+1*INNERC*CDIM,iw+2*INNERC*CDIM,nullptr,
                                    ib+INNERC,ib+2*INNERC,nullptr,p_k6,p_v6,nullptr,1,INNERC,CDIM);
        k_i2t_attn<<<BB*256,256>>>(p_qb,p_k6,p_v6,p_ab);
        k_gemm_tc<<<dim3(3,256),256>>>(p_ab,nullptr,1,i2t_ow+(size_t)i*CDIM*INNERC,i2t_ob+i*CDIM,p_keys,p_keys,BB*NTOK,CDIM,INNERC);
        if(i==0)
            k_ln<<<BB*NTOK,CDIM>>>(p_keys,p_keys,norms_w+3*CDIM,norms_b+3*CDIM);
    }
    k_lntrans<<<BB*(NTOK/32),256>>>(p_keys,outp,norms_w+7*CDIM,norms_b+7*CDIM);
}

// round 14
// speedup vs baseline: 1.0436x; 1.0103x over previous
#include <cuda_runtime.h>
#include <math.h>
#include <stdint.h>

#define BB 2
#define CDIM 320
#define NTOK 16384
#define DIN 640
#define DSTATE 32
#define NH 8
#define PDIM 80
#define CONVD 704
#define DPROJ 1352
#define INNERC 160
#define NQ 6
#define QCH 128
#define NCH (NTOK/QCH)
#define MLPD 1024
#define LN_EPS 1e-5f
#define TWOPI 6.28318530717958647692f

__device__ float g_xn[BB*NTOK*CDIM];
__device__ float g_zx[BB*NTOK*DPROJ];
__device__ float g_xbc[BB*NTOK*CONVD];
__device__ float g_dt[BB*NTOK*NH];
__device__ float g_cumL[BB*NH*NTOK];
__device__ float g_Sc[BB*NH*NCH*DSTATE*PDIM];
__device__ float g_Sin[BB*NH*NCH*DSTATE*PDIM];
__device__ float g_y[BB*NTOK*DIN];
__device__ float g_keys[BB*NTOK*CDIM];
__device__ float g_kpe[NTOK*CDIM];
__device__ float g_pe[BB*NQ*CDIM];
__device__ float g_qr[BB*NQ*CDIM];
__device__ float g_q6[BB*NQ*CDIM];
__device__ float g_k6[BB*NQ*CDIM];
__device__ float g_v6[BB*NQ*CDIM];
__device__ float g_a6[BB*NQ*CDIM];
__device__ float g_mlpb[BB*NQ*MLPD];
__device__ float g_kb[BB*NTOK*INNERC];
__device__ float g_vb[BB*NTOK*INNERC];
__device__ float g_qb[BB*NTOK*INNERC];
__device__ float g_ab[BB*NTOK*INNERC];

__device__ __forceinline__ float siluf(float x){ return x/(1.f+expf(-x)); }

__device__ __forceinline__ void blockReduce2(float& a,float& b,float* sa,float* sb){
    const unsigned m=0xffffffffu;
    for(int o=16;o>0;o>>=1){a+=__shfl_down_sync(m,a,o);b+=__shfl_down_sync(m,b,o);}
    int lane=threadIdx.x&31,w=threadIdx.x>>5;
    if(lane==0){sa[w]=a;sb[w]=b;}
    __syncthreads();
    int nw=(blockDim.x+31)>>5;
    if(w==0){
        a=(lane<nw)?sa[lane]:0.f; b=(lane<nw)?sb[lane]:0.f;
        for(int o=16;o>0;o>>=1){a+=__shfl_down_sync(m,a,o);b+=__shfl_down_sync(m,b,o);}
        if(lane==0){sa[0]=a;sb[0]=b;}
    }
    __syncthreads();
    a=sa[0];b=sb[0];
}

__global__ void k_transpose(const float* __restrict__ in,float* __restrict__ out,int R,int C){
    __shared__ float s[32][33];
    int b=blockIdx.z,r0=blockIdx.y*32,c0=blockIdx.x*32;
    const float* ip=in+(size_t)b*R*C; float* op=out+(size_t)b*R*C;
    #pragma unroll
    for(int j=0;j<32;j+=8){int r=r0+threadIdx.y+j,c=c0+threadIdx.x;
        if(r<R&&c<C)s[threadIdx.y+j][threadIdx.x]=ip[(size_t)r*C+c];}
    __syncthreads();
    #pragma unroll
    for(int j=0;j<32;j+=8){int r=c0+threadIdx.y+j,c=r0+threadIdx.x;
        if(r<C&&c<R)op[(size_t)r*R+c]=s[threadIdx.x][threadIdx.y+j];}
}

__global__ void k_ln(const float* __restrict__ in,float* __restrict__ out,
                     const float* __restrict__ w,const float* __restrict__ b){
    __shared__ float sa[32],sb[32];
    int row=blockIdx.x;
    float v=in[(size_t)row*CDIM+threadIdx.x];
    float s1=v,s2=v*v;
    blockReduce2(s1,s2,sa,sb);
    float mean=s1*(1.f/CDIM),var=s2*(1.f/CDIM)-mean*mean;
    float r=rsqrtf(var+LN_EPS);
    out[(size_t)row*CDIM+threadIdx.x]=(v-mean)*r*w[threadIdx.x]+b[threadIdx.x];
}

#define UPAD 20
__device__ __forceinline__ uint32_t pk2(float a,float b){
    uint32_t r; asm("cvt.rn.bf16x2.f32 %0, %1, %2;":"=r"(r):"f"(b),"f"(a)); return r;
}
__device__ __forceinline__ void mma_bf(float* d,uint32_t a0,uint32_t a1,uint32_t a2,uint32_t a3,
                                       uint32_t b0,uint32_t b1){
    asm volatile("mma.sync.aligned.m16n8k16.row.col.f32.bf16.bf16.f32 "
        "{%0,%1,%2,%3}, {%4,%5,%6,%7}, {%8,%9}, {%0,%1,%2,%3};"
        : "+f"(d[0]),"+f"(d[1]),"+f"(d[2]),"+f"(d[3])
        : "r"(a0),"r"(a1),"r"(a2),"r"(a3),"r"(b0),"r"(b1));
}

// C[M,N]=bias+res+(A(+Aadd))@W^T ; blockIdx.z==1 selects the B-set (W2/bias2/C2, Aadd2)
__global__ __launch_bounds__(256) void k_gemm_tc(
        const float* __restrict__ A,const float* __restrict__ Aadd,int addMod,
        const float* __restrict__ W,const float* __restrict__ bias,
        const float* __restrict__ res,float* __restrict__ C,int M,int N,int K,
        const float* __restrict__ Aadd2,const float* __restrict__ W2,
        const float* __restrict__ bias2,float* __restrict__ C2){
    if(blockIdx.z==1){ Aadd=Aadd2; W=W2; bias=bias2; C=C2; }
    __shared__ uint32_t Ah[128*UPAD],Al[128*UPAD],Wh[128*UPAD],Wl[128*UPAD];
    int m0=blockIdx.y*128,n0=blockIdx.x*128;
    int tid=threadIdx.x,lane=tid&31,warp=tid>>5;
    int wm=warp&3,wn=warp>>2,lg=lane>>2,lk=lane&3;
    int bnEnd=(N-n0-wn*64+7)>>3;
    if(bnEnd<0)bnEnd=0; if(bnEnd>8)bnEnd=8;
    float acc[2][8][4];
    #pragma unroll
    for(int am=0;am<2;am++)
        #pragma unroll
        for(int bn=0;bn<8;bn++)
            #pragma unroll
            for(int j=0;j<4;j++)acc[am][bn][j]=0.f;

    for(int kt=0;kt<K;kt+=32){
        #pragma unroll
        for(int i=0;i<4;i++){
            int f=tid+i*256,r=f>>3,kq=(f&7)<<2;
            int gm=m0+r;
            float4 v=*(const float4*)(A+(size_t)gm*K+kt+kq);
            if(Aadd){
                float4 u=*(const float4*)(Aadd+(size_t)(gm%addMod)*K+kt+kq);
                v.x+=u.x;v.y+=u.y;v.z+=u.z;v.w+=u.w;
            }
            uint32_t h0=pk2(v.x,v.y),h1=pk2(v.z,v.w);
            float l0=v.x-__uint_as_float(h0<<16),l1=v.y-__uint_as_float(h0&0xffff0000u);
            float l2=v.z-__uint_as_float(h1<<16),l3=v.w-__uint_as_float(h1&0xffff0000u);
            int si=r*UPAD+(kq>>1);
            *(uint2*)(Ah+si)=make_uint2(h0,h1);
            *(uint2*)(Al+si)=make_uint2(pk2(l0,l1),pk2(l2,l3));
            int gn=n0+r;
            float4 wv=make_float4(0.f,0.f,0.f,0.f);
            if(gn<N)wv=*(const float4*)(W+(size_t)gn*K+kt+kq);
            uint32_t g0=pk2(wv.x,wv.y),g1=pk2(wv.z,wv.w);
            float m0f=wv.x-__uint_as_float(g0<<16),m1f=wv.y-__uint_as_float(g0&0xffff0000u);
            float m2f=wv.z-__uint_as_float(g1<<16),m3f=wv.w-__uint_as_float(g1&0xffff0000u);
            *(uint2*)(Wh+si)=make_uint2(g0,g1);
            *(uint2*)(Wl+si)=make_uint2(pk2(m0f,m1f),pk2(m2f,m3f));
        }
        __syncthreads();
        if(bnEnd>0){
            #pragma unroll
            for(int ks=0;ks<2;ks++){
                uint32_t a0[2],a1[2],a2[2],a3[2],e0[2],e1[2],e2[2],e3[2];
                #pragma unroll
                for(int am=0;am<2;am++){
                    int r=wm*32+am*16+lg,c=ks*8+lk;
                    a0[am]=Ah[r*UPAD+c];     a1[am]=Ah[(r+8)*UPAD+c];
                    a2[am]=Ah[r*UPAD+c+4];   a3[am]=Ah[(r+8)*UPAD+c+4];
                    e0[am]=Al[r*UPAD+c];     e1[am]=Al[(r+8)*UPAD+c];
                    e2[am]=Al[r*UPAD+c+4];   e3[am]=Al[(r+8)*UPAD+c+4];
                }
                for(int bn=0;bn<bnEnd;bn++){
                    int col=wn*64+bn*8+lg,c=ks*8+lk;
                    uint32_t b0=Wh[col*UPAD+c],b1=Wh[col*UPAD+c+4];
                    uint32_t f0=Wl[col*UPAD+c],f1=Wl[col*UPAD+c+4];
                    #pragma unroll
                    for(int am=0;am<2;am++){
                        mma_bf(acc[am][bn],a0[am],a1[am],a2[am],a3[am],b0,b1);
                        mma_bf(acc[am][bn],a0[am],a1[am],a2[am],a3[am],f0,f1);
                        mma_bf(acc[am][bn],e0[am],e1[am],e2[am],e3[am],b0,b1);
                    }
                }
            }
        }
        __syncthreads();
    }
    #pragma unroll
    for(int am=0;am<2;am++){
        int r0=m0+wm*32+am*16+lg;
        for(int bn=0;bn<bnEnd;bn++){
            int c0=n0+wn*64+bn*8+2*lk;
            #pragma unroll
            for(int half=0;half<2;half++){
                int gm=r0+half*8;
                float d0=acc[am][bn][half*2+0],d1=acc[am][bn][half*2+1];
                if(c0<N){
                    float v=d0;
                    if(bias)v+=bias[c0];
                    if(res)v+=res[(size_t)gm*N+c0];
                    C[(size_t)gm*N+c0]=v;
                }
                if(c0+1<N){
                    float v=d1;
                    if(bias)v+=bias[c0+1];
                    if(res)v+=res[(size_t)gm*N+c0+1];
                    C[(size_t)gm*N+c0+1]=v;
                }
            }
        }
    }
}

__global__ void k_conv(const float* __restrict__ cw,const float* __restrict__ cb,
                       const float* __restrict__ dt_bias){
    int bt=blockIdx.x,t=bt&(NTOK-1);
    for(int c=threadIdx.x;c<CONVD;c+=blockDim.x){
        float acc=cb[c];
        #pragma unroll
        for(int k=0;k<4;k++){int ts=t+k-3;
            if(ts>=0)acc+=cw[c*4+k]*g_zx[(size_t)(bt+k-3)*DPROJ+DIN+c];}
        g_xbc[(size_t)bt*CONVD+c]=siluf(acc);
    }
    if(threadIdx.x<NH){
        float v=g_zx[(size_t)bt*DPROJ+DIN+CONVD+threadIdx.x]+dt_bias[threadIdx.x];
        v=(v>20.f)?v:log1pf(expf(v));
        g_dt[bt*NH+threadIdx.x]=v;
    }
}

__global__ void k_cumsum(const float* __restrict__ A_log){
    int g=blockIdx.x,ch=g%NCH,h=(g/NCH)%NH,b=g/(NCH*NH);
    int s=threadIdx.x,t=ch*QCH+s;
    float A=-expf(A_log[h]);
    __shared__ float sc[QCH];
    sc[s]=g_dt[((size_t)b*NTOK+t)*NH+h]*A;
    __syncthreads();
    for(int off=1;off<QCH;off<<=1){
        float add=(s>=off)?sc[s-off]:0.f;
        __syncthreads(); sc[s]+=add; __syncthreads();
    }
    g_cumL[((size_t)(b*NH+h))*NTOK+t]=sc[s];
}

__global__ void k_chunkstate(){
    extern __shared__ float sm[];
    float* w=sm; float* Bv=sm+QCH; float* Xv=Bv+QCH*DSTATE;
    int g=blockIdx.x,ch=g%NCH,h=(g/NCH)%NH,b=g/(NCH*NH);
    const float* cl=g_cumL+((size_t)(b*NH+h))*NTOK+ch*QCH;
    float total=cl[QCH-1];
    for(int i=threadIdx.x;i<QCH;i+=256){
        int t=ch*QCH+i;
        w[i]=expf(total-cl[i])*g_dt[((size_t)b*NTOK+t)*NH+h];
    }
    for(int i=threadIdx.x;i<QCH*DSTATE;i+=256){
        int s=i>>5,nn=i&31;
        Bv[i]=g_xbc[((size_t)b*NTOK+ch*QCH+s)*CONVD+DIN+nn];
    }
    for(int i=threadIdx.x;i<QCH*PDIM;i+=256){
        int s=i/PDIM,p=i-s*PDIM;
        Xv[i]=g_xbc[((size_t)b*NTOK+ch*QCH+s)*CONVD+h*PDIM+p];
    }
    __syncthreads();
    int n0=(threadIdx.x>>4)*2,p0=(threadIdx.x&15)*5;
    float acc[2][5];
    for(int a=0;a<2;a++)for(int q=0;q<5;q++)acc[a][q]=0.f;
    for(int s=0;s<QCH;s++){
        float ws=w[s],wb0=ws*Bv[s*DSTATE+n0],wb1=ws*Bv[s*DSTATE+n0+1];
        #pragma unroll
        for(int q=0;q<5;q++){
            float xv=Xv[s*PDIM+p0+q];
            acc[0][q]+=wb0*xv; acc[1][q]+=wb1*xv;
        }
    }
    size_t base=(size_t)g*(DSTATE*PDIM);
    for(int a=0;a<2;a++)for(int q=0;q<5;q++)
        g_Sc[base+(size_t)(n0+a)*PDIM+p0+q]=acc[a][q];
}

__global__ void k_staterec(){
    int bh=blockIdx.x;
    __shared__ float etot[NCH];
    for(int i=threadIdx.x;i<NCH;i+=256)
        etot[i]=expf(g_cumL[(size_t)bh*NTOK+i*QCH+QCH-1]);
    __syncthreads();
    float S[10];
    for(int j=0;j<10;j++)S[j]=0.f;
    for(int c=0;c<NCH;c++){
        size_t base=((size_t)bh*NCH+c)*(DSTATE*PDIM);
        float e=etot[c];
        #pragma unroll
        for(int j=0;j<10;j++){
            int idx=threadIdx.x+j*256;
            g_Sin[base+idx]=S[j];
            S[j]=S[j]*e+g_Sc[base+idx];
        }
    }
}

#define BVP 133
__global__ void k_ssd_out(const float* __restrict__ Dp){
    extern __shared__ float sm[];
    float* Lc=sm; float* dts=Lc+QCH; float* Cv=dts+QCH;
    float* BvT=Cv+QCH*DSTATE; float* Xv=BvT+DSTATE*BVP;
    float* Ss=Xv+QCH*PDIM; float* G=Ss+DSTATE*PDIM;
    int g=blockIdx.x,ch=g%NCH,h=(g/NCH)%NH,b=g/(NCH*NH);
    const float* cl=g_cumL+((size_t)(b*NH+h))*NTOK+ch*QCH;
    for(int i=threadIdx.x;i<QCH;i+=256){
        Lc[i]=cl[i];
        dts[i]=g_dt[((size_t)b*NTOK+ch*QCH+i)*NH+h];
    }
    for(int i=threadIdx.x;i<QCH*DSTATE;i+=256){
        int s=i>>5,nn=i&31;
        size_t rb=((size_t)b*NTOK+ch*QCH+s)*CONVD;
        Cv[i]=g_xbc[rb+DIN+DSTATE+nn];
        BvT[nn*BVP+s]=g_xbc[rb+DIN+nn];
    }
    for(int i=threadIdx.x;i<QCH*PDIM;i+=256){
        int s=i/PDIM,p=i-s*PDIM;
        Xv[i]=g_xbc[((size_t)b*NTOK+ch*QCH+s)*CONVD+h*PDIM+p];
    }
    for(int i=threadIdx.x;i<DSTATE*PDIM;i+=256)
        Ss[i]=g_Sin[(((size_t)(b*NH+h))*NCH+ch)*(DSTATE*PDIM)+i];
    __syncthreads();
    for(int e=threadIdx.x;e<QCH*QCH;e+=256){
        int t=e>>7,s=e&127;
        float val=0.f;
        if(s<=t){
            float d=0.f;
            #pragma unroll
            for(int nn=0;nn<DSTATE;nn++)d+=Cv[t*DSTATE+nn]*BvT[nn*BVP+s];
            val=d*expf(Lc[t]-Lc[s])*dts[s];
        }
        G[e]=val;
    }
    __syncthreads();
    float Dh=Dp[h];
    for(int o4=threadIdx.x;o4<QCH*PDIM/4;o4+=256){
        int idx=o4*4,t=idx/PDIM,p=idx-t*PDIM;
        float4 acc=make_float4(0.f,0.f,0.f,0.f);
        const float* Gt=G+t*QCH;
        for(int s4=0;s4<=t;s4+=4){
            float4 gq=*(const float4*)(Gt+s4);
            float4 x0=*(const float4*)(Xv+s4*PDIM+p);
            acc.x+=gq.x*x0.x;acc.y+=gq.x*x0.y;acc.z+=gq.x*x0.z;acc.w+=gq.x*x0.w;
            float4 x1=*(const float4*)(Xv+(s4+1)*PDIM+p);
            acc.x+=gq.y*x1.x;acc.y+=gq.y*x1.y;acc.z+=gq.y*x1.z;acc.w+=gq.y*x1.w;
            float4 x2=*(const float4*)(Xv+(s4+2)*PDIM+p);
            acc.x+=gq.z*x2.x;acc.y+=gq.z*x2.y;acc.z+=gq.z*x2.z;acc.w+=gq.z*x2.w;
            float4 x3=*(const float4*)(Xv+(s4+3)*PDIM+p);
            acc.x+=gq.w*x3.x;acc.y+=gq.w*x3.y;acc.z+=gq.w*x3.z;acc.w+=gq.w*x3.w;
        }
        float4 inter=make_float4(0.f,0.f,0.f,0.f);
        #pragma unroll
        for(int nn=0;nn<DSTATE;nn++){
            float cc=Cv[t*DSTATE+nn];
            float4 sv=*(const float4*)(Ss+nn*PDIM+p);
            inter.x+=cc*sv.x;inter.y+=cc*sv.y;inter.z+=cc*sv.z;inter.w+=cc*sv.w;
        }
        float elt=expf(Lc[t]);
        float4 xt=*(const float4*)(Xv+t*PDIM+p);
        acc.x+=elt*inter.x+Dh*xt.x; acc.y+=elt*inter.y+Dh*xt.y;
        acc.z+=elt*inter.z+Dh*xt.z; acc.w+=elt*inter.w+Dh*xt.w;
        *(float4*)(g_y+((size_t)b*NTOK+ch*QCH+t)*DIN+h*PDIM+p)=acc;
    }
}
#define SSD_SMEM ((QCH+QCH+QCH*DSTATE+DSTATE*BVP+QCH*PDIM+DSTATE*PDIM+QCH*QCH)*4)

__global__ void k_gate_rms(const float* __restrict__ rms_w){
    __shared__ float sa[32],sb[32];
    int row=blockIdx.x;
    float* yr=g_y+(size_t)row*DIN;
    const float* zr=g_zx+(size_t)row*DPROJ;
    float vals[3],ss=0.f;
    #pragma unroll
    for(int i=0;i<3;i++){
        int c=threadIdx.x+i*256;
        float v=0.f;
        if(c<DIN)v=yr[c]*siluf(zr[c]);
        vals[i]=v; ss+=v*v;
    }
    float dummy=0.f;
    blockReduce2(ss,dummy,sa,sb);
    float scale=rsqrtf(ss*(1.f/DIN)+LN_EPS);
    #pragma unroll
    for(int i=0;i<3;i++){
        int c=threadIdx.x+i*256;
        if(c<DIN)yr[c]=vals[i]*scale*rms_w[c];
    }
}

__global__ void k_kpe(const float* __restrict__ gauss){
    int t=blockIdx.x,j=threadIdx.x;
    int d=t>>10,r=t&1023,hh=r>>5,ww=r&31;
    float g0=2.f*((d+0.5f)/16.f)-1.f,g1=2.f*((hh+0.5f)/32.f)-1.f,g2=2.f*((ww+0.5f)/32.f)-1.f;
    float c=TWOPI*(g0*gauss[j]+g1*gauss[160+j]+g2*gauss[320+j]);
    g_kpe[(size_t)t*CDIM+j]=sinf(c);
    g_kpe[(size_t)t*CDIM+160+j]=cosf(c);
}

__global__ void k_pemb(const float* __restrict__ coords,const int* __restrict__ labels,
                       const float* __restrict__ gauss,const float* __restrict__ tab){
    int bp=blockIdx.x,j=threadIdx.x;
    float g0=2.f*(coords[bp*3+0]*(1.f/128.f))-1.f;
    float g1=2.f*(coords[bp*3+1]*(1.f/256.f))-1.f;
    float g2=2.f*(coords[bp*3+2]*(1.f/256.f))-1.f;
    float c=TWOPI*(g0*gauss[j]+g1*gauss[160+j]+g2*gauss[320+j]);
    int lb=labels[bp];
    float s=sinf(c)+tab[lb*CDIM+j],co=cosf(c)+tab[lb*CDIM+160+j];
    g_pe[bp*CDIM+j]=s; g_pe[bp*CDIM+160+j]=co;
    g_qr[bp*CDIM+j]=s; g_qr[bp*CDIM+160+j]=co;
}

__global__ void k_tiny(const float* __restrict__ in,const float* __restrict__ pe,
                       const float* __restrict__ W,const float* __restrict__ bias,
                       const float* __restrict__ res,float* __restrict__ out,
                       int N,int K,int relu){
    extern __shared__ float srow[];
    int m=blockIdx.x;
    for(int i=threadIdx.x;i<K;i+=blockDim.x){
        float v=in[m*K+i];
        if(pe)v+=pe[m*K+i];
        srow[i]=v;
    }
    __syncthreads();
    int lane=threadIdx.x&31,warp=threadIdx.x>>5;
    int nq=N/gridDim.y;
    int nBeg=blockIdx.y*nq,nEnd=nBeg+nq;
    for(int n=nBeg+warp;n<nEnd;n+=8){
        const float* wr=W+(size_t)n*K;
        float acc=0.f;
        for(int kk=lane;kk<K;kk+=32)acc+=srow[kk]*wr[kk];
        #pragma unroll
        for(int o=16;o>0;o>>=1)acc+=__shfl_down_sync(0xffffffffu,acc,o);
        if(lane==0){
            if(bias)acc+=bias[n];
            if(relu)acc=fmaxf(acc,0.f);
            if(res)acc+=res[m*N+n];
            out[m*N+n]=acc;
        }
    }
}

__global__ void k_selfattn(const float* __restrict__ q,const float* __restrict__ k,
                           const float* __restrict__ v,float* __restrict__ out){
    int bh=blockIdx.x,b=bh>>2,h=bh&3;
    __shared__ float qs[NQ][80],ks[NQ][80],vs[NQ][80],p[NQ][NQ];
    for(int i=threadIdx.x;i<NQ*80;i+=blockDim.x){
        int r=i/80,d=i-r*80;
        size_t off=(size_t)(b*NQ+r)*CDIM+h*80+d;
        qs[r][d]=q[off];ks[r][d]=k[off];vs[r][d]=v[off];
    }
    __syncthreads();
    if(threadIdx.x<36){
        int i=threadIdx.x/6,j=threadIdx.x%6;
        float s=0.f;
        #pragma unroll
        for(int d=0;d<80;d++)s+=qs[i][d]*ks[j][d];
        p[i][j]=s*0.11180339887498949f;
    }
    __syncthreads();
    if(threadIdx.x<NQ){
        int i=threadIdx.x;
        float m=-1e30f;
        for(int j=0;j<NQ;j++)m=fmaxf(m,p[i][j]);
        float ssum=0.f;
        for(int j=0;j<NQ;j++){float e=expf(p[i][j]-m);p[i][j]=e;ssum+=e;}
        float inv=1.f/ssum;
        for(int j=0;j<NQ;j++)p[i][j]*=inv;
    }
    __syncthreads();
    if(threadIdx.x<80){
        int d=threadIdx.x;
        for(int i=0;i<NQ;i++){
            float o=0.f;
            #pragma unroll
            for(int j=0;j<NQ;j++)o+=p[i][j]*vs[j][d];
            out[(size_t)(b*NQ+i)*CDIM+h*80+d]=o;
        }
    }
}

#define T2I_TP 41
#define T2I_SMEM ((NTOK + 256*T2I_TP + 256)*4)
__global__ void k_t2i_attn(const float* __restrict__ q6,const float* __restrict__ kbig,
                           const float* __restrict__ vbig,float* __restrict__ out){
    extern __shared__ float sm[];
    float* scr=sm;
    float* tile=sm+NTOK;
    float* red=tile+256*T2I_TP;
    __shared__ float wred[8][40];
    int g=blockIdx.x,qi=g%6,h=(g/6)%4,b=g/24;
    int tid=threadIdx.x;
    float qv[40];
    const float* qp=q6+(size_t)(b*NQ+qi)*INNERC+h*40;
    #pragma unroll
    for(int d=0;d<40;d++)qv[d]=qp[d]*0.15811388300841897f;
    const float* kb=kbig+(size_t)b*NTOK*INNERC+h*40;
    float lmax=-1e30f;
    for(int t0=0;t0<NTOK;t0+=256){
        for(int i=tid;i<256*40;i+=256){
            int r=i/40,c=i-r*40;
            tile[r*T2I_TP+c]=kb[(size_t)(t0+r)*INNERC+c];
        }
        __syncthreads();
        const float* tr=tile+tid*T2I_TP;
        float s=0.f;
        #pragma unroll
        for(int d=0;d<40;d++)s+=qv[d]*tr[d];
        scr[t0+tid]=s; lmax=fmaxf(lmax,s);
        __syncthreads();
    }
    red[tid]=lmax;__syncthreads();
    for(int o=128;o>0;o>>=1){if(tid<o)red[tid]=fmaxf(red[tid],red[tid+o]);__syncthreads();}
    float gmax=red[0];__syncthreads();
    float lsum=0.f;
    for(int kk=tid;kk<NTOK;kk+=256){float e=expf(scr[kk]-gmax);scr[kk]=e;lsum+=e;}
    red[tid]=lsum;__syncthreads();
    for(int o=128;o>0;o>>=1){if(tid<o)red[tid]+=red[tid+o];__syncthreads();}
    float gsum=red[0];__syncthreads();
    float acc[40];
    #pragma unroll
    for(int d=0;d<40;d++)acc[d]=0.f;
    const float* vb=vbig+(size_t)b*NTOK*INNERC+h*40;
    for(int t0=0;t0<NTOK;t0+=256){
        for(int i=tid;i<256*40;i+=256){
            int r=i/40,c=i-r*40;
            tile[r*T2I_TP+c]=vb[(size_t)(t0+r)*INNERC+c];
        }
        __syncthreads();
        float e=scr[t0+tid];
        const float* tr=tile+tid*T2I_TP;
        #pragma unroll
        for(int d=0;d<40;d++)acc[d]+=e*tr[d];
        __syncthreads();
    }
    int lane=tid&31,w=tid>>5;
    #pragma unroll
    for(int d=0;d<40;d++){
        float a=acc[d];
        for(int o=16;o>0;o>>=1)a+=__shfl_down_sync(0xffffffffu,a,o);
        if(lane==0)wred[w][d]=a;
    }
    __syncthreads();
    if(tid<40){
        float o=0.f;
        #pragma unroll
        for(int ww=0;ww<8;ww++)o+=wred[ww][tid];
        out[(size_t)(b*NQ+qi)*INNERC+h*40+tid]=o/gsum;
    }
}

__global__ void k_i2t_attn(const float* __restrict__ qbig,const float* __restrict__ k6,
                           const float* __restrict__ v6,float* __restrict__ out){
    __shared__ __align__(16) float ks[NQ*INNERC];
    __shared__ __align__(16) float vs[NQ*INNERC];
    int b=blockIdx.x>>8;
    for(int i=threadIdx.x;i<NQ*INNERC;i+=256){
        ks[i]=k6[b*NQ*INNERC+i]; vs[i]=v6[b*NQ*INNERC+i];
    }
    __syncthreads();
    int rem=(blockIdx.x&255)*256+threadIdx.x;
    int t=rem>>2,h=rem&3;
    const float* qp=qbig+((size_t)b*NTOK+t)*INNERC+h*40;
    float qv[40];
    #pragma unroll
    for(int d4=0;d4<10;d4++)((float4*)qv)[d4]=((const float4*)qp)[d4];
    float s[NQ];
    #pragma unroll
    for(int j=0;j<NQ;j++){
        float d=0.f;
        #pragma unroll
        for(int dd=0;dd<40;dd++)d+=qv[dd]*ks[j*INNERC+h*40+dd];
        s[j]=d*0.15811388300841897f;
    }
    float m=-1e30f;
    #pragma unroll
    for(int j=0;j<NQ;j++)m=fmaxf(m,s[j]);
    float ssum=0.f;
    #pragma unroll
    for(int j=0;j<NQ;j++){s[j]=expf(s[j]-m);ssum+=s[j];}
    float inv=1.f/ssum;
    float* op=out+((size_t)b*NTOK+t)*INNERC+h*40;
    #pragma unroll
    for(int d4=0;d4<10;d4++){
        float4 o=make_float4(0.f,0.f,0.f,0.f);
        #pragma unroll
        for(int j=0;j<NQ;j++){
            float e=s[j];
            float4 v=((const float4*)(vs+j*INNERC+h*40))[d4];
            o.x+=e*v.x;o.y+=e*v.y;o.z+=e*v.z;o.w+=e*v.w;
        }
        o.x*=inv;o.y*=inv;o.z*=inv;o.w*=inv;
        ((float4*)op)[d4]=o;
    }
}

extern "C" void kernel_launch(void* const* d_in,const int* in_sizes,int n_in,
                              void* d_out,int out_size){
    const float* x=(const float*)d_in[0];
    const float* coords=(const float*)d_in[1];
    const int* labels=(const int*)d_in[2];
    const float* ln_w=(const float*)d_in[3];
    const float* ln_b=(const float*)d_in[4];
    const float* in_w=(const float*)d_in[5];
    const float* conv_w=(const float*)d_in[6];
    const float* conv_b=(const float*)d_in[7];
    const float* dt_bias=(const float*)d_in[8];
    const float* A_log=(const float*)d_in[9];
    const float* Dp=(const float*)d_in[10];
    const float* rms_w=(const float*)d_in[11];
    const float* out_w=(const float*)d_in[12];
    const float* gauss=(const float*)d_in[13];
    const float* ptab=(const float*)d_in[14];
    const float* sa_w=(const float*)d_in[15];
    const float* sa_b=(const float*)d_in[16];
    const float* t2i_w=(const float*)d_in[17];
    const float* t2i_b=(const float*)d_in[18];
    const float* t2i_ow=(const float*)d_in[19];
    const float* t2i_ob=(const float*)d_in[20];
    const float* i2t_w=(const float*)d_in[21];
    const float* i2t_b=(const float*)d_in[22];
    const float* i2t_ow=(const float*)d_in[23];
    const float* i2t_ob=(const float*)d_in[24];
    const float* norms_w=(const float*)d_in[25];
    const float* norms_b=(const float*)d_in[26];
    const float* mlp_w1=(const float*)d_in[27];
    const float* mlp_b1=(const float*)d_in[28];
    const float* mlp_w2=(const float*)d_in[29];
    const float* mlp_b2=(const float*)d_in[30];
    float* outp=(float*)d_out;

    float *p_xn,*p_zx,*p_y,*p_keys,*p_kpe,*p_pe,*p_qr,*p_q6,*p_k6,*p_v6,*p_a6,*p_mlp,*p_kb,*p_vb,*p_qb,*p_ab;
    cudaGetSymbolAddress((void**)&p_xn,g_xn);
    cudaGetSymbolAddress((void**)&p_zx,g_zx);
    cudaGetSymbolAddress((void**)&p_y,g_y);
    cudaGetSymbolAddress((void**)&p_keys,g_keys);
    cudaGetSymbolAddress((void**)&p_kpe,g_kpe);
    cudaGetSymbolAddress((void**)&p_pe,g_pe);
    cudaGetSymbolAddress((void**)&p_qr,g_qr);
    cudaGetSymbolAddress((void**)&p_q6,g_q6);
    cudaGetSymbolAddress((void**)&p_k6,g_k6);
    cudaGetSymbolAddress((void**)&p_v6,g_v6);
    cudaGetSymbolAddress((void**)&p_a6,g_a6);
    cudaGetSymbolAddress((void**)&p_mlp,g_mlpb);
    cudaGetSymbolAddress((void**)&p_kb,g_kb);
    cudaGetSymbolAddress((void**)&p_vb,g_vb);
    cudaGetSymbolAddress((void**)&p_qb,g_qb);
    cudaGetSymbolAddress((void**)&p_ab,g_ab);

    cudaFuncSetAttribute(k_chunkstate,cudaFuncAttributeMaxDynamicSharedMemorySize,57856);
    cudaFuncSetAttribute(k_ssd_out,cudaFuncAttributeMaxDynamicSharedMemorySize,SSD_SMEM);
    cudaFuncSetAttribute(k_t2i_attn,cudaFuncAttributeMaxDynamicSharedMemorySize,T2I_SMEM);

    dim3 tb(32,8);
    dim3 tg(BB*NQ,4);
    k_kpe<<<NTOK,160>>>(gauss);
    k_transpose<<<dim3(512,10,BB),tb>>>(x,p_xn,CDIM,NTOK);
    k_ln<<<BB*NTOK,CDIM>>>(p_xn,p_xn,ln_w,ln_b);
    k_gemm_tc<<<dim3(11,256),256>>>(p_xn,nullptr,1,in_w,nullptr,nullptr,p_zx,BB*NTOK,DPROJ,CDIM,
                                    nullptr,nullptr,nullptr,nullptr);
    k_conv<<<BB*NTOK,256>>>(conv_w,conv_b,dt_bias);
    k_cumsum<<<BB*NH*NCH,QCH>>>(A_log);
    k_chunkstate<<<BB*NH*NCH,256,57856>>>();
    k_staterec<<<BB*NH,256>>>();
    k_ssd_out<<<BB*NH*NCH,256,SSD_SMEM>>>(Dp);
    k_gate_rms<<<BB*NTOK,256>>>(rms_w);
    k_gemm_tc<<<dim3(3,256),256>>>(p_y,nullptr,1,out_w,nullptr,nullptr,p_keys,BB*NTOK,CDIM,DIN,
                                   nullptr,nullptr,nullptr,nullptr);
    k_pemb<<<BB*NQ,160>>>(coords,labels,gauss,ptab);

    for(int i=0;i<2;i++){
        const float* saw=sa_w+(size_t)i*4*CDIM*CDIM;
        const float* sab=sa_b+(size_t)i*4*CDIM;
        const float* pe0=i?p_pe:nullptr;
        k_tiny<<<tg,256,CDIM*4>>>(p_qr,pe0,saw,sab,nullptr,p_q6,CDIM,CDIM,0);
        k_tiny<<<tg,256,CDIM*4>>>(p_qr,pe0,saw+1*CDIM*CDIM,sab+CDIM,nullptr,p_k6,CDIM,CDIM,0);
        k_tiny<<<tg,256,CDIM*4>>>(p_qr,nullptr,saw+2*CDIM*CDIM,sab+2*CDIM,nullptr,p_v6,CDIM,CDIM,0);
        k_selfattn<<<BB*4,128>>>(p_q6,p_k6,p_v6,p_a6);
        k_tiny<<<tg,256,CDIM*4>>>(p_a6,nullptr,saw+3*CDIM*CDIM,sab+3*CDIM,i?p_qr:nullptr,p_qr,CDIM,CDIM,0);
        k_ln<<<BB*NQ,CDIM>>>(p_qr,p_qr,norms_w+(i*4+0)*CDIM,norms_b+(i*4+0)*CDIM);
        const float* tw=t2i_w+(size_t)i*3*INNERC*CDIM;
        const float* tb2=t2i_b+(size_t)i*3*INNERC;
        k_tiny<<<tg,256,CDIM*4>>>(p_qr,p_pe,tw,tb2,nullptr,p_q6,INNERC,CDIM,0);
        // merged kb (z=0, +kpe) and vb (z=1) projections
        k_gemm_tc<<<dim3(2,256,2),256>>>(p_keys,p_kpe,NTOK,tw+1*INNERC*CDIM,tb2+INNERC,nullptr,p_kb,
                                         BB*NTOK,INNERC,CDIM,
                                         nullptr,tw+2*INNERC*CDIM,tb2+2*INNERC,p_vb);
        k_t2i_attn<<<BB*4*NQ,256,T2I_SMEM>>>(p_q6,p_kb,p_vb,p_a6);
        k_tiny<<<tg,256,INNERC*4>>>(p_a6,nullptr,t2i_ow+(size_t)i*CDIM*INNERC,t2i_ob+i*CDIM,p_qr,p_qr,CDIM,INNERC,0);
        k_ln<<<BB*NQ,CDIM>>>(p_qr,p_qr,norms_w+(i*4+1)*CDIM,norms_b+(i*4+1)*CDIM);
        k_tiny<<<tg,256,CDIM*4>>>(p_qr,nullptr,mlp_w1+(size_t)i*MLPD*CDIM,mlp_b1+i*MLPD,nullptr,p_mlp,MLPD,CDIM,1);
        k_tiny<<<tg,256,MLPD*4>>>(p_mlp,nullptr,mlp_w2+(size_t)i*CDIM*MLPD,mlp_b2+i*CDIM,p_qr,p_qr,CDIM,MLPD,0);
        k_ln<<<BB*NQ,CDIM>>>(p_qr,p_qr,norms_w+(i*4+2)*CDIM,norms_b+(i*4+2)*CDIM);
        const float* iw=i2t_w+(size_t)i*3*INNERC*CDIM;
        const float* ib=i2t_b+(size_t)i*3*INNERC;
        k_gemm_tc<<<dim3(2,256),256>>>(p_keys,p_kpe,NTOK,iw,ib,nullptr,p_qb,BB*NTOK,INNERC,CDIM,
                                       nullptr,nullptr,nullptr,nullptr);
        k_tiny<<<tg,256,CDIM*4>>>(p_qr,p_pe,iw+1*INNERC*CDIM,ib+INNERC,nullptr,p_k6,INNERC,CDIM,0);
        k_tiny<<<tg,256,CDIM*4>>>(p_qr,nullptr,iw+2*INNERC*CDIM,ib+2*INNERC,nullptr,p_v6,INNERC,CDIM,0);
        k_i2t_attn<<<BB*256,256>>>(p_qb,p_k6,p_v6,p_ab);
        k_gemm_tc<<<dim3(3,256),256>>>(p_ab,nullptr,1,i2t_ow+(size_t)i*CDIM*INNERC,i2t_ob+i*CDIM,p_keys,p_keys,BB*NTOK,CDIM,INNERC,
                                       nullptr,nullptr,nullptr,nullptr);
        k_ln<<<BB*NTOK,CDIM>>>(p_keys,p_keys,norms_w+(i*4+3)*CDIM,norms_b+(i*4+3)*CDIM);
    }
    k_transpose<<<dim3(10,512,BB),tb>>>(p_keys,outp,NTOK,CDIM);
}

// round 15
// speedup vs baseline: 1.1020x; 1.0559x over previous
#include <cuda_runtime.h>
#include <math.h>
#include <stdint.h>

#define BB 2
#define CDIM 320
#define NTOK 16384
#define DIN 640
#define DSTATE 32
#define NH 8
#define PDIM 80
#define CONVD 704
#define DPROJ 1352
#define INNERC 160
#define NQ 6
#define QCH 128
#define NCH (NTOK/QCH)
#define MLPD 1024
#define LN_EPS 1e-5f
#define TWOPI 6.28318530717958647692f

__device__ float g_xn[BB*NTOK*CDIM];
__device__ float g_zx[BB*NTOK*DPROJ];
__device__ float g_xbc[BB*NTOK*CONVD];
__device__ float g_dt[BB*NTOK*NH];
__device__ float g_cumL[BB*NH*NTOK];
__device__ float g_Sc[BB*NH*NCH*DSTATE*PDIM];
__device__ float g_Sin[BB*NH*NCH*DSTATE*PDIM];
__device__ float g_y[BB*NTOK*DIN];
__device__ float g_keys[BB*NTOK*CDIM];
__device__ float g_kpe[NTOK*CDIM];
__device__ float g_pe[BB*NQ*CDIM];
__device__ float g_qr[BB*NQ*CDIM];
__device__ float g_q6[BB*NQ*CDIM];
__device__ float g_k6[BB*NQ*CDIM];
__device__ float g_v6[BB*NQ*CDIM];
__device__ float g_a6[BB*NQ*CDIM];
__device__ float g_mlpb[BB*NQ*MLPD];
__device__ float g_kb[BB*NTOK*INNERC];
__device__ float g_vb[BB*NTOK*INNERC];
__device__ float g_qb[BB*NTOK*INNERC];
__device__ float g_ab[BB*NTOK*INNERC];

// pre-converted bf16 hi/lo weight store (packed bf16x2, K/2 uint32 per row)
#define OFF_INW  0
#define OFF_OUTW 216320
#define OFF_LAYER 318720
#define WTOT 523520
__device__ uint32_t g_whi[WTOT];
__device__ uint32_t g_wlo[WTOT];

__device__ __forceinline__ float siluf(float x){ return x/(1.f+expf(-x)); }

__device__ __forceinline__ void blockReduce2(float& a,float& b,float* sa,float* sb){
    const unsigned m=0xffffffffu;
    for(int o=16;o>0;o>>=1){a+=__shfl_down_sync(m,a,o);b+=__shfl_down_sync(m,b,o);}
    int lane=threadIdx.x&31,w=threadIdx.x>>5;
    if(lane==0){sa[w]=a;sb[w]=b;}
    __syncthreads();
    int nw=(blockDim.x+31)>>5;
    if(w==0){
        a=(lane<nw)?sa[lane]:0.f; b=(lane<nw)?sb[lane]:0.f;
        for(int o=16;o>0;o>>=1){a+=__shfl_down_sync(m,a,o);b+=__shfl_down_sync(m,b,o);}
        if(lane==0){sa[0]=a;sb[0]=b;}
    }
    __syncthreads();
    a=sa[0];b=sb[0];
}

__global__ void k_transpose(const float* __restrict__ in,float* __restrict__ out,int R,int C){
    __shared__ float s[32][33];
    int b=blockIdx.z,r0=blockIdx.y*32,c0=blockIdx.x*32;
    const float* ip=in+(size_t)b*R*C; float* op=out+(size_t)b*R*C;
    #pragma unroll
    for(int j=0;j<32;j+=8){int r=r0+threadIdx.y+j,c=c0+threadIdx.x;
        if(r<R&&c<C)s[threadIdx.y+j][threadIdx.x]=ip[(size_t)r*C+c];}
    __syncthreads();
    #pragma unroll
    for(int j=0;j<32;j+=8){int r=c0+threadIdx.y+j,c=r0+threadIdx.x;
        if(r<C&&c<R)op[(size_t)r*R+c]=s[threadIdx.x][threadIdx.y+j];}
}

__global__ void k_ln(const float* __restrict__ in,float* __restrict__ out,
                     const float* __restrict__ w,const float* __restrict__ b){
    __shared__ float sa[32],sb[32];
    int row=blockIdx.x;
    float v=in[(size_t)row*CDIM+threadIdx.x];
    float s1=v,s2=v*v;
    blockReduce2(s1,s2,sa,sb);
    float mean=s1*(1.f/CDIM),var=s2*(1.f/CDIM)-mean*mean;
    float r=rsqrtf(var+LN_EPS);
    out[(size_t)row*CDIM+threadIdx.x]=(v-mean)*r*w[threadIdx.x]+b[threadIdx.x];
}

#define UPAD 20
__device__ __forceinline__ uint32_t pk2(float a,float b){
    uint32_t r; asm("cvt.rn.bf16x2.f32 %0, %1, %2;":"=r"(r):"f"(b),"f"(a)); return r;
}
__device__ __forceinline__ void mma_bf(float* d,uint32_t a0,uint32_t a1,uint32_t a2,uint32_t a3,
                                       uint32_t b0,uint32_t b1){
    asm volatile("mma.sync.aligned.m16n8k16.row.col.f32.bf16.bf16.f32 "
        "{%0,%1,%2,%3}, {%4,%5,%6,%7}, {%8,%9}, {%0,%1,%2,%3};"
        : "+f"(d[0]),"+f"(d[1]),"+f"(d[2]),"+f"(d[3])
        : "r"(a0),"r"(a1),"r"(a2),"r"(a3),"r"(b0),"r"(b1));
}

// weight pre-conversion: 10 segments, one launch. grid=(128,10), 256 thr
struct CvtSegs { const float* src[10]; int cnt[10]; int off[10]; };
__global__ void k_cvtw(CvtSegs S){
    int s=blockIdx.y;
    const float* src=S.src[s];
    int cnt=S.cnt[s];
    uint32_t* ho=g_whi+S.off[s];
    uint32_t* lo=g_wlo+S.off[s];
    for(int j=blockIdx.x*256+threadIdx.x;j<cnt;j+=gridDim.x*256){
        float a=src[2*j],b=src[2*j+1];
        uint32_t h=pk2(a,b);
        float la=a-__uint_as_float(h<<16),lb=b-__uint_as_float(h&0xffff0000u);
        ho[j]=h; lo[j]=pk2(la,lb);
    }
}

// C[M,N]=bias+res+(A(+Aadd))@W^T ; W pre-converted (Whg/Wlg packed bf16x2, K/2 per row)
__global__ __launch_bounds__(256) void k_gemm_tc(
        const float* __restrict__ A,const float* __restrict__ Aadd,int addMod,
        const uint32_t* __restrict__ Whg,const uint32_t* __restrict__ Wlg,
        const float* __restrict__ bias,
        const float* __restrict__ res,float* __restrict__ C,int M,int N,int K){
    __shared__ uint32_t Ah[128*UPAD],Al[128*UPAD],Wh[128*UPAD],Wl[128*UPAD];
    int m0=blockIdx.y*128,n0=blockIdx.x*128;
    int tid=threadIdx.x,lane=tid&31,warp=tid>>5;
    int wm=warp&3,wn=warp>>2,lg=lane>>2,lk=lane&3;
    int bnEnd=(N-n0-wn*64+7)>>3;
    if(bnEnd<0)bnEnd=0; if(bnEnd>8)bnEnd=8;
    int halfK=K>>1;
    float acc[2][8][4];
    #pragma unroll
    for(int am=0;am<2;am++)
        #pragma unroll
        for(int bn=0;bn<8;bn++)
            #pragma unroll
            for(int j=0;j<4;j++)acc[am][bn][j]=0.f;

    for(int kt=0;kt<K;kt+=32){
        #pragma unroll
        for(int i=0;i<4;i++){
            int f=tid+i*256,r=f>>3,kq=(f&7)<<2;
            int gm=m0+r;
            float4 v=*(const float4*)(A+(size_t)gm*K+kt+kq);
            if(Aadd){
                float4 u=*(const float4*)(Aadd+(size_t)(gm%addMod)*K+kt+kq);
                v.x+=u.x;v.y+=u.y;v.z+=u.z;v.w+=u.w;
            }
            uint32_t h0=pk2(v.x,v.y),h1=pk2(v.z,v.w);
            float l0=v.x-__uint_as_float(h0<<16),l1=v.y-__uint_as_float(h0&0xffff0000u);
            float l2=v.z-__uint_as_float(h1<<16),l3=v.w-__uint_as_float(h1&0xffff0000u);
            int si=r*UPAD+(kq>>1);
            *(uint2*)(Ah+si)=make_uint2(h0,h1);
            *(uint2*)(Al+si)=make_uint2(pk2(l0,l1),pk2(l2,l3));
            int gn=n0+r;
            uint2 hv=make_uint2(0u,0u),lv=make_uint2(0u,0u);
            if(gn<N){
                size_t wi=(size_t)gn*halfK+((kt+kq)>>1);
                hv=*(const uint2*)(Whg+wi);
                lv=*(const uint2*)(Wlg+wi);
            }
            *(uint2*)(Wh+si)=hv;
            *(uint2*)(Wl+si)=lv;
        }
        __syncthreads();
        if(bnEnd>0){
            #pragma unroll
            for(int ks=0;ks<2;ks++){
                uint32_t a0[2],a1[2],a2[2],a3[2],e0[2],e1[2],e2[2],e3[2];
                #pragma unroll
                for(int am=0;am<2;am++){
                    int r=wm*32+am*16+lg,c=ks*8+lk;
                    a0[am]=Ah[r*UPAD+c];     a1[am]=Ah[(r+8)*UPAD+c];
                    a2[am]=Ah[r*UPAD+c+4];   a3[am]=Ah[(r+8)*UPAD+c+4];
                    e0[am]=Al[r*UPAD+c];     e1[am]=Al[(r+8)*UPAD+c];
                    e2[am]=Al[r*UPAD+c+4];   e3[am]=Al[(r+8)*UPAD+c+4];
                }
                for(int bn=0;bn<bnEnd;bn++){
                    int col=wn*64+bn*8+lg,c=ks*8+lk;
                    uint32_t b0=Wh[col*UPAD+c],b1=Wh[col*UPAD+c+4];
                    uint32_t f0=Wl[col*UPAD+c],f1=Wl[col*UPAD+c+4];
                    #pragma unroll
                    for(int am=0;am<2;am++){
                        mma_bf(acc[am][bn],a0[am],a1[am],a2[am],a3[am],b0,b1);
                        mma_bf(acc[am][bn],a0[am],a1[am],a2[am],a3[am],f0,f1);
                        mma_bf(acc[am][bn],e0[am],e1[am],e2[am],e3[am],b0,b1);
                    }
                }
            }
        }
        __syncthreads();
    }
    #pragma unroll
    for(int am=0;am<2;am++){
        int r0=m0+wm*32+am*16+lg;
        for(int bn=0;bn<bnEnd;bn++){
            int c0=n0+wn*64+bn*8+2*lk;
            #pragma unroll
            for(int half=0;half<2;half++){
                int gm=r0+half*8;
                float d0=acc[am][bn][half*2+0],d1=acc[am][bn][half*2+1];
                if(c0<N){
                    float v=d0;
                    if(bias)v+=bias[c0];
                    if(res)v+=res[(size_t)gm*N+c0];
                    C[(size_t)gm*N+c0]=v;
                }
                if(c0+1<N){
                    float v=d1;
                    if(bias)v+=bias[c0+1];
                    if(res)v+=res[(size_t)gm*N+c0+1];
                    C[(size_t)gm*N+c0+1]=v;
                }
            }
        }
    }
}

__global__ void k_conv(const float* __restrict__ cw,const float* __restrict__ cb,
                       const float* __restrict__ dt_bias){
    int bt=blockIdx.x,t=bt&(NTOK-1);
    for(int c=threadIdx.x;c<CONVD;c+=blockDim.x){
        float acc=cb[c];
        #pragma unroll
        for(int k=0;k<4;k++){int ts=t+k-3;
            if(ts>=0)acc+=cw[c*4+k]*g_zx[(size_t)(bt+k-3)*DPROJ+DIN+c];}
        g_xbc[(size_t)bt*CONVD+c]=siluf(acc);
    }
    if(threadIdx.x<NH){
        float v=g_zx[(size_t)bt*DPROJ+DIN+CONVD+threadIdx.x]+dt_bias[threadIdx.x];
        v=(v>20.f)?v:log1pf(expf(v));
        g_dt[bt*NH+threadIdx.x]=v;
    }
}

__global__ void k_cumsum(const float* __restrict__ A_log){
    int g=blockIdx.x,ch=g%NCH,h=(g/NCH)%NH,b=g/(NCH*NH);
    int s=threadIdx.x,t=ch*QCH+s;
    float A=-expf(A_log[h]);
    __shared__ float sc[QCH];
    sc[s]=g_dt[((size_t)b*NTOK+t)*NH+h]*A;
    __syncthreads();
    for(int off=1;off<QCH;off<<=1){
        float add=(s>=off)?sc[s-off]:0.f;
        __syncthreads(); sc[s]+=add; __syncthreads();
    }
    g_cumL[((size_t)(b*NH+h))*NTOK+t]=sc[s];
}

__global__ void k_chunkstate(){
    extern __shared__ float sm[];
    float* w=sm; float* Bv=sm+QCH; float* Xv=Bv+QCH*DSTATE;
    int g=blockIdx.x,ch=g%NCH,h=(g/NCH)%NH,b=g/(NCH*NH);
    const float* cl=g_cumL+((size_t)(b*NH+h))*NTOK+ch*QCH;
    float total=cl[QCH-1];
    for(int i=threadIdx.x;i<QCH;i+=256){
        int t=ch*QCH+i;
        w[i]=expf(total-cl[i])*g_dt[((size_t)b*NTOK+t)*NH+h];
    }
    for(int i=threadIdx.x;i<QCH*DSTATE;i+=256){
        int s=i>>5,nn=i&31;
        Bv[i]=g_xbc[((size_t)b*NTOK+ch*QCH+s)*CONVD+DIN+nn];
    }
    for(int i=threadIdx.x;i<QCH*PDIM;i+=256){
        int s=i/PDIM,p=i-s*PDIM;
        Xv[i]=g_xbc[((size_t)b*NTOK+ch*QCH+s)*CONVD+h*PDIM+p];
    }
    __syncthreads();
    int n0=(threadIdx.x>>4)*2,p0=(threadIdx.x&15)*5;
    float acc[2][5];
    for(int a=0;a<2;a++)for(int q=0;q<5;q++)acc[a][q]=0.f;
    for(int s=0;s<QCH;s++){
        float ws=w[s],wb0=ws*Bv[s*DSTATE+n0],wb1=ws*Bv[s*DSTATE+n0+1];
        #pragma unroll
        for(int q=0;q<5;q++){
            float xv=Xv[s*PDIM+p0+q];
            acc[0][q]+=wb0*xv; acc[1][q]+=wb1*xv;
        }
    }
    size_t base=(size_t)g*(DSTATE*PDIM);
    for(int a=0;a<2;a++)for(int q=0;q<5;q++)
        g_Sc[base+(size_t)(n0+a)*PDIM+p0+q]=acc[a][q];
}

__global__ void k_staterec(){
    int bh=blockIdx.x;
    __shared__ float etot[NCH];
    for(int i=threadIdx.x;i<NCH;i+=256)
        etot[i]=expf(g_cumL[(size_t)bh*NTOK+i*QCH+QCH-1]);
    __syncthreads();
    float S[10];
    for(int j=0;j<10;j++)S[j]=0.f;
    for(int c=0;c<NCH;c++){
        size_t base=((size_t)bh*NCH+c)*(DSTATE*PDIM);
        float e=etot[c];
        #pragma unroll
        for(int j=0;j<10;j++){
            int idx=threadIdx.x+j*256;
            g_Sin[base+idx]=S[j];
            S[j]=S[j]*e+g_Sc[base+idx];
        }
    }
}

#define BVP 133
__global__ void k_ssd_out(const float* __restrict__ Dp){
    extern __shared__ float sm[];
    float* Lc=sm; float* dts=Lc+QCH; float* Cv=dts+QCH;
    float* BvT=Cv+QCH*DSTATE; float* Xv=BvT+DSTATE*BVP;
    float* Ss=Xv+QCH*PDIM; float* G=Ss+DSTATE*PDIM;
    int g=blockIdx.x,ch=g%NCH,h=(g/NCH)%NH,b=g/(NCH*NH);
    const float* cl=g_cumL+((size_t)(b*NH+h))*NTOK+ch*QCH;
    for(int i=threadIdx.x;i<QCH;i+=256){
        Lc[i]=cl[i];
        dts[i]=g_dt[((size_t)b*NTOK+ch*QCH+i)*NH+h];
    }
    for(int i=threadIdx.x;i<QCH*DSTATE;i+=256){
        int s=i>>5,nn=i&31;
        size_t rb=((size_t)b*NTOK+ch*QCH+s)*CONVD;
        Cv[i]=g_xbc[rb+DIN+DSTATE+nn];
        BvT[nn*BVP+s]=g_xbc[rb+DIN+nn];
    }
    for(int i=threadIdx.x;i<QCH*PDIM;i+=256){
        int s=i/PDIM,p=i-s*PDIM;
        Xv[i]=g_xbc[((size_t)b*NTOK+ch*QCH+s)*CONVD+h*PDIM+p];
    }
    for(int i=threadIdx.x;i<DSTATE*PDIM;i+=256)
        Ss[i]=g_Sin[(((size_t)(b*NH+h))*NCH+ch)*(DSTATE*PDIM)+i];
    __syncthreads();
    for(int e=threadIdx.x;e<QCH*QCH;e+=256){
        int t=e>>7,s=e&127;
        float val=0.f;
        if(s<=t){
            float d=0.f;
            #pragma unroll
            for(int nn=0;nn<DSTATE;nn++)d+=Cv[t*DSTATE+nn]*BvT[nn*BVP+s];
            val=d*expf(Lc[t]-Lc[s])*dts[s];
        }
        G[e]=val;
    }
    __syncthreads();
    float Dh=Dp[h];
    for(int o4=threadIdx.x;o4<QCH*PDIM/4;o4+=256){
        int idx=o4*4,t=idx/PDIM,p=idx-t*PDIM;
        float4 acc=make_float4(0.f,0.f,0.f,0.f);
        const float* Gt=G+t*QCH;
        for(int s=0;s<=t;s++){
            float gg=Gt[s];
            float4 xv=*(const float4*)(Xv+s*PDIM+p);
            acc.x+=gg*xv.x;acc.y+=gg*xv.y;acc.z+=gg*xv.z;acc.w+=gg*xv.w;
        }
        float4 inter=make_float4(0.f,0.f,0.f,0.f);
        #pragma unroll
        for(int nn=0;nn<DSTATE;nn++){
            float cc=Cv[t*DSTATE+nn];
            float4 sv=*(const float4*)(Ss+nn*PDIM+p);
            inter.x+=cc*sv.x;inter.y+=cc*sv.y;inter.z+=cc*sv.z;inter.w+=cc*sv.w;
        }
        float elt=expf(Lc[t]);
        float4 xt=*(const float4*)(Xv+t*PDIM+p);
        acc.x+=elt*inter.x+Dh*xt.x; acc.y+=elt*inter.y+Dh*xt.y;
        acc.z+=elt*inter.z+Dh*xt.z; acc.w+=elt*inter.w+Dh*xt.w;
        *(float4*)(g_y+((size_t)b*NTOK+ch*QCH+t)*DIN+h*PDIM+p)=acc;
    }
}
#define SSD_SMEM ((QCH+QCH+QCH*DSTATE+DSTATE*BVP+QCH*PDIM+DSTATE*PDIM+QCH*QCH)*4)

__global__ void k_gate_rms(const float* __restrict__ rms_w){
    __shared__ float sa[32],sb[32];
    int row=blockIdx.x;
    float* yr=g_y+(size_t)row*DIN;
    const float* zr=g_zx+(size_t)row*DPROJ;
    float vals[3],ss=0.f;
    #pragma unroll
    for(int i=0;i<3;i++){
        int c=threadIdx.x+i*256;
        float v=0.f;
        if(c<DIN)v=yr[c]*siluf(zr[c]);
        vals[i]=v; ss+=v*v;
    }
    float dummy=0.f;
    blockReduce2(ss,dummy,sa,sb);
    float scale=rsqrtf(ss*(1.f/DIN)+LN_EPS);
    #pragma unroll
    for(int i=0;i<3;i++){
        int c=threadIdx.x+i*256;
        if(c<DIN)yr[c]=vals[i]*scale*rms_w[c];
    }
}

__global__ void k_kpe(const float* __restrict__ gauss){
    int t=blockIdx.x,j=threadIdx.x;
    int d=t>>10,r=t&1023,hh=r>>5,ww=r&31;
    float g0=2.f*((d+0.5f)/16.f)-1.f,g1=2.f*((hh+0.5f)/32.f)-1.f,g2=2.f*((ww+0.5f)/32.f)-1.f;
    float c=TWOPI*(g0*gauss[j]+g1*gauss[160+j]+g2*gauss[320+j]);
    g_kpe[(size_t)t*CDIM+j]=sinf(c);
    g_kpe[(size_t)t*CDIM+160+j]=cosf(c);
}

__global__ void k_pemb(const float* __restrict__ coords,const int* __restrict__ labels,
                       const float* __restrict__ gauss,const float* __restrict__ tab){
    int bp=blockIdx.x,j=threadIdx.x;
    float g0=2.f*(coords[bp*3+0]*(1.f/128.f))-1.f;
    float g1=2.f*(coords[bp*3+1]*(1.f/256.f))-1.f;
    float g2=2.f*(coords[bp*3+2]*(1.f/256.f))-1.f;
    float c=TWOPI*(g0*gauss[j]+g1*gauss[160+j]+g2*gauss[320+j]);
    int lb=labels[bp];
    float s=sinf(c)+tab[lb*CDIM+j],co=cosf(c)+tab[lb*CDIM+160+j];
    g_pe[bp*CDIM+j]=s; g_pe[bp*CDIM+160+j]=co;
    g_qr[bp*CDIM+j]=s; g_qr[bp*CDIM+160+j]=co;
}

__global__ void k_tiny(const float* __restrict__ in,const float* __restrict__ pe,
                       const float* __restrict__ W,const float* __restrict__ bias,
                       const float* __restrict__ res,float* __restrict__ out,
                       int N,int K,int relu){
    extern __shared__ float srow[];
    int m=blockIdx.x;
    for(int i=threadIdx.x;i<K;i+=blockDim.x){
        float v=in[m*K+i];
        if(pe)v+=pe[m*K+i];
        srow[i]=v;
    }
    __syncthreads();
    int lane=threadIdx.x&31,warp=threadIdx.x>>5;
    int nq=N/gridDim.y;
    int nBeg=blockIdx.y*nq,nEnd=nBeg+nq;
    for(int n=nBeg+warp;n<nEnd;n+=8){
        const float* wr=W+(size_t)n*K;
        float acc=0.f;
        for(int kk=lane;kk<K;kk+=32)acc+=srow[kk]*wr[kk];
        #pragma unroll
        for(int o=16;o>0;o>>=1)acc+=__shfl_down_sync(0xffffffffu,acc,o);
        if(lane==0){
            if(bias)acc+=bias[n];
            if(relu)acc=fmaxf(acc,0.f);
            if(res)acc+=res[m*N+n];
            out[m*N+n]=acc;
        }
    }
}

__global__ void k_selfattn(const float* __restrict__ q,const float* __restrict__ k,
                           const float* __restrict__ v,float* __restrict__ out){
    int bh=blockIdx.x,b=bh>>2,h=bh&3;
    __shared__ float qs[NQ][80],ks[NQ][80],vs[NQ][80],p[NQ][NQ];
    for(int i=threadIdx.x;i<NQ*80;i+=blockDim.x){
        int r=i/80,d=i-r*80;
        size_t off=(size_t)(b*NQ+r)*CDIM+h*80+d;
        qs[r][d]=q[off];ks[r][d]=k[off];vs[r][d]=v[off];
    }
    __syncthreads();
    if(threadIdx.x<36){
        int i=threadIdx.x/6,j=threadIdx.x%6;
        float s=0.f;
        #pragma unroll
        for(int d=0;d<80;d++)s+=qs[i][d]*ks[j][d];
        p[i][j]=s*0.11180339887498949f;
    }
    __syncthreads();
    if(threadIdx.x<NQ){
        int i=threadIdx.x;
        float m=-1e30f;
        for(int j=0;j<NQ;j++)m=fmaxf(m,p[i][j]);
        float ssum=0.f;
        for(int j=0;j<NQ;j++){float e=expf(p[i][j]-m);p[i][j]=e;ssum+=e;}
        float inv=1.f/ssum;
        for(int j=0;j<NQ;j++)p[i][j]*=inv;
    }
    __syncthreads();
    if(threadIdx.x<80){
        int d=threadIdx.x;
        for(int i=0;i<NQ;i++){
            float o=0.f;
            #pragma unroll
            for(int j=0;j<NQ;j++)o+=p[i][j]*vs[j][d];
            out[(size_t)(b*NQ+i)*CDIM+h*80+d]=o;
        }
    }
}

#define T2I_TP 41
#define T2I_SMEM ((NTOK + 256*T2I_TP + 256)*4)
__global__ void k_t2i_attn(const float* __restrict__ q6,const float* __restrict__ kbig,
                           const float* __restrict__ vbig,float* __restrict__ out){
    extern __shared__ float sm[];
    float* scr=sm;
    float* tile=sm+NTOK;
    float* red=tile+256*T2I_TP;
    __shared__ float wred[8][40];
    int g=blockIdx.x,qi=g%6,h=(g/6)%4,b=g/24;
    int tid=threadIdx.x;
    float qv[40];
    const float* qp=q6+(size_t)(b*NQ+qi)*INNERC+h*40;
    #pragma unroll
    for(int d=0;d<40;d++)qv[d]=qp[d]*0.15811388300841897f;
    const float* kb=kbig+(size_t)b*NTOK*INNERC+h*40;
    float lmax=-1e30f;
    for(int t0=0;t0<NTOK;t0+=256){
        for(int i=tid;i<256*40;i+=256){
            int r=i/40,c=i-r*40;
            tile[r*T2I_TP+c]=kb[(size_t)(t0+r)*INNERC+c];
        }
        __syncthreads();
        const float* tr=tile+tid*T2I_TP;
        float s=0.f;
        #pragma unroll
        for(int d=0;d<40;d++)s+=qv[d]*tr[d];
        scr[t0+tid]=s; lmax=fmaxf(lmax,s);
        __syncthreads();
    }
    red[tid]=lmax;__syncthreads();
    for(int o=128;o>0;o>>=1){if(tid<o)red[tid]=fmaxf(red[tid],red[tid+o]);__syncthreads();}
    float gmax=red[0];__syncthreads();
    float lsum=0.f;
    for(int kk=tid;kk<NTOK;kk+=256){float e=expf(scr[kk]-gmax);scr[kk]=e;lsum+=e;}
    red[tid]=lsum;__syncthreads();
    for(int o=128;o>0;o>>=1){if(tid<o)red[tid]+=red[tid+o];__syncthreads();}
    float gsum=red[0];__syncthreads();
    float acc[40];
    #pragma unroll
    for(int d=0;d<40;d++)acc[d]=0.f;
    const float* vb=vbig+(size_t)b*NTOK*INNERC+h*40;
    for(int t0=0;t0<NTOK;t0+=256){
        for(int i=tid;i<256*40;i+=256){
            int r=i/40,c=i-r*40;
            tile[r*T2I_TP+c]=vb[(size_t)(t0+r)*INNERC+c];
        }
        __syncthreads();
        float e=scr[t0+tid];
        const float* tr=tile+tid*T2I_TP;
        #pragma unroll
        for(int d=0;d<40;d++)acc[d]+=e*tr[d];
        __syncthreads();
    }
    int lane=tid&31,w=tid>>5;
    #pragma unroll
    for(int d=0;d<40;d++){
        float a=acc[d];
        for(int o=16;o>0;o>>=1)a+=__shfl_down_sync(0xffffffffu,a,o);
        if(lane==0)wred[w][d]=a;
    }
    __syncthreads();
    if(tid<40){
        float o=0.f;
        #pragma unroll
        for(int ww=0;ww<8;ww++)o+=wred[ww][tid];
        out[(size_t)(b*NQ+qi)*INNERC+h*40+tid]=o/gsum;
    }
}

__global__ void k_i2t_attn(const float* __restrict__ qbig,const float* __restrict__ k6,
                           const float* __restrict__ v6,float* __restrict__ out){
    __shared__ __align__(16) float ks[NQ*INNERC];
    __shared__ __align__(16) float vs[NQ*INNERC];
    int b=blockIdx.x>>8;
    for(int i=threadIdx.x;i<NQ*INNERC;i+=256){
        ks[i]=k6[b*NQ*INNERC+i]; vs[i]=v6[b*NQ*INNERC+i];
    }
    __syncthreads();
    int rem=(blockIdx.x&255)*256+threadIdx.x;
    int t=rem>>2,h=rem&3;
    const float* qp=qbig+((size_t)b*NTOK+t)*INNERC+h*40;
    float qv[40];
    #pragma unroll
    for(int d4=0;d4<10;d4++)((float4*)qv)[d4]=((const float4*)qp)[d4];
    float s[NQ];
    #pragma unroll
    for(int j=0;j<NQ;j++){
        float d=0.f;
        #pragma unroll
        for(int dd=0;dd<40;dd++)d+=qv[dd]*ks[j*INNERC+h*40+dd];
        s[j]=d*0.15811388300841897f;
    }
    float m=-1e30f;
    #pragma unroll
    for(int j=0;j<NQ;j++)m=fmaxf(m,s[j]);
    float ssum=0.f;
    #pragma unroll
    for(int j=0;j<NQ;j++){s[j]=expf(s[j]-m);ssum+=s[j];}
    float inv=1.f/ssum;
    float* op=out+((size_t)b*NTOK+t)*INNERC+h*40;
    #pragma unroll
    for(int d4=0;d4<10;d4++){
        float4 o=make_float4(0.f,0.f,0.f,0.f);
        #pragma unroll
        for(int j=0;j<NQ;j++){
            float e=s[j];
            float4 v=((const float4*)(vs+j*INNERC+h*40))[d4];
            o.x+=e*v.x;o.y+=e*v.y;o.z+=e*v.z;o.w+=e*v.w;
        }
        o.x*=inv;o.y*=inv;o.z*=inv;o.w*=inv;
        ((float4*)op)[d4]=o;
    }
}

extern "C" void kernel_launch(void* const* d_in,const int* in_sizes,int n_in,
                              void* d_out,int out_size){
    const float* x=(const float*)d_in[0];
    const float* coords=(const float*)d_in[1];
    const int* labels=(const int*)d_in[2];
    const float* ln_w=(const float*)d_in[3];
    const float* ln_b=(const float*)d_in[4];
    const float* in_w=(const float*)d_in[5];
    const float* conv_w=(const float*)d_in[6];
    const float* conv_b=(const float*)d_in[7];
    const float* dt_bias=(const float*)d_in[8];
    const float* A_log=(const float*)d_in[9];
    const float* Dp=(const float*)d_in[10];
    const float* rms_w=(const float*)d_in[11];
    const float* out_w=(const float*)d_in[12];
    const float* gauss=(const float*)d_in[13];
    const float* ptab=(const float*)d_in[14];
    const float* sa_w=(const float*)d_in[15];
    const float* sa_b=(const float*)d_in[16];
    const float* t2i_w=(const float*)d_in[17];
    const float* t2i_b=(const float*)d_in[18];
    const float* t2i_ow=(const float*)d_in[19];
    const float* t2i_ob=(const float*)d_in[20];
    const float* i2t_w=(const float*)d_in[21];
    const float* i2t_b=(const float*)d_in[22];
    const float* i2t_ow=(const float*)d_in[23];
    const float* i2t_ob=(const float*)d_in[24];
    const float* norms_w=(const float*)d_in[25];
    const float* norms_b=(const float*)d_in[26];
    const float* mlp_w1=(const float*)d_in[27];
    const float* mlp_b1=(const float*)d_in[28];
    const float* mlp_w2=(const float*)d_in[29];
    const float* mlp_b2=(const float*)d_in[30];
    float* outp=(float*)d_out;

    float *p_xn,*p_zx,*p_y,*p_keys,*p_kpe,*p_pe,*p_qr,*p_q6,*p_k6,*p_v6,*p_a6,*p_mlp,*p_kb,*p_vb,*p_qb,*p_ab;
    uint32_t *p_whi,*p_wlo;
    cudaGetSymbolAddress((void**)&p_xn,g_xn);
    cudaGetSymbolAddress((void**)&p_zx,g_zx);
    cudaGetSymbolAddress((void**)&p_y,g_y);
    cudaGetSymbolAddress((void**)&p_keys,g_keys);
    cudaGetSymbolAddress((void**)&p_kpe,g_kpe);
    cudaGetSymbolAddress((void**)&p_pe,g_pe);
    cudaGetSymbolAddress((void**)&p_qr,g_qr);
    cudaGetSymbolAddress((void**)&p_q6,g_q6);
    cudaGetSymbolAddress((void**)&p_k6,g_k6);
    cudaGetSymbolAddress((void**)&p_v6,g_v6);
    cudaGetSymbolAddress((void**)&p_a6,g_a6);
    cudaGetSymbolAddress((void**)&p_mlp,g_mlpb);
    cudaGetSymbolAddress((void**)&p_kb,g_kb);
    cudaGetSymbolAddress((void**)&p_vb,g_vb);
    cudaGetSymbolAddress((void**)&p_qb,g_qb);
    cudaGetSymbolAddress((void**)&p_ab,g_ab);
    cudaGetSymbolAddress((void**)&p_whi,g_whi);
    cudaGetSymbolAddress((void**)&p_wlo,g_wlo);

    cudaFuncSetAttribute(k_chunkstate,cudaFuncAttributeMaxDynamicSharedMemorySize,57856);
    cudaFuncSetAttribute(k_ssd_out,cudaFuncAttributeMaxDynamicSharedMemorySize,SSD_SMEM);
    cudaFuncSetAttribute(k_t2i_attn,cudaFuncAttributeMaxDynamicSharedMemorySize,T2I_SMEM);

    // weight conversion segment table
    CvtSegs S;
    S.src[0]=in_w;   S.cnt[0]=DPROJ*(CDIM/2);  S.off[0]=OFF_INW;
    S.src[1]=out_w;  S.cnt[1]=CDIM*(DIN/2);    S.off[1]=OFF_OUTW;
    for(int i=0;i<2;i++){
        int base=OFF_LAYER+i*102400;
        S.src[2+i*4]=t2i_w+(size_t)(i*3+1)*INNERC*CDIM; S.cnt[2+i*4]=INNERC*(CDIM/2); S.off[2+i*4]=base;
        S.src[3+i*4]=t2i_w+(size_t)(i*3+2)*INNERC*CDIM; S.cnt[3+i*4]=INNERC*(CDIM/2); S.off[3+i*4]=base+25600;
        S.src[4+i*4]=i2t_w+(size_t)(i*3+0)*INNERC*CDIM; S.cnt[4+i*4]=INNERC*(CDIM/2); S.off[4+i*4]=base+51200;
        S.src[5+i*4]=i2t_ow+(size_t)i*CDIM*INNERC;      S.cnt[5+i*4]=CDIM*(INNERC/2); S.off[5+i*4]=base+76800;
    }

    dim3 tb(32,8);
    dim3 tg(BB*NQ,4);
    k_cvtw<<<dim3(128,10),256>>>(S);
    k_transpose<<<dim3(512,10,BB),tb>>>(x,p_xn,CDIM,NTOK);
    k_ln<<<BB*NTOK,CDIM>>>(p_xn,p_xn,ln_w,ln_b);
    k_gemm_tc<<<dim3(11,256),256>>>(p_xn,nullptr,1,p_whi+OFF_INW,p_wlo+OFF_INW,nullptr,nullptr,p_zx,BB*NTOK,DPROJ,CDIM);
    k_conv<<<BB*NTOK,256>>>(conv_w,conv_b,dt_bias);
    k_cumsum<<<BB*NH*NCH,QCH>>>(A_log);
    k_chunkstate<<<BB*NH*NCH,256,57856>>>();
    k_staterec<<<BB*NH,256>>>();
    k_ssd_out<<<BB*NH*NCH,256,SSD_SMEM>>>(Dp);
    k_gate_rms<<<BB*NTOK,256>>>(rms_w);
    k_gemm_tc<<<dim3(3,256),256>>>(p_y,nullptr,1,p_whi+OFF_OUTW,p_wlo+OFF_OUTW,nullptr,nullptr,p_keys,BB*NTOK,CDIM,DIN);
    k_kpe<<<NTOK,160>>>(gauss);
    k_pemb<<<BB*NQ,160>>>(coords,labels,gauss,ptab);

    for(int i=0;i<2;i++){
        int base=OFF_LAYER+i*102400;
        const float* saw=sa_w+(size_t)i*4*CDIM*CDIM;
        const float* sab=sa_b+(size_t)i*4*CDIM;
        const float* pe0=i?p_pe:nullptr;
        k_tiny<<<tg,256,CDIM*4>>>(p_qr,pe0,saw,sab,nullptr,p_q6,CDIM,CDIM,0);
        k_tiny<<<tg,256,CDIM*4>>>(p_qr,pe0,saw+1*CDIM*CDIM,sab+CDIM,nullptr,p_k6,CDIM,CDIM,0);
        k_tiny<<<tg,256,CDIM*4>>>(p_qr,nullptr,saw+2*CDIM*CDIM,sab+2*CDIM,nullptr,p_v6,CDIM,CDIM,0);
        k_selfattn<<<BB*4,128>>>(p_q6,p_k6,p_v6,p_a6);
        k_tiny<<<tg,256,CDIM*4>>>(p_a6,nullptr,saw+3*CDIM*CDIM,sab+3*CDIM,i?p_qr:nullptr,p_qr,CDIM,CDIM,0);
        k_ln<<<BB*NQ,CDIM>>>(p_qr,p_qr,norms_w+(i*4+0)*CDIM,norms_b+(i*4+0)*CDIM);
        const float* tw=t2i_w+(size_t)i*3*INNERC*CDIM;
        const float* tb2=t2i_b+(size_t)i*3*INNERC;
        k_tiny<<<tg,256,CDIM*4>>>(p_qr,p_pe,tw,tb2,nullptr,p_q6,INNERC,CDIM,0);
        k_gemm_tc<<<dim3(2,256),256>>>(p_keys,p_kpe,NTOK,p_whi+base,p_wlo+base,tb2+INNERC,nullptr,p_kb,BB*NTOK,INNERC,CDIM);
        k_gemm_tc<<<dim3(2,256),256>>>(p_keys,nullptr,1,p_whi+base+25600,p_wlo+base+25600,tb2+2*INNERC,nullptr,p_vb,BB*NTOK,INNERC,CDIM);
        k_t2i_attn<<<BB*4*NQ,256,T2I_SMEM>>>(p_q6,p_kb,p_vb,p_a6);
        k_tiny<<<tg,256,INNERC*4>>>(p_a6,nullptr,t2i_ow+(size_t)i*CDIM*INNERC,t2i_ob+i*CDIM,p_qr,p_qr,CDIM,INNERC,0);
        k_ln<<<BB*NQ,CDIM>>>(p_qr,p_qr,norms_w+(i*4+1)*CDIM,norms_b+(i*4+1)*CDIM);
        k_tiny<<<tg,256,CDIM*4>>>(p_qr,nullptr,mlp_w1+(size_t)i*MLPD*CDIM,mlp_b1+i*MLPD,nullptr,p_mlp,MLPD,CDIM,1);
        k_tiny<<<tg,256,MLPD*4>>>(p_mlp,nullptr,mlp_w2+(size_t)i*CDIM*MLPD,mlp_b2+i*CDIM,p_qr,p_qr,CDIM,MLPD,0);
        k_ln<<<BB*NQ,CDIM>>>(p_qr,p_qr,norms_w+(i*4+2)*CDIM,norms_b+(i*4+2)*CDIM);
        const float* iw=i2t_w+(size_t)i*3*INNERC*CDIM;
        const float* ib=i2t_b+(size_t)i*3*INNERC;
        k_gemm_tc<<<dim3(2,256),256>>>(p_keys,p_kpe,NTOK,p_whi+base+51200,p_wlo+base+51200,ib,nullptr,p_qb,BB*NTOK,INNERC,CDIM);
        k_tiny<<<tg,256,CDIM*4>>>(p_qr,p_pe,iw+1*INNERC*CDIM,ib+INNERC,nullptr,p_k6,INNERC,CDIM,0);
        k_tiny<<<tg,256,CDIM*4>>>(p_qr,nullptr,iw+2*INNERC*CDIM,ib+2*INNERC,nullptr,p_v6,INNERC,CDIM,0);
        k_i2t_attn<<<BB*256,256>>>(p_qb,p_k6,p_v6,p_ab);
        k_gemm_tc<<<dim3(3,256),256>>>(p_ab,nullptr,1,p_whi+base+76800,p_wlo+base+76800,i2t_ob+i*CDIM,p_keys,p_keys,BB*NTOK,CDIM,INNERC);
        k_ln<<<BB*NTOK,CDIM>>>(p_keys,p_keys,norms_w+(i*4+3)*CDIM,norms_b+(i*4+3)*CDIM);
    }
    k_transpose<<<dim3(10,512,BB),tb>>>(p_keys,outp,NTOK,CDIM);
}